// round 2
// baseline (speedup 1.0000x reference)
#include <cuda_runtime.h>
#include <math.h>
#include <stdint.h>

#define BB 4
#define NN 1024
#define DIMD 512
#define HH 8
#define DHD 64
#define INNERD 512
#define BH (BB*HH)            // 32
#define NROWS (BH*NN)         // 32768
#define SCALE 0.125f
#define INVTEMP 10.0f
#define LNEG (-1.0e9f)

// ---------------- scratch (device globals; no runtime allocation) ----------
__device__ float g_q[NROWS*DHD];
__device__ float g_k[NROWS*DHD];
__device__ float g_v[NROWS*DHD];
__device__ float g_qn[NROWS];
__device__ float g_kn[NROWS];
__device__ float g_ctx[(size_t)BB*NN*INNERD];
__device__ float g_clus[NROWS];
__device__ int   g_msum;
__device__ float g_attn_fb[(size_t)BH*NN*NN];   // fallback if d_out lacks attn region

// ---------------- init ----------------
__global__ void init_kernel() {
    if (threadIdx.x == 0 && blockIdx.x == 0) g_msum = 0;
}

// ---------------- generic 64x64 tiled SGEMM: C = A[4096x512] @ W[512x512] + bias
// MODE 0: store head-split into g_q ; 1: g_k ; 2: g_v
// MODE 3: A ignored, reads g_ctx (device symbol), plain row-major into out
template<int MODE>
__global__ void gemm64_kernel(const float* __restrict__ A,
                              const float* __restrict__ W,
                              const float* __restrict__ bias,
                              float* __restrict__ out)
{
    __shared__ float As[16][64];
    __shared__ float Bs[16][64];
    const int tid = threadIdx.x;          // 256
    const int tx = tid & 15, ty = tid >> 4;
    const int bm = blockIdx.y * 64;
    const int bn = blockIdx.x * 64;
    float acc[4][4] = {};

    const float* Aptr = (MODE == 3) ? (const float*)g_ctx : A;

    for (int k0 = 0; k0 < 512; k0 += 16) {
        // A tile: [64 rows x 16 k] -> As[k][m]
        {
            int r = tid >> 2, vq = tid & 3;
            float4 a = *(const float4*)(Aptr + (size_t)(bm + r) * 512 + k0 + vq * 4);
            As[vq*4+0][r] = a.x; As[vq*4+1][r] = a.y;
            As[vq*4+2][r] = a.z; As[vq*4+3][r] = a.w;
        }
        // W tile: [16 k x 64 n] -> Bs[k][n]
        {
            int kk = tid >> 4, nq = tid & 15;
            *(float4*)&Bs[kk][nq*4] =
                *(const float4*)(W + (size_t)(k0 + kk) * 512 + bn + nq * 4);
        }
        __syncthreads();
        #pragma unroll
        for (int kk = 0; kk < 16; kk++) {
            float4 a4 = *(const float4*)&As[kk][ty*4];
            float4 b4 = *(const float4*)&Bs[kk][tx*4];
            float ar[4] = {a4.x, a4.y, a4.z, a4.w};
            float br[4] = {b4.x, b4.y, b4.z, b4.w};
            #pragma unroll
            for (int i = 0; i < 4; i++)
                #pragma unroll
                for (int j = 0; j < 4; j++)
                    acc[i][j] += ar[i] * br[j];
        }
        __syncthreads();
    }

    #pragma unroll
    for (int i = 0; i < 4; i++) {
        int m = bm + ty*4 + i;            // m = b*1024 + n
        #pragma unroll
        for (int j = 0; j < 4; j++) {
            int c = bn + tx*4 + j;        // c = h*64 + d
            float val = acc[i][j] + bias[c];
            if (MODE <= 2) {
                int b = m >> 10, n = m & 1023;
                int h = c >> 6,  d = c & 63;
                size_t idx = (((size_t)(b*HH + h) * NN + n) * DHD) + d;
                if (MODE == 0) g_q[idx] = val;
                else if (MODE == 1) g_k[idx] = val;
                else g_v[idx] = val;
            } else {
                out[(size_t)m * DIMD + c] = val;
            }
        }
    }
}

// ---------------- row norms of q and k ----------------
__global__ void norms_kernel() {
    int gw = (blockIdx.x * blockDim.x + threadIdx.x) >> 5;
    int lane = threadIdx.x & 31;
    if (gw >= 2 * NROWS) return;
    const float* src = (gw < NROWS) ? g_q : g_k;
    float* dst = (gw < NROWS) ? g_qn : g_kn;
    int row = (gw < NROWS) ? gw : gw - NROWS;
    const float* p = src + (size_t)row * DHD;
    float a = p[lane], b2 = p[lane + 32];
    float s = a * a + b2 * b2;
    #pragma unroll
    for (int o = 16; o > 0; o >>= 1) s += __shfl_xor_sync(0xffffffffu, s, o);
    if (lane == 0) dst[row] = sqrtf(s);
}

// ---------------- mask sum (integer atomics: deterministic) ----------------
__global__ void masksum_kernel(const int* __restrict__ mask) {
    const long total = (long)BB * NN * NN;
    long i = (long)blockIdx.x * blockDim.x + threadIdx.x;
    int s = 0;
    for (; i < total; i += (long)gridDim.x * blockDim.x) s += mask[i];
    #pragma unroll
    for (int o = 16; o > 0; o >>= 1) s += __shfl_xor_sync(0xffffffffu, s, o);
    __shared__ int ws[8];
    int lane = threadIdx.x & 31, w = threadIdx.x >> 5;
    if (lane == 0) ws[w] = s;
    __syncthreads();
    if (threadIdx.x < 8) {
        int v = ws[threadIdx.x];
        #pragma unroll
        for (int o = 4; o > 0; o >>= 1) v += __shfl_xor_sync(0xffu, v, o);
        if (threadIdx.x == 0) atomicAdd(&g_msum, v);
    }
}

// ---------------- fused scores + mask + softmax + contrastive ----------------
// one block = 8 query rows of one (b,h); 256 threads = 8 warps (warp per row)
__global__ void attn_kernel(const int* __restrict__ mask,
                            float* __restrict__ attn_out)
{
    extern __shared__ float sm[];
    float* qsh = sm;               // 8*64
    float* ksh = sm + 512;         // 64*64
    float* ssc = sm + 512 + 4096;  // 8*1024

    const int tid = threadIdx.x;
    const int warp = tid >> 5, lane = tid & 31;
    const int blk = blockIdx.x;            // 4096 blocks
    const int bh = blk >> 7;               // 128 blocks per (b,h)
    const int i0 = (blk & 127) * 8;
    const int b = bh >> 3;

    const float* qbase = g_q + (size_t)bh * NN * DHD;
    const float* kbase = g_k + (size_t)bh * NN * DHD;

    for (int idx = tid; idx < 8 * 64; idx += 256)
        qsh[idx] = qbase[(size_t)i0 * DHD + idx];

    const int myrow = i0 + warp;
    const float qn = g_qn[bh * NN + myrow];
    const int* mptr = mask + ((size_t)b * NN + myrow) * NN;
    const float* knrow = g_kn + bh * NN;

    float pos = 0.f, allsum = 0.f, mx = -3.4e38f;
    float* srow = ssc + warp * 1024;

    for (int jt = 0; jt < 16; jt++) {
        __syncthreads();
        {   // load k tile [64 x 64]
            const float4* src = (const float4*)(kbase + (size_t)jt * 64 * 64);
            float4* dst = (float4*)ksh;
            for (int idx = tid; idx < 1024; idx += 256) dst[idx] = src[idx];
        }
        __syncthreads();
        #pragma unroll
        for (int u = 0; u < 2; u++) {
            int jl = lane + u * 32;
            int j = jt * 64 + jl;
            const float4* kr = (const float4*)(ksh + jl * 64);
            const float4* qr = (const float4*)(qsh + warp * 64);
            float dot = 0.f;
            #pragma unroll
            for (int d = 0; d < 16; d++) {
                float4 kv = kr[d], qv = qr[d];
                dot += kv.x*qv.x + kv.y*qv.y + kv.z*qv.z + kv.w*qv.w;
            }
            int m = mptr[j];
            float cosv = dot / (qn * knrow[j]);
            float e = __expf(cosv * INVTEMP);
            allsum += e;
            if (m) pos += e;
            float masked = (m ? dot : LNEG) * SCALE;
            srow[j] = masked;
            mx = fmaxf(mx, masked);
        }
    }
    #pragma unroll
    for (int o = 16; o > 0; o >>= 1)
        mx = fmaxf(mx, __shfl_xor_sync(0xffffffffu, mx, o));
    #pragma unroll
    for (int o = 16; o > 0; o >>= 1)
        allsum += __shfl_xor_sync(0xffffffffu, allsum, o);
    #pragma unroll
    for (int o = 16; o > 0; o >>= 1)
        pos += __shfl_xor_sync(0xffffffffu, pos, o);

    float sumexp = 0.f;
    #pragma unroll 4
    for (int t = 0; t < 32; t++) {
        int j = lane + t * 32;
        float p = __expf(srow[j] - mx);
        srow[j] = p;
        sumexp += p;
    }
    #pragma unroll
    for (int o = 16; o > 0; o >>= 1)
        sumexp += __shfl_xor_sync(0xffffffffu, sumexp, o);

    float inv = 1.0f / sumexp;
    float* orow = attn_out + ((size_t)bh * NN + myrow) * NN;
    #pragma unroll 4
    for (int t = 0; t < 32; t++) {
        int j = lane + t * 32;
        orow[j] = srow[j] * inv;
    }
    if (lane == 0)
        g_clus[bh * NN + myrow] = -__logf(pos / allsum);
}

// ---------------- attn @ v -> ctx in [b, n, h*DH + d] ----------------
__global__ void av_kernel(const float* __restrict__ attn) {
    __shared__ float vsh[64 * 64];
    __shared__ float ash[32 * 64];
    const int tx = threadIdx.x;   // 0..63 -> d
    const int ty = threadIdx.y;   // 0..3
    const int tid = ty * 64 + tx;
    const int blk = blockIdx.x;   // 1024
    const int bh = blk >> 5;
    const int i0 = (blk & 31) * 32;
    const float* vbase = g_v + (size_t)bh * NN * DHD;
    const float* abase = attn + ((size_t)bh * NN + i0) * NN;
    float acc[8] = {};

    for (int jt = 0; jt < 16; jt++) {
        __syncthreads();
        {
            const float4* vs = (const float4*)(vbase + (size_t)jt * 64 * 64);
            float4* vd = (float4*)vsh;
            for (int idx = tid; idx < 1024; idx += 256) vd[idx] = vs[idx];
        }
        for (int idx = tid; idx < 512; idx += 256) {
            int r = idx >> 4, cq = idx & 15;
            ((float4*)ash)[r * 16 + cq] =
                *(const float4*)(abase + (size_t)r * NN + jt * 64 + cq * 4);
        }
        __syncthreads();
        #pragma unroll
        for (int j = 0; j < 64; j += 4) {
            float vv0 = vsh[(j+0)*64 + tx];
            float vv1 = vsh[(j+1)*64 + tx];
            float vv2 = vsh[(j+2)*64 + tx];
            float vv3 = vsh[(j+3)*64 + tx];
            #pragma unroll
            for (int r = 0; r < 8; r++) {
                float4 a = *(const float4*)&ash[(ty + r*4) * 64 + j];
                acc[r] += a.x*vv0 + a.y*vv1 + a.z*vv2 + a.w*vv3;
            }
        }
    }
    const int h = bh & 7, b = bh >> 3;
    #pragma unroll
    for (int r = 0; r < 8; r++) {
        int i = i0 + ty + r * 4;
        g_ctx[((size_t)b * NN + i) * INNERD + h * 64 + tx] = acc[r];
    }
}

// ---------------- final dcl scalar ----------------
__global__ void dcl_kernel(float* out_dcl) {
    __shared__ float red[1024];
    const int tid = threadIdx.x;
    float s = 0.f;
    const int base = tid * 32;
    #pragma unroll 8
    for (int i = 0; i < 32; i++) s += g_clus[base + i];
    red[tid] = s;
    __syncthreads();
    for (int o = 512; o > 0; o >>= 1) {
        if (tid < o) red[tid] += red[tid + o];
        __syncthreads();
    }
    if (tid == 0 && out_dcl) {
        float clus_mean = red[0] / (float)NROWS;
        float regular = ((float)g_msum - (float)(BB * NN)) /
                        ((float)BB * (float)NN * (float)(NN - 1));
        out_dcl[0] = clus_mean + 0.3f * regular;
    }
}

// ---------------- launcher ----------------
extern "C" void kernel_launch(void* const* d_in, const int* in_sizes, int n_in,
                              void* d_out, int out_size) {
    const float* x   = (const float*)d_in[0];
    const int*   msk = (const int*)  d_in[1];
    const float* Wq  = (const float*)d_in[2];
    const float* bq  = (const float*)d_in[3];
    const float* Wk  = (const float*)d_in[4];
    const float* bk  = (const float*)d_in[5];
    const float* Wv  = (const float*)d_in[6];
    const float* bv  = (const float*)d_in[7];
    const float* Wo  = (const float*)d_in[8];
    const float* bo  = (const float*)d_in[9];
    float* out = (float*)d_out;

    const size_t OUTE  = (size_t)BB * NN * DIMD;   // 2097152
    const size_t ATTNE = (size_t)BH * NN * NN;     // 33554432

    float* attn_ptr;
    if ((size_t)out_size >= OUTE + ATTNE) {
        attn_ptr = out + OUTE;
    } else {
        void* p = nullptr;
        cudaGetSymbolAddress(&p, g_attn_fb);
        attn_ptr = (float*)p;
    }
    float* dcl_ptr = ((size_t)out_size >= OUTE + ATTNE + 1) ? (out + OUTE + ATTNE)
                                                            : nullptr;

    const int smem_attn = (512 + 4096 + 8192) * 4;  // 51200 B
    cudaFuncSetAttribute(attn_kernel,
                         cudaFuncAttributeMaxDynamicSharedMemorySize, smem_attn);

    init_kernel<<<1, 32>>>();

    dim3 ggrid(DIMD / 64, (BB * NN) / 64);          // (8, 64)
    gemm64_kernel<0><<<ggrid, 256>>>(x, Wq, bq, nullptr);
    gemm64_kernel<1><<<ggrid, 256>>>(x, Wk, bk, nullptr);
    gemm64_kernel<2><<<ggrid, 256>>>(x, Wv, bv, nullptr);

    norms_kernel<<<(2 * NROWS) / 8, 256>>>();       // 8192 blocks, warp/row
    masksum_kernel<<<512, 256>>>(msk);

    attn_kernel<<<BH * (NN / 8), 256, smem_attn>>>(msk, attn_ptr);

    av_kernel<<<BH * (NN / 32), dim3(64, 4)>>>(attn_ptr);

    gemm64_kernel<3><<<ggrid, 256>>>(nullptr, Wo, bo, out);

    dcl_kernel<<<1, 1024>>>(dcl_ptr);
}

// round 3
// speedup vs baseline: 2.9926x; 2.9926x over previous
#include <cuda_runtime.h>
#include <math.h>
#include <stdint.h>

#define BB 4
#define NN 1024
#define DIMD 512
#define HH 8
#define DHD 64
#define INNERD 512
#define BH (BB*HH)            // 32
#define NROWS (BH*NN)         // 32768
#define SCALE 0.125f
#define INVTEMP 10.0f

// ---------------- scratch (device globals; no runtime allocation) ----------
__device__ float g_q[NROWS*DHD];
__device__ float g_k[NROWS*DHD];
__device__ float g_v[NROWS*DHD];
__device__ float g_qn[NROWS];
__device__ float g_kn[NROWS];
__device__ float g_ctx[(size_t)BB*NN*INNERD];
__device__ float g_clus[NROWS];
__device__ int   g_msum;
__device__ float g_attn_fb[(size_t)BH*NN*NN];   // fallback if d_out lacks attn region

// ---------------- init ----------------
__global__ void init_kernel() {
    if (threadIdx.x == 0 && blockIdx.x == 0) g_msum = 0;
}

// ---------------- generic 64x64 tiled SGEMM: C = A[4096x512] @ W[512x512] + bias
// MODE 0: store head-split into g_q ; 1: g_k ; 2: g_v
// MODE 3: A ignored, reads g_ctx (device symbol), plain row-major into out
template<int MODE>
__global__ void gemm64_kernel(const float* __restrict__ A,
                              const float* __restrict__ W,
                              const float* __restrict__ bias,
                              float* __restrict__ out)
{
    __shared__ float As[16][64];
    __shared__ float Bs[16][64];
    const int tid = threadIdx.x;          // 256
    const int tx = tid & 15, ty = tid >> 4;
    const int bm = blockIdx.y * 64;
    const int bn = blockIdx.x * 64;
    float acc[4][4] = {};

    const float* Aptr = (MODE == 3) ? (const float*)g_ctx : A;

    for (int k0 = 0; k0 < 512; k0 += 16) {
        {
            int r = tid >> 2, vq = tid & 3;
            float4 a = *(const float4*)(Aptr + (size_t)(bm + r) * 512 + k0 + vq * 4);
            As[vq*4+0][r] = a.x; As[vq*4+1][r] = a.y;
            As[vq*4+2][r] = a.z; As[vq*4+3][r] = a.w;
        }
        {
            int kk = tid >> 4, nq = tid & 15;
            *(float4*)&Bs[kk][nq*4] =
                *(const float4*)(W + (size_t)(k0 + kk) * 512 + bn + nq * 4);
        }
        __syncthreads();
        #pragma unroll
        for (int kk = 0; kk < 16; kk++) {
            float4 a4 = *(const float4*)&As[kk][ty*4];
            float4 b4 = *(const float4*)&Bs[kk][tx*4];
            float ar[4] = {a4.x, a4.y, a4.z, a4.w};
            float br[4] = {b4.x, b4.y, b4.z, b4.w};
            #pragma unroll
            for (int i = 0; i < 4; i++)
                #pragma unroll
                for (int j = 0; j < 4; j++)
                    acc[i][j] += ar[i] * br[j];
        }
        __syncthreads();
    }

    #pragma unroll
    for (int i = 0; i < 4; i++) {
        int m = bm + ty*4 + i;            // m = b*1024 + n
        #pragma unroll
        for (int j = 0; j < 4; j++) {
            int c = bn + tx*4 + j;        // c = h*64 + d
            float val = acc[i][j] + bias[c];
            if (MODE <= 2) {
                int b = m >> 10, n = m & 1023;
                int h = c >> 6,  d = c & 63;
                size_t idx = (((size_t)(b*HH + h) * NN + n) * DHD) + d;
                if (MODE == 0) g_q[idx] = val;
                else if (MODE == 1) g_k[idx] = val;
                else g_v[idx] = val;
            } else {
                out[(size_t)m * DIMD + c] = val;
            }
        }
    }
}

// ---------------- row norms of q and k ----------------
__global__ void norms_kernel() {
    int gw = (blockIdx.x * blockDim.x + threadIdx.x) >> 5;
    int lane = threadIdx.x & 31;
    if (gw >= 2 * NROWS) return;
    const float* src = (gw < NROWS) ? g_q : g_k;
    float* dst = (gw < NROWS) ? g_qn : g_kn;
    int row = (gw < NROWS) ? gw : gw - NROWS;
    const float* p = src + (size_t)row * DHD;
    float a = p[lane], b2 = p[lane + 32];
    float s = a * a + b2 * b2;
    #pragma unroll
    for (int o = 16; o > 0; o >>= 1) s += __shfl_xor_sync(0xffffffffu, s, o);
    if (lane == 0) dst[row] = sqrtf(s);
}

// ---------------- mask sum (integer atomics: deterministic) ----------------
__global__ void masksum_kernel(const int* __restrict__ mask) {
    const long total = (long)BB * NN * NN;
    long i = (long)blockIdx.x * blockDim.x + threadIdx.x;
    int s = 0;
    for (; i < total; i += (long)gridDim.x * blockDim.x) s += mask[i];
    #pragma unroll
    for (int o = 16; o > 0; o >>= 1) s += __shfl_xor_sync(0xffffffffu, s, o);
    __shared__ int ws[8];
    int lane = threadIdx.x & 31, w = threadIdx.x >> 5;
    if (lane == 0) ws[w] = s;
    __syncthreads();
    if (threadIdx.x < 8) {
        int v = ws[threadIdx.x];
        #pragma unroll
        for (int o = 4; o > 0; o >>= 1) v += __shfl_xor_sync(0xffu, v, o);
        if (threadIdx.x == 0) atomicAdd(&g_msum, v);
    }
}

// ============ fused scores + mask + softmax + contrastive (GEMM-style) ======
// One block = 32 q-rows of one (b,h) x full 1024 k.
// 256 threads: warp = ty (0..7) -> rows warp*4..+3; lane = tx -> cols lane*4..+3
// within a 128-wide j-tile. Scores are O(1) so softmax skips max-subtraction
// (masked entries -> exp(-1.25e8) == 0 exactly); single smem pass, one write.
#define Q_STRIDE 36
#define K_STRIDE 132
#define ES_FLOATS (32*1024)
#define QS_FLOATS (64*Q_STRIDE)
#define KS_FLOATS (64*K_STRIDE)
#define ATTN2_SMEM ((ES_FLOATS + QS_FLOATS + KS_FLOATS + 32) * 4)

__global__ __launch_bounds__(256, 1)
void attn2_kernel(const int* __restrict__ mask, float* __restrict__ attn_out)
{
    extern __shared__ float sm[];
    float* es   = sm;                                  // 32 x 1024
    float* qs   = sm + ES_FLOATS;                      // [64][36]  (d-major)
    float* ks   = sm + ES_FLOATS + QS_FLOATS;          // [64][132] (d-major)
    float* invs = sm + ES_FLOATS + QS_FLOATS + KS_FLOATS; // 32

    const int tid  = threadIdx.x;
    const int warp = tid >> 5, lane = tid & 31;
    const int blk  = blockIdx.x;          // 1024
    const int bh   = blk >> 5;
    const int i0   = (blk & 31) * 32;
    const int b    = bh >> 3;

    const float* qbase = g_q + (size_t)bh * NN * DHD;
    const float* kbase = g_k + (size_t)bh * NN * DHD;

    // load 32 q-rows transposed into qs[d][i]
    #pragma unroll
    for (int it = 0; it < 2; it++) {
        int idx = tid + it * 256;         // 512 float4
        int r = idx >> 4, q4 = idx & 15;
        float4 a = *(const float4*)(qbase + (size_t)(i0 + r) * DHD + q4 * 4);
        qs[(q4*4+0)*Q_STRIDE + r] = a.x;
        qs[(q4*4+1)*Q_STRIDE + r] = a.y;
        qs[(q4*4+2)*Q_STRIDE + r] = a.z;
        qs[(q4*4+3)*Q_STRIDE + r] = a.w;
    }

    float qn[4];
    #pragma unroll
    for (int r = 0; r < 4; r++)
        qn[r] = g_qn[bh * NN + i0 + warp * 4 + r];

    float rsum[4] = {}, rpos[4] = {}, rall[4] = {};

    for (int jt = 0; jt < 8; jt++) {
        __syncthreads();
        // load 128 k-rows transposed into ks[d][j]
        #pragma unroll
        for (int it = 0; it < 8; it++) {
            int idx = tid + it * 256;     // 2048 float4
            int r = idx >> 4, q4 = idx & 15;
            float4 a = *(const float4*)(kbase + (size_t)(jt*128 + r) * DHD + q4 * 4);
            ks[(q4*4+0)*K_STRIDE + r] = a.x;
            ks[(q4*4+1)*K_STRIDE + r] = a.y;
            ks[(q4*4+2)*K_STRIDE + r] = a.z;
            ks[(q4*4+3)*K_STRIDE + r] = a.w;
        }
        __syncthreads();

        float acc[4][4] = {};
        #pragma unroll 16
        for (int d = 0; d < 64; d++) {
            float4 qv = *(const float4*)&qs[d*Q_STRIDE + warp*4]; // broadcast
            float4 kv = *(const float4*)&ks[d*K_STRIDE + lane*4]; // conflict-free
            float qr[4] = {qv.x, qv.y, qv.z, qv.w};
            float kr[4] = {kv.x, kv.y, kv.z, kv.w};
            #pragma unroll
            for (int r = 0; r < 4; r++)
                #pragma unroll
                for (int c = 0; c < 4; c++)
                    acc[r][c] += qr[r] * kr[c];
        }

        const int j0 = jt * 128 + lane * 4;
        float4 kn4 = *(const float4*)&g_kn[bh * NN + j0];
        float knr[4] = {kn4.x, kn4.y, kn4.z, kn4.w};

        #pragma unroll
        for (int r = 0; r < 4; r++) {
            int i = i0 + warp * 4 + r;
            int4 mm = *(const int4*)(mask + ((size_t)b * NN + i) * NN + j0);
            int mr[4] = {mm.x, mm.y, mm.z, mm.w};
            float4 esv;
            float* esp = (float*)&esv;
            #pragma unroll
            for (int c = 0; c < 4; c++) {
                float dot = acc[r][c];
                float e_c = __expf(__fdividef(dot, qn[r] * knr[c]) * INVTEMP);
                rall[r] += e_c;
                if (mr[c]) rpos[r] += e_c;
                float e_s = mr[c] ? __expf(dot * SCALE) : 0.f;
                rsum[r] += e_s;
                esp[c] = e_s;
            }
            *(float4*)&es[(warp*4+r)*1024 + j0] = esv;
        }
    }

    // warp-reduce row quantities (lanes hold disjoint j subsets)
    #pragma unroll
    for (int r = 0; r < 4; r++) {
        #pragma unroll
        for (int o = 16; o > 0; o >>= 1) {
            rsum[r] += __shfl_xor_sync(0xffffffffu, rsum[r], o);
            rall[r] += __shfl_xor_sync(0xffffffffu, rall[r], o);
            rpos[r] += __shfl_xor_sync(0xffffffffu, rpos[r], o);
        }
    }
    if (lane == 0) {
        #pragma unroll
        for (int r = 0; r < 4; r++) {
            int li = warp * 4 + r;
            invs[li] = __frcp_rn(rsum[r]);
            g_clus[bh * NN + i0 + li] = -__logf(__fdividef(rpos[r], rall[r]));
        }
    }
    __syncthreads();

    // normalize + single coalesced write of attn
    #pragma unroll 4
    for (int it = 0; it < 32; it++) {
        int idx = tid + it * 256;         // 8192 float4
        int i = idx >> 8, q4 = idx & 255;
        float4 v = ((const float4*)es)[i*256 + q4];
        float s = invs[i];
        v.x *= s; v.y *= s; v.z *= s; v.w *= s;
        *(float4*)(attn_out + ((size_t)bh * NN + i0 + i) * NN + q4 * 4) = v;
    }
}

// ---------------- attn @ v -> ctx in [b, n, h*DH + d] ----------------
__global__ void av_kernel(const float* __restrict__ attn) {
    __shared__ float vsh[64 * 64];
    __shared__ float ash[32 * 64];
    const int tx = threadIdx.x;   // 0..63 -> d
    const int ty = threadIdx.y;   // 0..3
    const int tid = ty * 64 + tx;
    const int blk = blockIdx.x;   // 1024
    const int bh = blk >> 5;
    const int i0 = (blk & 31) * 32;
    const float* vbase = g_v + (size_t)bh * NN * DHD;
    const float* abase = attn + ((size_t)bh * NN + i0) * NN;
    float acc[8] = {};

    for (int jt = 0; jt < 16; jt++) {
        __syncthreads();
        {
            const float4* vs = (const float4*)(vbase + (size_t)jt * 64 * 64);
            float4* vd = (float4*)vsh;
            for (int idx = tid; idx < 1024; idx += 256) vd[idx] = vs[idx];
        }
        for (int idx = tid; idx < 512; idx += 256) {
            int r = idx >> 4, cq = idx & 15;
            ((float4*)ash)[r * 16 + cq] =
                *(const float4*)(abase + (size_t)r * NN + jt * 64 + cq * 4);
        }
        __syncthreads();
        #pragma unroll
        for (int j = 0; j < 64; j += 4) {
            float vv0 = vsh[(j+0)*64 + tx];
            float vv1 = vsh[(j+1)*64 + tx];
            float vv2 = vsh[(j+2)*64 + tx];
            float vv3 = vsh[(j+3)*64 + tx];
            #pragma unroll
            for (int r = 0; r < 8; r++) {
                float4 a = *(const float4*)&ash[(ty + r*4) * 64 + j];
                acc[r] += a.x*vv0 + a.y*vv1 + a.z*vv2 + a.w*vv3;
            }
        }
    }
    const int h = bh & 7, b = bh >> 3;
    #pragma unroll
    for (int r = 0; r < 8; r++) {
        int i = i0 + ty + r * 4;
        g_ctx[((size_t)b * NN + i) * INNERD + h * 64 + tx] = acc[r];
    }
}

// ---------------- final dcl scalar ----------------
__global__ void dcl_kernel(float* out_dcl) {
    __shared__ float red[1024];
    const int tid = threadIdx.x;
    float s = 0.f;
    const int base = tid * 32;
    #pragma unroll 8
    for (int i = 0; i < 32; i++) s += g_clus[base + i];
    red[tid] = s;
    __syncthreads();
    for (int o = 512; o > 0; o >>= 1) {
        if (tid < o) red[tid] += red[tid + o];
        __syncthreads();
    }
    if (tid == 0 && out_dcl) {
        float clus_mean = red[0] / (float)NROWS;
        float regular = ((float)g_msum - (float)(BB * NN)) /
                        ((float)BB * (float)NN * (float)(NN - 1));
        out_dcl[0] = clus_mean + 0.3f * regular;
    }
}

// ---------------- launcher ----------------
extern "C" void kernel_launch(void* const* d_in, const int* in_sizes, int n_in,
                              void* d_out, int out_size) {
    const float* x   = (const float*)d_in[0];
    const int*   msk = (const int*)  d_in[1];
    const float* Wq  = (const float*)d_in[2];
    const float* bq  = (const float*)d_in[3];
    const float* Wk  = (const float*)d_in[4];
    const float* bk  = (const float*)d_in[5];
    const float* Wv  = (const float*)d_in[6];
    const float* bv  = (const float*)d_in[7];
    const float* Wo  = (const float*)d_in[8];
    const float* bo  = (const float*)d_in[9];
    float* out = (float*)d_out;

    const size_t OUTE  = (size_t)BB * NN * DIMD;   // 2097152
    const size_t ATTNE = (size_t)BH * NN * NN;     // 33554432

    float* attn_ptr;
    if ((size_t)out_size >= OUTE + ATTNE) {
        attn_ptr = out + OUTE;
    } else {
        void* p = nullptr;
        cudaGetSymbolAddress(&p, g_attn_fb);
        attn_ptr = (float*)p;
    }
    float* dcl_ptr = ((size_t)out_size >= OUTE + ATTNE + 1) ? (out + OUTE + ATTNE)
                                                            : nullptr;

    cudaFuncSetAttribute(attn2_kernel,
                         cudaFuncAttributeMaxDynamicSharedMemorySize, ATTN2_SMEM);

    init_kernel<<<1, 32>>>();

    dim3 ggrid(DIMD / 64, (BB * NN) / 64);          // (8, 64)
    gemm64_kernel<0><<<ggrid, 256>>>(x, Wq, bq, nullptr);
    gemm64_kernel<1><<<ggrid, 256>>>(x, Wk, bk, nullptr);
    gemm64_kernel<2><<<ggrid, 256>>>(x, Wv, bv, nullptr);

    norms_kernel<<<(2 * NROWS) / 8, 256>>>();       // 8192 blocks, warp/row
    masksum_kernel<<<512, 256>>>(msk);

    attn2_kernel<<<BH * (NN / 32), 256, ATTN2_SMEM>>>(msk, attn_ptr);

    av_kernel<<<BH * (NN / 32), dim3(64, 4)>>>(attn_ptr);

    gemm64_kernel<3><<<ggrid, 256>>>(nullptr, Wo, bo, out);

    dcl_kernel<<<1, 1024>>>(dcl_ptr);
}

// round 4
// speedup vs baseline: 3.7921x; 1.2671x over previous
#include <cuda_runtime.h>
#include <math.h>
#include <stdint.h>

#define BB 4
#define NN 1024
#define DIMD 512
#define HH 8
#define DHD 64
#define INNERD 512
#define BH (BB*HH)            // 32
#define NROWS (BH*NN)         // 32768
#define SCALE 0.125f
#define INVTEMP 10.0f

// ---------------- scratch (device globals; no runtime allocation) ----------
__device__ float g_q[NROWS*DHD];            // [bh][n][d]
__device__ float g_k[NROWS*DHD];            // TRANSPOSED: [bh][d][n]
__device__ float g_v[NROWS*DHD];            // [bh][n][d]
__device__ float g_qn[NROWS];
__device__ float g_kn[NROWS];
__device__ float g_ctx[(size_t)BB*NN*INNERD];
__device__ float g_clus[NROWS];
__device__ int   g_msum;
__device__ float g_attn_fb[(size_t)BH*NN*NN];   // fallback if d_out lacks attn region

// ---------------- init ----------------
__global__ void init_kernel() {
    if (threadIdx.x == 0 && blockIdx.x == 0) g_msum = 0;
}

// ============ 128x128 tiled SGEMM, 8x8 micro-tile ============
// C = A[4096x512] @ W[512x512] + bias
// MODE 0: head-split into g_q ; 1: TRANSPOSED head-split into g_k ; 2: g_v
// MODE 3: A ignored, reads g_ctx, row-major into out
template<int MODE>
__global__ __launch_bounds__(256)
void gemm128_kernel(const float* __restrict__ A,
                    const float* __restrict__ W,
                    const float* __restrict__ bias,
                    float* __restrict__ out)
{
    __shared__ float As[16][132];
    __shared__ float Bs[16][132];
    const int tid = threadIdx.x;
    const int tx = tid & 15, ty = tid >> 4;
    const int bm = blockIdx.y * 128, bn = blockIdx.x * 128;
    const float* Aptr = (MODE == 3) ? (const float*)g_ctx : A;

    const int lr = tid >> 1;              // A-load row 0..127
    const int lk = (tid & 1) * 8;         // A-load k offset
    const int bk = tid >> 4;              // B-load k row 0..15
    const int bn4 = tid & 15;

    float acc[8][8] = {};
    float4 a0, a1, b0, b1;

    // prefetch chunk 0
    a0 = *(const float4*)(Aptr + (size_t)(bm + lr) * 512 + lk);
    a1 = *(const float4*)(Aptr + (size_t)(bm + lr) * 512 + lk + 4);
    b0 = *(const float4*)(W + (size_t)bk * 512 + bn + bn4 * 4);
    b1 = *(const float4*)(W + (size_t)bk * 512 + bn + 64 + bn4 * 4);

    for (int k0 = 0; k0 < 512; k0 += 16) {
        __syncthreads();
        As[lk+0][lr] = a0.x; As[lk+1][lr] = a0.y;
        As[lk+2][lr] = a0.z; As[lk+3][lr] = a0.w;
        As[lk+4][lr] = a1.x; As[lk+5][lr] = a1.y;
        As[lk+6][lr] = a1.z; As[lk+7][lr] = a1.w;
        *(float4*)&Bs[bk][bn4*4]      = b0;
        *(float4*)&Bs[bk][64+bn4*4]   = b1;
        __syncthreads();
        if (k0 + 16 < 512) {
            a0 = *(const float4*)(Aptr + (size_t)(bm + lr) * 512 + k0 + 16 + lk);
            a1 = *(const float4*)(Aptr + (size_t)(bm + lr) * 512 + k0 + 16 + lk + 4);
            b0 = *(const float4*)(W + (size_t)(k0 + 16 + bk) * 512 + bn + bn4 * 4);
            b1 = *(const float4*)(W + (size_t)(k0 + 16 + bk) * 512 + bn + 64 + bn4 * 4);
        }
        #pragma unroll
        for (int kk = 0; kk < 16; kk++) {
            float4 x0 = *(const float4*)&As[kk][ty*4];
            float4 x1 = *(const float4*)&As[kk][64+ty*4];
            float4 y0 = *(const float4*)&Bs[kk][tx*4];
            float4 y1 = *(const float4*)&Bs[kk][64+tx*4];
            float xa[8] = {x0.x,x0.y,x0.z,x0.w,x1.x,x1.y,x1.z,x1.w};
            float yb[8] = {y0.x,y0.y,y0.z,y0.w,y1.x,y1.y,y1.z,y1.w};
            #pragma unroll
            for (int i = 0; i < 8; i++)
                #pragma unroll
                for (int j = 0; j < 8; j++)
                    acc[i][j] += xa[i] * yb[j];
        }
    }

    // epilogue
    float4 bias0 = *(const float4*)(bias + bn + tx*4);
    float4 bias1 = *(const float4*)(bias + bn + 64 + tx*4);
    float bb0[4] = {bias0.x, bias0.y, bias0.z, bias0.w};
    float bb1[4] = {bias1.x, bias1.y, bias1.z, bias1.w};

    if (MODE == 1) {
        // transposed store: g_k[((b*8+h)*64 + d)*1024 + n]
        const int b = bm >> 10;
        const int n0 = bm & 1023;
        #pragma unroll
        for (int jh = 0; jh < 2; jh++) {
            #pragma unroll
            for (int jj = 0; jj < 4; jj++) {
                int c = bn + jh*64 + tx*4 + jj;
                int h = c >> 6, d = c & 63;
                float bv = jh ? bb1[jj] : bb0[jj];
                int j = jh*4 + jj;
                float4 v0 = make_float4(acc[0][j]+bv, acc[1][j]+bv,
                                        acc[2][j]+bv, acc[3][j]+bv);
                float4 v1 = make_float4(acc[4][j]+bv, acc[5][j]+bv,
                                        acc[6][j]+bv, acc[7][j]+bv);
                size_t base = ((size_t)((b*HH + h)*DHD + d)) * NN;
                *(float4*)&g_k[base + n0 + ty*4]      = v0;
                *(float4*)&g_k[base + n0 + 64 + ty*4] = v1;
            }
        }
    } else {
        #pragma unroll
        for (int i = 0; i < 8; i++) {
            int m = bm + ((i < 4) ? (ty*4 + i) : (64 + ty*4 + i - 4));
            #pragma unroll
            for (int jh = 0; jh < 2; jh++) {
                int c0 = bn + jh*64 + tx*4;
                float4 v;
                v.x = acc[i][jh*4+0] + (jh ? bb1[0] : bb0[0]);
                v.y = acc[i][jh*4+1] + (jh ? bb1[1] : bb0[1]);
                v.z = acc[i][jh*4+2] + (jh ? bb1[2] : bb0[2]);
                v.w = acc[i][jh*4+3] + (jh ? bb1[3] : bb0[3]);
                if (MODE == 3) {
                    *(float4*)(out + (size_t)m * DIMD + c0) = v;
                } else {
                    int b = m >> 10, n = m & 1023;
                    int h = c0 >> 6, d0 = c0 & 63;
                    size_t idx = (((size_t)(b*HH + h) * NN + n) * DHD) + d0;
                    if (MODE == 0) *(float4*)&g_q[idx] = v;
                    else           *(float4*)&g_v[idx] = v;
                }
            }
        }
    }
}

// ---------------- q row norms (g_q row-major) ----------------
__global__ void qnorm_kernel() {
    int gw = (blockIdx.x * blockDim.x + threadIdx.x) >> 5;
    int lane = threadIdx.x & 31;
    if (gw >= NROWS) return;
    const float* p = g_q + (size_t)gw * DHD;
    float a = p[lane], b2 = p[lane + 32];
    float s = a * a + b2 * b2;
    #pragma unroll
    for (int o = 16; o > 0; o >>= 1) s += __shfl_xor_sync(0xffffffffu, s, o);
    if (lane == 0) g_qn[gw] = sqrtf(s);
}

// ---------------- k norms (g_k transposed layout) ----------------
__global__ void knormT_kernel() {
    const int bh = blockIdx.x;
    const int tid = threadIdx.x;    // 256, 4 cols each
    const float* base = g_k + (size_t)bh * DHD * NN;
    float s0 = 0.f, s1 = 0.f, s2 = 0.f, s3 = 0.f;
    #pragma unroll 8
    for (int d = 0; d < 64; d++) {
        float4 v = *(const float4*)(base + (size_t)d * NN + tid * 4);
        s0 += v.x*v.x; s1 += v.y*v.y; s2 += v.z*v.z; s3 += v.w*v.w;
    }
    float4 o = make_float4(sqrtf(s0), sqrtf(s1), sqrtf(s2), sqrtf(s3));
    *(float4*)&g_kn[bh * NN + tid * 4] = o;
}

// ---------------- mask sum (integer atomics: deterministic) ----------------
__global__ void masksum_kernel(const int* __restrict__ mask) {
    const long total = (long)BB * NN * NN;
    long i = (long)blockIdx.x * blockDim.x + threadIdx.x;
    int s = 0;
    for (; i < total; i += (long)gridDim.x * blockDim.x) s += mask[i];
    #pragma unroll
    for (int o = 16; o > 0; o >>= 1) s += __shfl_xor_sync(0xffffffffu, s, o);
    __shared__ int ws[8];
    int lane = threadIdx.x & 31, w = threadIdx.x >> 5;
    if (lane == 0) ws[w] = s;
    __syncthreads();
    if (threadIdx.x < 8) {
        int v = ws[threadIdx.x];
        #pragma unroll
        for (int o = 4; o > 0; o >>= 1) v += __shfl_xor_sync(0xffu, v, o);
        if (threadIdx.x == 0) atomicAdd(&g_msum, v);
    }
}

// ============ fused scores + softmax + contrastive + attn@V ============
// Block = 32 q-rows of one (b,h). Phase A: scores GEMM (4x8 micro, 256-wide
// j-tiles), exp epilogue into smem es. Phase B: ctx = es @ V from smem,
// scaled by row inverse. attn written normalized once.
#define ES_STRIDE 1036
#define KS_STRIDE 264
#define VS_STRIDE 68
#define ES_FLOATS (32*ES_STRIDE)
#define QS_FLOATS (64*36)
#define KS_FLOATS (64*KS_STRIDE)
#define ATTN_SMEM ((ES_FLOATS + QS_FLOATS + KS_FLOATS + 32) * 4)

__global__ __launch_bounds__(256, 1)
void attn2_kernel(const int* __restrict__ mask, float* __restrict__ attn_out)
{
    extern __shared__ float sm[];
    float* es   = sm;                                   // [32][1036]
    float* qs   = sm + ES_FLOATS;                       // [64][36] / reduce buf
    float* ks   = sm + ES_FLOATS + QS_FLOATS;           // [64][264] / V [128][68]
    float* invs = sm + ES_FLOATS + QS_FLOATS + KS_FLOATS; // 32

    const int tid  = threadIdx.x;
    const int warp = tid >> 5, lane = tid & 31;
    const int blk  = blockIdx.x;          // 1024
    const int bh   = blk >> 5;
    const int i0   = (blk & 31) * 32;
    const int b    = bh >> 3;

    const float* qbase = g_q + (size_t)bh * NN * DHD;
    const float* ktbase = g_k + (size_t)bh * DHD * NN;  // [d][n]
    const float* vbase = g_v + (size_t)bh * NN * DHD;

    // load 32 q-rows transposed into qs[d][i]
    #pragma unroll
    for (int it = 0; it < 2; it++) {
        int idx = tid + it * 256;         // 512 float4
        int r = idx >> 4, q4 = idx & 15;
        float4 a = *(const float4*)(qbase + (size_t)(i0 + r) * DHD + q4 * 4);
        qs[(q4*4+0)*36 + r] = a.x;
        qs[(q4*4+1)*36 + r] = a.y;
        qs[(q4*4+2)*36 + r] = a.z;
        qs[(q4*4+3)*36 + r] = a.w;
    }

    float qn[4];
    #pragma unroll
    for (int r = 0; r < 4; r++)
        qn[r] = g_qn[bh * NN + i0 + warp * 4 + r];

    float rsum[4] = {}, rpos[4] = {}, rall[4] = {};

    // ---- Phase A: 4 j-tiles of 256 ----
    for (int jt = 0; jt < 4; jt++) {
        __syncthreads();
        // load k tile [64 d][256 j] directly (K already transposed in gmem)
        #pragma unroll
        for (int it = 0; it < 16; it++) {
            int idx = tid + it * 256;     // 4096 float4
            int d = idx >> 6, j4 = idx & 63;
            float4 a = *(const float4*)(ktbase + (size_t)d * NN + jt * 256 + j4 * 4);
            *(float4*)&ks[d * KS_STRIDE + j4 * 4] = a;
        }
        __syncthreads();

        float acc[4][8] = {};
        #pragma unroll 16
        for (int d = 0; d < 64; d++) {
            float4 qv = *(const float4*)&qs[d*36 + warp*4];           // broadcast
            float4 k0 = *(const float4*)&ks[d*KS_STRIDE + lane*4];
            float4 k1 = *(const float4*)&ks[d*KS_STRIDE + 128 + lane*4];
            float qr[4] = {qv.x, qv.y, qv.z, qv.w};
            float kr[8] = {k0.x,k0.y,k0.z,k0.w,k1.x,k1.y,k1.z,k1.w};
            #pragma unroll
            for (int r = 0; r < 4; r++)
                #pragma unroll
                for (int c = 0; c < 8; c++)
                    acc[r][c] += qr[r] * kr[c];
        }

        #pragma unroll
        for (int half = 0; half < 2; half++) {
            const int j0 = jt * 256 + half * 128 + lane * 4;
            float4 kn4 = *(const float4*)&g_kn[bh * NN + j0];
            float knr[4] = {kn4.x, kn4.y, kn4.z, kn4.w};
            #pragma unroll
            for (int r = 0; r < 4; r++) {
                int i = i0 + warp * 4 + r;
                int4 mm = *(const int4*)(mask + ((size_t)b * NN + i) * NN + j0);
                int mr[4] = {mm.x, mm.y, mm.z, mm.w};
                float4 esv;
                float* esp = (float*)&esv;
                #pragma unroll
                for (int c = 0; c < 4; c++) {
                    float dot = acc[r][half*4 + c];
                    float e_c = __expf(__fdividef(dot, qn[r] * knr[c]) * INVTEMP);
                    rall[r] += e_c;
                    if (mr[c]) rpos[r] += e_c;
                    float e_s = mr[c] ? __expf(dot * SCALE) : 0.f;
                    rsum[r] += e_s;
                    esp[c] = e_s;
                }
                *(float4*)&es[(warp*4+r)*ES_STRIDE + j0] = esv;
            }
        }
    }

    // warp-reduce row quantities
    #pragma unroll
    for (int r = 0; r < 4; r++) {
        #pragma unroll
        for (int o = 16; o > 0; o >>= 1) {
            rsum[r] += __shfl_xor_sync(0xffffffffu, rsum[r], o);
            rall[r] += __shfl_xor_sync(0xffffffffu, rall[r], o);
            rpos[r] += __shfl_xor_sync(0xffffffffu, rpos[r], o);
        }
    }
    if (lane == 0) {
        #pragma unroll
        for (int r = 0; r < 4; r++) {
            int li = warp * 4 + r;
            invs[li] = __frcp_rn(rsum[r]);
            g_clus[bh * NN + i0 + li] = -__logf(__fdividef(rpos[r], rall[r]));
        }
    }
    __syncthreads();

    // write attn normalized (coalesced)
    #pragma unroll 4
    for (int it = 0; it < 32; it++) {
        int idx = tid + it * 256;         // 8192 float4
        int i = idx >> 8, q4 = idx & 255;
        float4 v = *(const float4*)&es[i*ES_STRIDE + q4*4];
        float s = invs[i];
        v.x *= s; v.y *= s; v.z *= s; v.w *= s;
        *(float4*)(attn_out + ((size_t)bh * NN + i0 + i) * NN + q4 * 4) = v;
    }

    // ---- Phase B: ctx = es @ V (V streamed through ks region) ----
    const int sub = warp & 1;                  // j-half within tile
    const int ipair = (warp >> 1) * 4 + ((lane >> 3) & 3);  // 0..15
    const int d4 = lane & 7;
    float av0[8] = {}, av1[8] = {};

    for (int jt = 0; jt < 8; jt++) {
        __syncthreads();
        #pragma unroll
        for (int it = 0; it < 8; it++) {
            int idx = tid + it * 256;     // 2048 float4
            int r = idx >> 4, q4 = idx & 15;
            float4 a = *(const float4*)(vbase + (size_t)(jt*128 + r) * DHD + q4 * 4);
            *(float4*)&ks[r * VS_STRIDE + q4 * 4] = a;
        }
        __syncthreads();
        const float* e0p = &es[(ipair*2+0)*ES_STRIDE + jt*128 + sub*64];
        const float* e1p = e0p + ES_STRIDE;
        const float* vp  = &ks[(sub*64) * VS_STRIDE];
        #pragma unroll 8
        for (int j = 0; j < 64; j++) {
            float e0 = e0p[j], e1 = e1p[j];
            float4 v0 = *(const float4*)(vp + j*VS_STRIDE + d4*4);
            float4 v1 = *(const float4*)(vp + j*VS_STRIDE + 32 + d4*4);
            float vv[8] = {v0.x,v0.y,v0.z,v0.w,v1.x,v1.y,v1.z,v1.w};
            #pragma unroll
            for (int k2 = 0; k2 < 8; k2++) {
                av0[k2] += e0 * vv[k2];
                av1[k2] += e1 * vv[k2];
            }
        }
    }

    // reduce sub pairs through smem (qs region) and write ctx
    float* red = qs;
    __syncthreads();
    if (sub == 1) {
        int rid = (ipair * 8 + d4) * 16;
        *(float4*)&red[rid + 0]  = make_float4(av0[0], av0[1], av0[2], av0[3]);
        *(float4*)&red[rid + 4]  = make_float4(av0[4], av0[5], av0[6], av0[7]);
        *(float4*)&red[rid + 8]  = make_float4(av1[0], av1[1], av1[2], av1[3]);
        *(float4*)&red[rid + 12] = make_float4(av1[4], av1[5], av1[6], av1[7]);
    }
    __syncthreads();
    if (sub == 0) {
        int rid = (ipair * 8 + d4) * 16;
        const int h = bh & 7;
        #pragma unroll
        for (int r = 0; r < 2; r++) {
            float* avp = r ? av1 : av0;
            float4 p0 = *(const float4*)&red[rid + r*8];
            float4 p1 = *(const float4*)&red[rid + r*8 + 4];
            int i = ipair * 2 + r;
            float s = invs[i];
            float4 o0 = make_float4((avp[0]+p0.x)*s, (avp[1]+p0.y)*s,
                                    (avp[2]+p0.z)*s, (avp[3]+p0.w)*s);
            float4 o1 = make_float4((avp[4]+p1.x)*s, (avp[5]+p1.y)*s,
                                    (avp[6]+p1.z)*s, (avp[7]+p1.w)*s);
            size_t base = ((size_t)b * NN + i0 + i) * INNERD + h * DHD;
            *(float4*)&g_ctx[base + d4*4]      = o0;
            *(float4*)&g_ctx[base + 32 + d4*4] = o1;
        }
    }
}

// ---------------- final dcl scalar ----------------
__global__ void dcl_kernel(float* out_dcl) {
    __shared__ float red[1024];
    const int tid = threadIdx.x;
    float s = 0.f;
    const int base = tid * 32;
    #pragma unroll 8
    for (int i = 0; i < 32; i++) s += g_clus[base + i];
    red[tid] = s;
    __syncthreads();
    for (int o = 512; o > 0; o >>= 1) {
        if (tid < o) red[tid] += red[tid + o];
        __syncthreads();
    }
    if (tid == 0 && out_dcl) {
        float clus_mean = red[0] / (float)NROWS;
        float regular = ((float)g_msum - (float)(BB * NN)) /
                        ((float)BB * (float)NN * (float)(NN - 1));
        out_dcl[0] = clus_mean + 0.3f * regular;
    }
}

// ---------------- launcher ----------------
extern "C" void kernel_launch(void* const* d_in, const int* in_sizes, int n_in,
                              void* d_out, int out_size) {
    const float* x   = (const float*)d_in[0];
    const int*   msk = (const int*)  d_in[1];
    const float* Wq  = (const float*)d_in[2];
    const float* bq  = (const float*)d_in[3];
    const float* Wk  = (const float*)d_in[4];
    const float* bk  = (const float*)d_in[5];
    const float* Wv  = (const float*)d_in[6];
    const float* bv  = (const float*)d_in[7];
    const float* Wo  = (const float*)d_in[8];
    const float* bo  = (const float*)d_in[9];
    float* out = (float*)d_out;

    const size_t OUTE  = (size_t)BB * NN * DIMD;   // 2097152
    const size_t ATTNE = (size_t)BH * NN * NN;     // 33554432

    float* attn_ptr;
    if ((size_t)out_size >= OUTE + ATTNE) {
        attn_ptr = out + OUTE;
    } else {
        void* p = nullptr;
        cudaGetSymbolAddress(&p, g_attn_fb);
        attn_ptr = (float*)p;
    }
    float* dcl_ptr = ((size_t)out_size >= OUTE + ATTNE + 1) ? (out + OUTE + ATTNE)
                                                            : nullptr;

    cudaFuncSetAttribute(attn2_kernel,
                         cudaFuncAttributeMaxDynamicSharedMemorySize, ATTN_SMEM);

    init_kernel<<<1, 32>>>();

    dim3 ggrid(DIMD / 128, (BB * NN) / 128);        // (4, 32)
    gemm128_kernel<0><<<ggrid, 256>>>(x, Wq, bq, nullptr);
    gemm128_kernel<1><<<ggrid, 256>>>(x, Wk, bk, nullptr);
    gemm128_kernel<2><<<ggrid, 256>>>(x, Wv, bv, nullptr);

    qnorm_kernel<<<NROWS / 8, 256>>>();
    knormT_kernel<<<BH, 256>>>();
    masksum_kernel<<<512, 256>>>(msk);

    attn2_kernel<<<BH * (NN / 32), 256, ATTN_SMEM>>>(msk, attn_ptr);

    gemm128_kernel<3><<<ggrid, 256>>>(nullptr, Wo, bo, out);

    dcl_kernel<<<1, 1024>>>(dcl_ptr);
}

// round 5
// speedup vs baseline: 3.8825x; 1.0238x over previous
#include <cuda_runtime.h>
#include <math.h>
#include <stdint.h>

#define BB 4
#define NN 1024
#define DIMD 512
#define HH 8
#define DHD 64
#define INNERD 512
#define BH (BB*HH)            // 32
#define NROWS (BH*NN)         // 32768
#define SCALE 0.125f

// ---------------- scratch (device globals; no runtime allocation) ----------
__device__ float g_q[NROWS*DHD];            // [bh][n][d]
__device__ float g_k[NROWS*DHD];            // TRANSPOSED: [bh][d][n]
__device__ float g_v[NROWS*DHD];            // [bh][n][d]
__device__ float g_qni[NROWS];              // reciprocal q norms
__device__ float g_kni[NROWS];              // reciprocal k norms
__device__ float g_ctx[(size_t)BB*NN*INNERD];
__device__ float g_clus[NROWS];
__device__ int   g_msum;                    // 8 * sum(mask)
__device__ float g_attn_fb[(size_t)BH*NN*NN];

// ---------------- init ----------------
__global__ void init_kernel() {
    if (threadIdx.x == 0 && blockIdx.x == 0) g_msum = 0;
}

// ============ fused QKV projection: z selects Wq/Wk/Wv ============
// 128x128 tile, 8x8 micro. z=0 -> g_q + inv norms; z=1 -> g_k transposed +
// inv norms; z=2 -> g_v.
__global__ __launch_bounds__(256)
void qkv_kernel(const float* __restrict__ x,
                const float* __restrict__ Wq, const float* __restrict__ bq,
                const float* __restrict__ Wk, const float* __restrict__ bk,
                const float* __restrict__ Wv, const float* __restrict__ bv)
{
    __shared__ float As[16][132];
    __shared__ float Bs[16][132];
    const int tid = threadIdx.x;
    const int tx = tid & 15, ty = tid >> 4;
    const int bm = blockIdx.y * 128, bn = blockIdx.x * 128;
    const int z = blockIdx.z;
    const float* W    = (z == 0) ? Wq : (z == 1) ? Wk : Wv;
    const float* bias = (z == 0) ? bq : (z == 1) ? bk : bv;

    const int lr = tid >> 1;
    const int lk = (tid & 1) * 8;
    const int bk2 = tid >> 4;
    const int bn4 = tid & 15;

    float acc[8][8] = {};
    float4 a0, a1, b0, b1;

    a0 = *(const float4*)(x + (size_t)(bm + lr) * 512 + lk);
    a1 = *(const float4*)(x + (size_t)(bm + lr) * 512 + lk + 4);
    b0 = *(const float4*)(W + (size_t)bk2 * 512 + bn + bn4 * 4);
    b1 = *(const float4*)(W + (size_t)bk2 * 512 + bn + 64 + bn4 * 4);

    for (int k0 = 0; k0 < 512; k0 += 16) {
        __syncthreads();
        As[lk+0][lr] = a0.x; As[lk+1][lr] = a0.y;
        As[lk+2][lr] = a0.z; As[lk+3][lr] = a0.w;
        As[lk+4][lr] = a1.x; As[lk+5][lr] = a1.y;
        As[lk+6][lr] = a1.z; As[lk+7][lr] = a1.w;
        *(float4*)&Bs[bk2][bn4*4]    = b0;
        *(float4*)&Bs[bk2][64+bn4*4] = b1;
        __syncthreads();
        if (k0 + 16 < 512) {
            a0 = *(const float4*)(x + (size_t)(bm + lr) * 512 + k0 + 16 + lk);
            a1 = *(const float4*)(x + (size_t)(bm + lr) * 512 + k0 + 16 + lk + 4);
            b0 = *(const float4*)(W + (size_t)(k0 + 16 + bk2) * 512 + bn + bn4 * 4);
            b1 = *(const float4*)(W + (size_t)(k0 + 16 + bk2) * 512 + bn + 64 + bn4 * 4);
        }
        #pragma unroll
        for (int kk = 0; kk < 16; kk++) {
            float4 x0 = *(const float4*)&As[kk][ty*4];
            float4 x1 = *(const float4*)&As[kk][64+ty*4];
            float4 y0 = *(const float4*)&Bs[kk][tx*4];
            float4 y1 = *(const float4*)&Bs[kk][64+tx*4];
            float xa[8] = {x0.x,x0.y,x0.z,x0.w,x1.x,x1.y,x1.z,x1.w};
            float yb[8] = {y0.x,y0.y,y0.z,y0.w,y1.x,y1.y,y1.z,y1.w};
            #pragma unroll
            for (int i = 0; i < 8; i++)
                #pragma unroll
                for (int j = 0; j < 8; j++)
                    acc[i][j] += xa[i] * yb[j];
        }
    }

    float4 bias0 = *(const float4*)(bias + bn + tx*4);
    float4 bias1 = *(const float4*)(bias + bn + 64 + tx*4);
    float bb0[4] = {bias0.x, bias0.y, bias0.z, bias0.w};
    float bb1[4] = {bias1.x, bias1.y, bias1.z, bias1.w};

    float ss[8][2];
    #pragma unroll
    for (int i = 0; i < 8; i++) { ss[i][0] = 0.f; ss[i][1] = 0.f; }

    if (z == 1) {
        // transposed store: g_k[((b*8+h)*64 + d)*1024 + n]
        const int b = bm >> 10;
        const int n0 = bm & 1023;
        #pragma unroll
        for (int jh = 0; jh < 2; jh++) {
            #pragma unroll
            for (int jj = 0; jj < 4; jj++) {
                int c = bn + jh*64 + tx*4 + jj;
                int h = c >> 6, d = c & 63;
                float bv2 = jh ? bb1[jj] : bb0[jj];
                int j = jh*4 + jj;
                float vr[8];
                #pragma unroll
                for (int i = 0; i < 8; i++) {
                    vr[i] = acc[i][j] + bv2;
                    ss[i][jh] += vr[i] * vr[i];
                }
                size_t base = ((size_t)((b*HH + h)*DHD + d)) * NN;
                *(float4*)&g_k[base + n0 + ty*4] =
                    make_float4(vr[0], vr[1], vr[2], vr[3]);
                *(float4*)&g_k[base + n0 + 64 + ty*4] =
                    make_float4(vr[4], vr[5], vr[6], vr[7]);
            }
        }
    } else {
        #pragma unroll
        for (int i = 0; i < 8; i++) {
            int m = bm + ((i < 4) ? (ty*4 + i) : (64 + ty*4 + i - 4));
            #pragma unroll
            for (int jh = 0; jh < 2; jh++) {
                int c0 = bn + jh*64 + tx*4;
                float v0 = acc[i][jh*4+0] + (jh ? bb1[0] : bb0[0]);
                float v1 = acc[i][jh*4+1] + (jh ? bb1[1] : bb0[1]);
                float v2 = acc[i][jh*4+2] + (jh ? bb1[2] : bb0[2]);
                float v3 = acc[i][jh*4+3] + (jh ? bb1[3] : bb0[3]);
                if (z == 0)
                    ss[i][jh] += v0*v0 + v1*v1 + v2*v2 + v3*v3;
                int b = m >> 10, n = m & 1023;
                int h = c0 >> 6, d0 = c0 & 63;
                size_t idx = (((size_t)(b*HH + h) * NN + n) * DHD) + d0;
                float4 v = make_float4(v0, v1, v2, v3);
                if (z == 0) *(float4*)&g_q[idx] = v;
                else        *(float4*)&g_v[idx] = v;
            }
        }
    }

    if (z < 2) {
        float* dst = (z == 0) ? g_qni : g_kni;
        #pragma unroll
        for (int i = 0; i < 8; i++) {
            #pragma unroll
            for (int jh = 0; jh < 2; jh++) {
                float s = ss[i][jh];
                s += __shfl_xor_sync(0xffffffffu, s, 1);
                s += __shfl_xor_sync(0xffffffffu, s, 2);
                s += __shfl_xor_sync(0xffffffffu, s, 4);
                s += __shfl_xor_sync(0xffffffffu, s, 8);
                if (tx == 0) {
                    int m = bm + ((i < 4) ? (ty*4 + i) : (64 + ty*4 + i - 4));
                    int b = m >> 10, n = m & 1023;
                    int h = (bn >> 6) + jh;
                    dst[(b*HH + h) * NN + n] = rsqrtf(s);
                }
            }
        }
    }
}

// ============ out projection: out = g_ctx @ Wo + bo ============
__global__ __launch_bounds__(256)
void outproj_kernel(const float* __restrict__ W,
                    const float* __restrict__ bias,
                    float* __restrict__ out)
{
    __shared__ float As[16][132];
    __shared__ float Bs[16][132];
    const int tid = threadIdx.x;
    const int tx = tid & 15, ty = tid >> 4;
    const int bm = blockIdx.y * 128, bn = blockIdx.x * 128;
    const float* Aptr = (const float*)g_ctx;

    const int lr = tid >> 1;
    const int lk = (tid & 1) * 8;
    const int bk2 = tid >> 4;
    const int bn4 = tid & 15;

    float acc[8][8] = {};
    float4 a0, a1, b0, b1;

    a0 = *(const float4*)(Aptr + (size_t)(bm + lr) * 512 + lk);
    a1 = *(const float4*)(Aptr + (size_t)(bm + lr) * 512 + lk + 4);
    b0 = *(const float4*)(W + (size_t)bk2 * 512 + bn + bn4 * 4);
    b1 = *(const float4*)(W + (size_t)bk2 * 512 + bn + 64 + bn4 * 4);

    for (int k0 = 0; k0 < 512; k0 += 16) {
        __syncthreads();
        As[lk+0][lr] = a0.x; As[lk+1][lr] = a0.y;
        As[lk+2][lr] = a0.z; As[lk+3][lr] = a0.w;
        As[lk+4][lr] = a1.x; As[lk+5][lr] = a1.y;
        As[lk+6][lr] = a1.z; As[lk+7][lr] = a1.w;
        *(float4*)&Bs[bk2][bn4*4]    = b0;
        *(float4*)&Bs[bk2][64+bn4*4] = b1;
        __syncthreads();
        if (k0 + 16 < 512) {
            a0 = *(const float4*)(Aptr + (size_t)(bm + lr) * 512 + k0 + 16 + lk);
            a1 = *(const float4*)(Aptr + (size_t)(bm + lr) * 512 + k0 + 16 + lk + 4);
            b0 = *(const float4*)(W + (size_t)(k0 + 16 + bk2) * 512 + bn + bn4 * 4);
            b1 = *(const float4*)(W + (size_t)(k0 + 16 + bk2) * 512 + bn + 64 + bn4 * 4);
        }
        #pragma unroll
        for (int kk = 0; kk < 16; kk++) {
            float4 x0 = *(const float4*)&As[kk][ty*4];
            float4 x1 = *(const float4*)&As[kk][64+ty*4];
            float4 y0 = *(const float4*)&Bs[kk][tx*4];
            float4 y1 = *(const float4*)&Bs[kk][64+tx*4];
            float xa[8] = {x0.x,x0.y,x0.z,x0.w,x1.x,x1.y,x1.z,x1.w};
            float yb[8] = {y0.x,y0.y,y0.z,y0.w,y1.x,y1.y,y1.z,y1.w};
            #pragma unroll
            for (int i = 0; i < 8; i++)
                #pragma unroll
                for (int j = 0; j < 8; j++)
                    acc[i][j] += xa[i] * yb[j];
        }
    }

    float4 bias0 = *(const float4*)(bias + bn + tx*4);
    float4 bias1 = *(const float4*)(bias + bn + 64 + tx*4);
    float bb0[4] = {bias0.x, bias0.y, bias0.z, bias0.w};
    float bb1[4] = {bias1.x, bias1.y, bias1.z, bias1.w};

    #pragma unroll
    for (int i = 0; i < 8; i++) {
        int m = bm + ((i < 4) ? (ty*4 + i) : (64 + ty*4 + i - 4));
        #pragma unroll
        for (int jh = 0; jh < 2; jh++) {
            int c0 = bn + jh*64 + tx*4;
            float4 v;
            v.x = acc[i][jh*4+0] + (jh ? bb1[0] : bb0[0]);
            v.y = acc[i][jh*4+1] + (jh ? bb1[1] : bb0[1]);
            v.z = acc[i][jh*4+2] + (jh ? bb1[2] : bb0[2]);
            v.w = acc[i][jh*4+3] + (jh ? bb1[3] : bb0[3]);
            *(float4*)(out + (size_t)m * DIMD + c0) = v;
        }
    }
}

// ============ fused scores + softmax + contrastive + attn@V ============
// Block = 32 q-rows of one (b,h). Phase A: 128-wide k-tiles (register
// double-buffered), 4x4 micro, exp epilogue into smem es + mask count.
// Phase B: ctx = es @ V (v tiles register double-buffered).
#define ES_STRIDE 1036
#define QS_STRIDE 36
#define KS_STRIDE 132
#define VS_STRIDE 68
#define ES_FLOATS (32*ES_STRIDE)
#define QS_FLOATS (64*QS_STRIDE)
#define KV_FLOATS (128*VS_STRIDE)   // 8704 >= 64*132=8448
#define ATTN_SMEM ((ES_FLOATS + QS_FLOATS + KV_FLOATS + 48) * 4)

__global__ __launch_bounds__(256, 1)
void attn2_kernel(const int* __restrict__ mask, float* __restrict__ attn_out)
{
    extern __shared__ float sm[];
    float* es   = sm;                       // [32][1036]
    float* qs   = sm + ES_FLOATS;           // [64][36] (also Phase-B reduce buf)
    float* ks   = qs + QS_FLOATS;           // k tiles [64][132] / v tiles [128][68]
    float* invs = ks + KV_FLOATS;           // 32
    int*   wcnt = (int*)(invs + 32);        // 8

    const int tid  = threadIdx.x;
    const int warp = tid >> 5, lane = tid & 31;
    const int blk  = blockIdx.x;            // 1024
    const int bh   = blk >> 5;
    const int i0   = (blk & 31) * 32;
    const int b    = bh >> 3;

    const float* qbase  = g_q + (size_t)bh * NN * DHD;
    const float* ktbase = g_k + (size_t)bh * DHD * NN;   // [d][n]
    const float* vbase  = g_v + (size_t)bh * NN * DHD;

    // load 32 q-rows transposed into qs[d][i]
    #pragma unroll
    for (int it = 0; it < 2; it++) {
        int idx = tid + it * 256;
        int r = idx >> 4, q4 = idx & 15;
        float4 a = *(const float4*)(qbase + (size_t)(i0 + r) * DHD + q4 * 4);
        qs[(q4*4+0)*QS_STRIDE + r] = a.x;
        qs[(q4*4+1)*QS_STRIDE + r] = a.y;
        qs[(q4*4+2)*QS_STRIDE + r] = a.z;
        qs[(q4*4+3)*QS_STRIDE + r] = a.w;
    }

    float qn10[4];
    #pragma unroll
    for (int r = 0; r < 4; r++)
        qn10[r] = g_qni[bh * NN + i0 + warp * 4 + r] * 10.0f;

    float rsum[4] = {}, rpos[4] = {}, rall[4] = {};
    int cnt = 0;

    // ---- Phase A: 8 k-tiles of 128, register double-buffered ----
    float4 pf[8];
    #pragma unroll
    for (int it = 0; it < 8; it++) {
        int idx = tid + it * 256;
        int d = idx >> 5, j4 = idx & 31;
        pf[it] = *(const float4*)(ktbase + (size_t)d * NN + j4 * 4);
    }

    for (int jt = 0; jt < 8; jt++) {
        __syncthreads();
        #pragma unroll
        for (int it = 0; it < 8; it++) {
            int idx = tid + it * 256;
            int d = idx >> 5, j4 = idx & 31;
            *(float4*)&ks[d * KS_STRIDE + j4 * 4] = pf[it];
        }
        __syncthreads();
        if (jt < 7) {
            #pragma unroll
            for (int it = 0; it < 8; it++) {
                int idx = tid + it * 256;
                int d = idx >> 5, j4 = idx & 31;
                pf[it] = *(const float4*)(ktbase + (size_t)d * NN +
                                          (jt + 1) * 128 + j4 * 4);
            }
        }

        float acc[4][4] = {};
        #pragma unroll 16
        for (int d = 0; d < 64; d++) {
            float4 qv = *(const float4*)&qs[d*QS_STRIDE + warp*4];  // broadcast
            float4 kv = *(const float4*)&ks[d*KS_STRIDE + lane*4];
            float qr[4] = {qv.x, qv.y, qv.z, qv.w};
            float kr[4] = {kv.x, kv.y, kv.z, kv.w};
            #pragma unroll
            for (int r = 0; r < 4; r++)
                #pragma unroll
                for (int c = 0; c < 4; c++)
                    acc[r][c] += qr[r] * kr[c];
        }

        const int j0 = jt * 128 + lane * 4;
        float4 kn4 = *(const float4*)&g_kni[bh * NN + j0];
        float knr[4] = {kn4.x, kn4.y, kn4.z, kn4.w};
        #pragma unroll
        for (int r = 0; r < 4; r++) {
            int i = i0 + warp * 4 + r;
            int4 mm = *(const int4*)(mask + ((size_t)b * NN + i) * NN + j0);
            int mr[4] = {mm.x, mm.y, mm.z, mm.w};
            float4 esv;
            float* esp = (float*)&esv;
            #pragma unroll
            for (int c = 0; c < 4; c++) {
                float dot = acc[r][c];
                float e_c = __expf(dot * qn10[r] * knr[c]);
                rall[r] += e_c;
                if (mr[c]) rpos[r] += e_c;
                cnt += mr[c];
                float e_s = mr[c] ? __expf(dot * SCALE) : 0.f;
                rsum[r] += e_s;
                esp[c] = e_s;
            }
            *(float4*)&es[(warp*4+r)*ES_STRIDE + j0] = esv;
        }
    }

    // reduce row quantities over lanes (disjoint j)
    #pragma unroll
    for (int r = 0; r < 4; r++) {
        #pragma unroll
        for (int o = 16; o > 0; o >>= 1) {
            rsum[r] += __shfl_xor_sync(0xffffffffu, rsum[r], o);
            rall[r] += __shfl_xor_sync(0xffffffffu, rall[r], o);
            rpos[r] += __shfl_xor_sync(0xffffffffu, rpos[r], o);
        }
    }
    #pragma unroll
    for (int o = 16; o > 0; o >>= 1)
        cnt += __shfl_xor_sync(0xffffffffu, cnt, o);
    if (lane == 0) {
        #pragma unroll
        for (int r = 0; r < 4; r++) {
            int li = warp * 4 + r;
            invs[li] = __frcp_rn(rsum[r]);
            g_clus[bh * NN + i0 + li] = -__logf(__fdividef(rpos[r], rall[r]));
        }
        wcnt[warp] = cnt;
    }
    __syncthreads();
    if (tid == 0) {
        int s = 0;
        #pragma unroll
        for (int w = 0; w < 8; w++) s += wcnt[w];
        atomicAdd(&g_msum, s);
    }

    // write attn normalized (coalesced)
    #pragma unroll 4
    for (int it = 0; it < 32; it++) {
        int idx = tid + it * 256;
        int i = idx >> 8, q4 = idx & 255;
        float4 v = *(const float4*)&es[i*ES_STRIDE + q4*4];
        float s = invs[i];
        v.x *= s; v.y *= s; v.z *= s; v.w *= s;
        *(float4*)(attn_out + ((size_t)bh * NN + i0 + i) * NN + q4 * 4) = v;
    }

    // ---- Phase B: ctx = es @ V, v tiles register double-buffered ----
    const int sub = warp & 1;
    const int ipair = (warp >> 1) * 4 + ((lane >> 3) & 3);
    const int d4 = lane & 7;
    float av0[8] = {}, av1[8] = {};

    #pragma unroll
    for (int it = 0; it < 8; it++) {
        int idx = tid + it * 256;
        int r = idx >> 4, q4 = idx & 15;
        pf[it] = *(const float4*)(vbase + (size_t)r * DHD + q4 * 4);
    }

    for (int jt = 0; jt < 8; jt++) {
        __syncthreads();
        #pragma unroll
        for (int it = 0; it < 8; it++) {
            int idx = tid + it * 256;
            int r = idx >> 4, q4 = idx & 15;
            *(float4*)&ks[r * VS_STRIDE + q4 * 4] = pf[it];
        }
        __syncthreads();
        if (jt < 7) {
            #pragma unroll
            for (int it = 0; it < 8; it++) {
                int idx = tid + it * 256;
                int r = idx >> 4, q4 = idx & 15;
                pf[it] = *(const float4*)(vbase + (size_t)((jt+1)*128 + r) * DHD + q4 * 4);
            }
        }
        const float* e0p = &es[(ipair*2+0)*ES_STRIDE + jt*128 + sub*64];
        const float* e1p = e0p + ES_STRIDE;
        const float* vp  = &ks[(sub*64) * VS_STRIDE];
        #pragma unroll 8
        for (int j = 0; j < 64; j++) {
            float e0 = e0p[j], e1 = e1p[j];
            float4 v0 = *(const float4*)(vp + j*VS_STRIDE + d4*4);
            float4 v1 = *(const float4*)(vp + j*VS_STRIDE + 32 + d4*4);
            float vv[8] = {v0.x,v0.y,v0.z,v0.w,v1.x,v1.y,v1.z,v1.w};
            #pragma unroll
            for (int k2 = 0; k2 < 8; k2++) {
                av0[k2] += e0 * vv[k2];
                av1[k2] += e1 * vv[k2];
            }
        }
    }

    // reduce sub pairs through smem (qs region) and write ctx
    float* red = qs;
    __syncthreads();
    if (sub == 1) {
        int rid = (ipair * 8 + d4) * 16;
        *(float4*)&red[rid + 0]  = make_float4(av0[0], av0[1], av0[2], av0[3]);
        *(float4*)&red[rid + 4]  = make_float4(av0[4], av0[5], av0[6], av0[7]);
        *(float4*)&red[rid + 8]  = make_float4(av1[0], av1[1], av1[2], av1[3]);
        *(float4*)&red[rid + 12] = make_float4(av1[4], av1[5], av1[6], av1[7]);
    }
    __syncthreads();
    if (sub == 0) {
        int rid = (ipair * 8 + d4) * 16;
        const int h = bh & 7;
        #pragma unroll
        for (int r = 0; r < 2; r++) {
            float* avp = r ? av1 : av0;
            float4 p0 = *(const float4*)&red[rid + r*8];
            float4 p1 = *(const float4*)&red[rid + r*8 + 4];
            int i = ipair * 2 + r;
            float s = invs[i];
            float4 o0 = make_float4((avp[0]+p0.x)*s, (avp[1]+p0.y)*s,
                                    (avp[2]+p0.z)*s, (avp[3]+p0.w)*s);
            float4 o1 = make_float4((avp[4]+p1.x)*s, (avp[5]+p1.y)*s,
                                    (avp[6]+p1.z)*s, (avp[7]+p1.w)*s);
            size_t base = ((size_t)b * NN + i0 + i) * INNERD + h * DHD;
            *(float4*)&g_ctx[base + d4*4]      = o0;
            *(float4*)&g_ctx[base + 32 + d4*4] = o1;
        }
    }
}

// ---------------- final dcl scalar ----------------
__global__ void dcl_kernel(float* out_dcl) {
    __shared__ float red[1024];
    const int tid = threadIdx.x;
    float s = 0.f;
    const int base = tid * 32;
    #pragma unroll 8
    for (int i = 0; i < 32; i++) s += g_clus[base + i];
    red[tid] = s;
    __syncthreads();
    for (int o = 512; o > 0; o >>= 1) {
        if (tid < o) red[tid] += red[tid + o];
        __syncthreads();
    }
    if (tid == 0 && out_dcl) {
        float clus_mean = red[0] / (float)NROWS;
        float regular = ((float)(g_msum >> 3) - (float)(BB * NN)) /
                        ((float)BB * (float)NN * (float)(NN - 1));
        out_dcl[0] = clus_mean + 0.3f * regular;
    }
}

// ---------------- launcher ----------------
extern "C" void kernel_launch(void* const* d_in, const int* in_sizes, int n_in,
                              void* d_out, int out_size) {
    const float* x   = (const float*)d_in[0];
    const int*   msk = (const int*)  d_in[1];
    const float* Wq  = (const float*)d_in[2];
    const float* bq  = (const float*)d_in[3];
    const float* Wk  = (const float*)d_in[4];
    const float* bk  = (const float*)d_in[5];
    const float* Wv  = (const float*)d_in[6];
    const float* bv  = (const float*)d_in[7];
    const float* Wo  = (const float*)d_in[8];
    const float* bo  = (const float*)d_in[9];
    float* out = (float*)d_out;

    const size_t OUTE  = (size_t)BB * NN * DIMD;   // 2097152
    const size_t ATTNE = (size_t)BH * NN * NN;     // 33554432

    float* attn_ptr;
    if ((size_t)out_size >= OUTE + ATTNE) {
        attn_ptr = out + OUTE;
    } else {
        void* p = nullptr;
        cudaGetSymbolAddress(&p, g_attn_fb);
        attn_ptr = (float*)p;
    }
    float* dcl_ptr = ((size_t)out_size >= OUTE + ATTNE + 1) ? (out + OUTE + ATTNE)
                                                            : nullptr;

    cudaFuncSetAttribute(attn2_kernel,
                         cudaFuncAttributeMaxDynamicSharedMemorySize, ATTN_SMEM);

    init_kernel<<<1, 32>>>();

    dim3 qkvgrid(DIMD / 128, (BB * NN) / 128, 3);   // (4, 32, 3)
    qkv_kernel<<<qkvgrid, 256>>>(x, Wq, bq, Wk, bk, Wv, bv);

    attn2_kernel<<<BH * (NN / 32), 256, ATTN_SMEM>>>(msk, attn_ptr);

    dim3 ogrid(DIMD / 128, (BB * NN) / 128);        // (4, 32)
    outproj_kernel<<<ogrid, 256>>>(Wo, bo, out);

    dcl_kernel<<<1, 1024>>>(dcl_ptr);
}

// round 7
// speedup vs baseline: 5.2398x; 1.3496x over previous
#include <cuda_runtime.h>
#include <cuda_bf16.h>
#include <math.h>
#include <stdint.h>

#define BB 4
#define NN 1024
#define DIMD 512
#define HH 8
#define DHD 64
#define INNERD 512
#define BH (BB*HH)            // 32
#define NROWS (BH*NN)         // 32768
#define SCALE 0.125f

// ---------------- scratch (device globals; no runtime allocation) ----------
__device__ float g_q[NROWS*DHD];            // [bh][n][d]
__device__ float g_k[NROWS*DHD];            // TRANSPOSED: [bh][d][n]
__device__ float g_v[NROWS*DHD];            // [bh][n][d]
__device__ float g_qni[NROWS];              // reciprocal q norms
__device__ float g_kni[NROWS];              // reciprocal k norms
__device__ float g_clus[NROWS];
__device__ int   g_msum;                    // 8 * sum(mask)
__device__ float g_attn_fb[(size_t)BH*NN*NN];
// bf16 split operands
__device__ __nv_bfloat16 g_x_hi[(size_t)BB*NN*DIMD];
__device__ __nv_bfloat16 g_x_lo[(size_t)BB*NN*DIMD];
__device__ __nv_bfloat16 g_wt_hi[4*512*512];   // W^T [n][k], slots q,k,v,o
__device__ __nv_bfloat16 g_wt_lo[4*512*512];
__device__ __nv_bfloat16 g_ctx_hi[(size_t)BB*NN*INNERD];
__device__ __nv_bfloat16 g_ctx_lo[(size_t)BB*NN*INNERD];

// ---------------- helpers ----------------
__device__ __forceinline__ uint32_t smem_to_u32(const void* p) {
    uint32_t a;
    asm("{ .reg .u64 t; cvta.to.shared.u64 t, %1; cvt.u32.u64 %0, t; }"
        : "=r"(a) : "l"(p));
    return a;
}
#define SMEM_SWZ(off) ((off) ^ (((off) >> 3) & 0x70))

#define LDSM4(R0, R1, R2, R3, ADDR) \
    asm volatile("ldmatrix.sync.aligned.m8n8.x4.shared.b16 {%0,%1,%2,%3}, [%4];" \
        : "=r"(R0), "=r"(R1), "=r"(R2), "=r"(R3) : "r"(ADDR))

#define MMA16816(C, A, B0, B1) \
    asm volatile("mma.sync.aligned.m16n8k16.row.col.f32.bf16.bf16.f32 " \
        "{%0,%1,%2,%3}, {%4,%5,%6,%7}, {%8,%9}, {%0,%1,%2,%3};" \
        : "+f"((C)[0]), "+f"((C)[1]), "+f"((C)[2]), "+f"((C)[3]) \
        : "r"((A)[0]), "r"((A)[1]), "r"((A)[2]), "r"((A)[3]), "r"(B0), "r"(B1))

__device__ __forceinline__ void split_store4(__nv_bfloat16* hp, __nv_bfloat16* lp,
                                             float v0, float v1, float v2, float v3)
{
    __nv_bfloat16 h0 = __float2bfloat16(v0), h1 = __float2bfloat16(v1);
    __nv_bfloat16 h2 = __float2bfloat16(v2), h3 = __float2bfloat16(v3);
    *(__nv_bfloat162*)(hp)     = __halves2bfloat162(h0, h1);
    *(__nv_bfloat162*)(hp + 2) = __halves2bfloat162(h2, h3);
    *(__nv_bfloat162*)(lp)     = __halves2bfloat162(
        __float2bfloat16(v0 - __bfloat162float(h0)),
        __float2bfloat16(v1 - __bfloat162float(h1)));
    *(__nv_bfloat162*)(lp + 2) = __halves2bfloat162(
        __float2bfloat16(v2 - __bfloat162float(h2)),
        __float2bfloat16(v3 - __bfloat162float(h3)));
}

// ---------------- init ----------------
__global__ void init_kernel() {
    if (threadIdx.x == 0 && blockIdx.x == 0) g_msum = 0;
}

// ---------------- convert x -> hi/lo bf16 ----------------
__global__ void convx_kernel(const float* __restrict__ x) {
    int i = blockIdx.x * blockDim.x + threadIdx.x;   // 524288
    float4 v = ((const float4*)x)[i];
    split_store4(g_x_hi + (size_t)i * 4, g_x_lo + (size_t)i * 4,
                 v.x, v.y, v.z, v.w);
}

// ---------------- transpose+convert W -> W^T hi/lo bf16 ----------------
__global__ void convw_kernel(const float* __restrict__ Wq,
                             const float* __restrict__ Wk,
                             const float* __restrict__ Wv,
                             const float* __restrict__ Wo)
{
    __shared__ float tile[32][33];
    const int z = blockIdx.z;
    const float* W = (z == 0) ? Wq : (z == 1) ? Wk : (z == 2) ? Wv : Wo;
    const int tx = threadIdx.x, ty = threadIdx.y;      // (32, 8)
    const int bk = blockIdx.y * 32, bn = blockIdx.x * 32;
    #pragma unroll
    for (int r = 0; r < 4; r++)
        tile[ty + 8*r][tx] = W[(size_t)(bk + ty + 8*r) * 512 + bn + tx];
    __syncthreads();
    #pragma unroll
    for (int r = 0; r < 4; r++) {
        int n = bn + ty + 8*r, k = bk + tx;
        float v = tile[tx][ty + 8*r];
        __nv_bfloat16 h = __float2bfloat16(v);
        size_t o = (size_t)z * 262144 + (size_t)n * 512 + k;
        g_wt_hi[o] = h;
        g_wt_lo[o] = __float2bfloat16(v - __bfloat162float(h));
    }
}

// ================= HMMA projection GEMM =================
// C[128x128 tile] = A @ W + bias, 3-term bf16 split on legacy tensor cores.
// z = 0: q (+inv norms), 1: k transposed (+inv norms), 2: v, 3: out (A=ctx).
#define SA_HI 0
#define SA_LO 16384
#define SB_HI 32768
#define SB_LO 49152
#define BMMA_SMEM 65536

__global__ __launch_bounds__(256)
void bmma_kernel(const float* __restrict__ b0, const float* __restrict__ b1,
                 const float* __restrict__ b2, float* __restrict__ out, int mode)
{
    extern __shared__ char smc[];
    const uint32_t smb = smem_to_u32(smc);
    const int tid = threadIdx.x;
    const int wid = tid >> 5, lane = tid & 31;
    const int z = (mode < 0) ? (int)blockIdx.z : mode;
    const int bm = blockIdx.y * 128, bn = blockIdx.x * 128;
    const int wm = wid & 3, wn = wid >> 2;

    const __nv_bfloat16* Ah = (z == 3) ? g_ctx_hi : g_x_hi;
    const __nv_bfloat16* Al = (z == 3) ? g_ctx_lo : g_x_lo;
    const __nv_bfloat16* Bh = g_wt_hi + (size_t)z * 262144;
    const __nv_bfloat16* Bl = g_wt_lo + (size_t)z * 262144;
    const float* bias = (z == 0) ? b0 : (z == 1) ? b1 : (z == 2) ? b2 : b0;

    float acc[2][8][4] = {};

    const int ldr = tid >> 3, ldu = tid & 7;           // row 0..31-block, unit
    for (int kc = 0; kc < 8; kc++) {
        __syncthreads();
        // each thread: 4 x 16B per buffer (128 rows x 8 units / 256 thr)
        #pragma unroll
        for (int it = 0; it < 4; it++) {
            int r = ldr + it * 32;
            size_t ga = (size_t)(bm + r) * 512 + kc * 64 + ldu * 8;
            size_t gb = (size_t)(bn + r) * 512 + kc * 64 + ldu * 8;
            uint32_t so = SMEM_SWZ((uint32_t)(r * 128 + ldu * 16));
            *(uint4*)(smc + SA_HI + so) = *(const uint4*)(Ah + ga);
            *(uint4*)(smc + SA_LO + so) = *(const uint4*)(Al + ga);
            *(uint4*)(smc + SB_HI + so) = *(const uint4*)(Bh + gb);
            *(uint4*)(smc + SB_LO + so) = *(const uint4*)(Bl + gb);
        }
        __syncthreads();

        #pragma unroll
        for (int ks = 0; ks < 4; ks++) {
            uint32_t ah[2][4], al[2][4], bhf[8][2], blf[8][2];
            const int arow = wm * 32 + (lane & 15);
            const int akb  = ks * 32 + (lane >> 4) * 16;
            #pragma unroll
            for (int m = 0; m < 2; m++) {
                uint32_t off = SMEM_SWZ((uint32_t)((arow + m * 16) * 128 + akb));
                LDSM4(ah[m][0], ah[m][1], ah[m][2], ah[m][3], smb + SA_HI + off);
                LDSM4(al[m][0], al[m][1], al[m][2], al[m][3], smb + SA_LO + off);
            }
            const int lr = lane & 7, sel = lane >> 3;
            const int nrow = wn * 64 + ((sel >> 1) & 1) * 8 + lr;
            const int bkb  = ks * 32 + (sel & 1) * 16;
            #pragma unroll
            for (int p = 0; p < 4; p++) {
                uint32_t off = SMEM_SWZ((uint32_t)((nrow + p * 16) * 128 + bkb));
                LDSM4(bhf[2*p][0], bhf[2*p][1], bhf[2*p+1][0], bhf[2*p+1][1],
                      smb + SB_HI + off);
                LDSM4(blf[2*p][0], blf[2*p][1], blf[2*p+1][0], blf[2*p+1][1],
                      smb + SB_LO + off);
            }
            #pragma unroll
            for (int m = 0; m < 2; m++)
                #pragma unroll
                for (int nb = 0; nb < 8; nb++) {
                    MMA16816(acc[m][nb], ah[m], bhf[nb][0], bhf[nb][1]);
                    MMA16816(acc[m][nb], ah[m], blf[nb][0], blf[nb][1]);
                    MMA16816(acc[m][nb], al[m], bhf[nb][0], bhf[nb][1]);
                }
        }
    }

    // ---------------- epilogue ----------------
    const int g = lane >> 2, t = lane & 3;
    const int cb = bn + wn * 64;
    const int h = cb >> 6;
    float2 bv[8];
    #pragma unroll
    for (int nb = 0; nb < 8; nb++)
        bv[nb] = *(const float2*)&bias[cb + nb * 8 + 2 * t];

    #pragma unroll
    for (int m = 0; m < 2; m++) {
        #pragma unroll
        for (int half = 0; half < 2; half++) {
            const int rglob = bm + wm * 32 + m * 16 + g + half * 8;
            const int bi = rglob >> 10, n = rglob & 1023;
            float ss = 0.f;
            #pragma unroll
            for (int nb = 0; nb < 8; nb++) {
                float v0 = acc[m][nb][half * 2 + 0] + bv[nb].x;
                float v1 = acc[m][nb][half * 2 + 1] + bv[nb].y;
                ss += v0 * v0 + v1 * v1;
                const int d = nb * 8 + 2 * t;
                if (z == 3) {
                    *(float2*)(out + (size_t)rglob * 512 + cb + d) =
                        make_float2(v0, v1);
                } else if (z == 1) {
                    size_t kb = ((size_t)(bi * HH + h) * DHD + d) * NN + n;
                    g_k[kb] = v0;
                    g_k[kb + NN] = v1;
                } else {
                    float* dst = (z == 0) ? g_q : g_v;
                    *(float2*)(dst + ((size_t)(bi * HH + h) * NN + n) * DHD + d) =
                        make_float2(v0, v1);
                }
            }
            if (z < 2) {
                ss += __shfl_xor_sync(0xffffffffu, ss, 1);
                ss += __shfl_xor_sync(0xffffffffu, ss, 2);
                if (t == 0) {
                    float* dst = (z == 0) ? g_qni : g_kni;
                    dst[(bi * HH + h) * NN + n] = rsqrtf(ss);
                }
            }
        }
    }
}

// ============ fused scores + softmax + contrastive + attn@V ============
#define ES_STRIDE 1036
#define QS_STRIDE 36
#define KS_STRIDE 132
#define VS_STRIDE 68
#define ES_FLOATS (32*ES_STRIDE)
#define QS_FLOATS (64*QS_STRIDE)
#define KV_FLOATS (128*VS_STRIDE)
#define ATTN_SMEM ((ES_FLOATS + QS_FLOATS + KV_FLOATS + 48) * 4)

__global__ __launch_bounds__(256, 1)
void attn2_kernel(const int* __restrict__ mask, float* __restrict__ attn_out)
{
    extern __shared__ float sm[];
    float* es   = sm;
    float* qs   = sm + ES_FLOATS;
    float* ks   = qs + QS_FLOATS;
    float* invs = ks + KV_FLOATS;
    int*   wcnt = (int*)(invs + 32);

    const int tid  = threadIdx.x;
    const int warp = tid >> 5, lane = tid & 31;
    const int blk  = blockIdx.x;
    const int bh   = blk >> 5;
    const int i0   = (blk & 31) * 32;
    const int b    = bh >> 3;

    const float* qbase  = g_q + (size_t)bh * NN * DHD;
    const float* ktbase = g_k + (size_t)bh * DHD * NN;
    const float* vbase  = g_v + (size_t)bh * NN * DHD;

    #pragma unroll
    for (int it = 0; it < 2; it++) {
        int idx = tid + it * 256;
        int r = idx >> 4, q4 = idx & 15;
        float4 a = *(const float4*)(qbase + (size_t)(i0 + r) * DHD + q4 * 4);
        qs[(q4*4+0)*QS_STRIDE + r] = a.x;
        qs[(q4*4+1)*QS_STRIDE + r] = a.y;
        qs[(q4*4+2)*QS_STRIDE + r] = a.z;
        qs[(q4*4+3)*QS_STRIDE + r] = a.w;
    }

    float qn10[4];
    #pragma unroll
    for (int r = 0; r < 4; r++)
        qn10[r] = g_qni[bh * NN + i0 + warp * 4 + r] * 10.0f;

    float rsum[4] = {}, rpos[4] = {}, rall[4] = {};
    int cnt = 0;

    float4 pf[8];
    #pragma unroll
    for (int it = 0; it < 8; it++) {
        int idx = tid + it * 256;
        int d = idx >> 5, j4 = idx & 31;
        pf[it] = *(const float4*)(ktbase + (size_t)d * NN + j4 * 4);
    }

    for (int jt = 0; jt < 8; jt++) {
        __syncthreads();
        #pragma unroll
        for (int it = 0; it < 8; it++) {
            int idx = tid + it * 256;
            int d = idx >> 5, j4 = idx & 31;
            *(float4*)&ks[d * KS_STRIDE + j4 * 4] = pf[it];
        }
        __syncthreads();
        if (jt < 7) {
            #pragma unroll
            for (int it = 0; it < 8; it++) {
                int idx = tid + it * 256;
                int d = idx >> 5, j4 = idx & 31;
                pf[it] = *(const float4*)(ktbase + (size_t)d * NN +
                                          (jt + 1) * 128 + j4 * 4);
            }
        }

        float acc[4][4] = {};
        #pragma unroll 16
        for (int d = 0; d < 64; d++) {
            float4 qv = *(const float4*)&qs[d*QS_STRIDE + warp*4];
            float4 kv = *(const float4*)&ks[d*KS_STRIDE + lane*4];
            float qr[4] = {qv.x, qv.y, qv.z, qv.w};
            float kr[4] = {kv.x, kv.y, kv.z, kv.w};
            #pragma unroll
            for (int r = 0; r < 4; r++)
                #pragma unroll
                for (int c = 0; c < 4; c++)
                    acc[r][c] += qr[r] * kr[c];
        }

        const int j0 = jt * 128 + lane * 4;
        float4 kn4 = *(const float4*)&g_kni[bh * NN + j0];
        float knr[4] = {kn4.x, kn4.y, kn4.z, kn4.w};
        #pragma unroll
        for (int r = 0; r < 4; r++) {
            int i = i0 + warp * 4 + r;
            int4 mm = *(const int4*)(mask + ((size_t)b * NN + i) * NN + j0);
            int mr[4] = {mm.x, mm.y, mm.z, mm.w};
            float4 esv;
            float* esp = (float*)&esv;
            #pragma unroll
            for (int c = 0; c < 4; c++) {
                float dot = acc[r][c];
                float e_c = __expf(dot * qn10[r] * knr[c]);
                rall[r] += e_c;
                if (mr[c]) rpos[r] += e_c;
                cnt += mr[c];
                float e_s = mr[c] ? __expf(dot * SCALE) : 0.f;
                rsum[r] += e_s;
                esp[c] = e_s;
            }
            *(float4*)&es[(warp*4+r)*ES_STRIDE + j0] = esv;
        }
    }

    #pragma unroll
    for (int r = 0; r < 4; r++) {
        #pragma unroll
        for (int o = 16; o > 0; o >>= 1) {
            rsum[r] += __shfl_xor_sync(0xffffffffu, rsum[r], o);
            rall[r] += __shfl_xor_sync(0xffffffffu, rall[r], o);
            rpos[r] += __shfl_xor_sync(0xffffffffu, rpos[r], o);
        }
    }
    #pragma unroll
    for (int o = 16; o > 0; o >>= 1)
        cnt += __shfl_xor_sync(0xffffffffu, cnt, o);
    if (lane == 0) {
        #pragma unroll
        for (int r = 0; r < 4; r++) {
            int li = warp * 4 + r;
            invs[li] = __frcp_rn(rsum[r]);
            g_clus[bh * NN + i0 + li] = -__logf(__fdividef(rpos[r], rall[r]));
        }
        wcnt[warp] = cnt;
    }
    __syncthreads();
    if (tid == 0) {
        int s = 0;
        #pragma unroll
        for (int w = 0; w < 8; w++) s += wcnt[w];
        atomicAdd(&g_msum, s);
    }

    #pragma unroll 4
    for (int it = 0; it < 32; it++) {
        int idx = tid + it * 256;
        int i = idx >> 8, q4 = idx & 255;
        float4 v = *(const float4*)&es[i*ES_STRIDE + q4*4];
        float s = invs[i];
        v.x *= s; v.y *= s; v.z *= s; v.w *= s;
        *(float4*)(attn_out + ((size_t)bh * NN + i0 + i) * NN + q4 * 4) = v;
    }

    // Phase B: ctx = es @ V
    const int sub = warp & 1;
    const int ipair = (warp >> 1) * 4 + ((lane >> 3) & 3);
    const int d4 = lane & 7;
    float av0[8] = {}, av1[8] = {};

    #pragma unroll
    for (int it = 0; it < 8; it++) {
        int idx = tid + it * 256;
        int r = idx >> 4, q4 = idx & 15;
        pf[it] = *(const float4*)(vbase + (size_t)r * DHD + q4 * 4);
    }

    for (int jt = 0; jt < 8; jt++) {
        __syncthreads();
        #pragma unroll
        for (int it = 0; it < 8; it++) {
            int idx = tid + it * 256;
            int r = idx >> 4, q4 = idx & 15;
            *(float4*)&ks[r * VS_STRIDE + q4 * 4] = pf[it];
        }
        __syncthreads();
        if (jt < 7) {
            #pragma unroll
            for (int it = 0; it < 8; it++) {
                int idx = tid + it * 256;
                int r = idx >> 4, q4 = idx & 15;
                pf[it] = *(const float4*)(vbase + (size_t)((jt+1)*128 + r) * DHD + q4 * 4);
            }
        }
        const float* e0p = &es[(ipair*2+0)*ES_STRIDE + jt*128 + sub*64];
        const float* e1p = e0p + ES_STRIDE;
        const float* vp  = &ks[(sub*64) * VS_STRIDE];
        #pragma unroll 8
        for (int j = 0; j < 64; j++) {
            float e0 = e0p[j], e1 = e1p[j];
            float4 v0 = *(const float4*)(vp + j*VS_STRIDE + d4*4);
            float4 v1 = *(const float4*)(vp + j*VS_STRIDE + 32 + d4*4);
            float vv[8] = {v0.x,v0.y,v0.z,v0.w,v1.x,v1.y,v1.z,v1.w};
            #pragma unroll
            for (int k2 = 0; k2 < 8; k2++) {
                av0[k2] += e0 * vv[k2];
                av1[k2] += e1 * vv[k2];
            }
        }
    }

    float* red = qs;
    __syncthreads();
    if (sub == 1) {
        int rid = (ipair * 8 + d4) * 16;
        *(float4*)&red[rid + 0]  = make_float4(av0[0], av0[1], av0[2], av0[3]);
        *(float4*)&red[rid + 4]  = make_float4(av0[4], av0[5], av0[6], av0[7]);
        *(float4*)&red[rid + 8]  = make_float4(av1[0], av1[1], av1[2], av1[3]);
        *(float4*)&red[rid + 12] = make_float4(av1[4], av1[5], av1[6], av1[7]);
    }
    __syncthreads();
    if (sub == 0) {
        int rid = (ipair * 8 + d4) * 16;
        const int h = bh & 7;
        #pragma unroll
        for (int r = 0; r < 2; r++) {
            float* avp = r ? av1 : av0;
            float4 p0 = *(const float4*)&red[rid + r*8];
            float4 p1 = *(const float4*)&red[rid + r*8 + 4];
            int i = ipair * 2 + r;
            float s = invs[i];
            size_t base = ((size_t)b * NN + i0 + i) * INNERD + h * DHD;
            split_store4(g_ctx_hi + base + d4*4, g_ctx_lo + base + d4*4,
                         (avp[0]+p0.x)*s, (avp[1]+p0.y)*s,
                         (avp[2]+p0.z)*s, (avp[3]+p0.w)*s);
            split_store4(g_ctx_hi + base + 32 + d4*4, g_ctx_lo + base + 32 + d4*4,
                         (avp[4]+p1.x)*s, (avp[5]+p1.y)*s,
                         (avp[6]+p1.z)*s, (avp[7]+p1.w)*s);
        }
    }
}

// ---------------- final dcl scalar ----------------
__global__ void dcl_kernel(float* out_dcl) {
    __shared__ float red[1024];
    const int tid = threadIdx.x;
    float s = 0.f;
    const int base = tid * 32;
    #pragma unroll 8
    for (int i = 0; i < 32; i++) s += g_clus[base + i];
    red[tid] = s;
    __syncthreads();
    for (int o = 512; o > 0; o >>= 1) {
        if (tid < o) red[tid] += red[tid + o];
        __syncthreads();
    }
    if (tid == 0 && out_dcl) {
        float clus_mean = red[0] / (float)NROWS;
        float regular = ((float)(g_msum >> 3) - (float)(BB * NN)) /
                        ((float)BB * (float)NN * (float)(NN - 1));
        out_dcl[0] = clus_mean + 0.3f * regular;
    }
}

// ---------------- launcher ----------------
extern "C" void kernel_launch(void* const* d_in, const int* in_sizes, int n_in,
                              void* d_out, int out_size) {
    const float* x   = (const float*)d_in[0];
    const int*   msk = (const int*)  d_in[1];
    const float* Wq  = (const float*)d_in[2];
    const float* bq  = (const float*)d_in[3];
    const float* Wk  = (const float*)d_in[4];
    const float* bk  = (const float*)d_in[5];
    const float* Wv  = (const float*)d_in[6];
    const float* bv  = (const float*)d_in[7];
    const float* Wo  = (const float*)d_in[8];
    const float* bo  = (const float*)d_in[9];
    float* out = (float*)d_out;

    const size_t OUTE  = (size_t)BB * NN * DIMD;
    const size_t ATTNE = (size_t)BH * NN * NN;

    float* attn_ptr;
    if ((size_t)out_size >= OUTE + ATTNE) {
        attn_ptr = out + OUTE;
    } else {
        void* p = nullptr;
        cudaGetSymbolAddress(&p, g_attn_fb);
        attn_ptr = (float*)p;
    }
    float* dcl_ptr = ((size_t)out_size >= OUTE + ATTNE + 1) ? (out + OUTE + ATTNE)
                                                            : nullptr;

    cudaFuncSetAttribute(attn2_kernel,
                         cudaFuncAttributeMaxDynamicSharedMemorySize, ATTN_SMEM);
    cudaFuncSetAttribute(bmma_kernel,
                         cudaFuncAttributeMaxDynamicSharedMemorySize, BMMA_SMEM);

    init_kernel<<<1, 32>>>();
    convx_kernel<<<2048, 256>>>(x);
    convw_kernel<<<dim3(16, 16, 4), dim3(32, 8)>>>(Wq, Wk, Wv, Wo);

    dim3 qkvgrid(4, 32, 3);
    bmma_kernel<<<qkvgrid, 256, BMMA_SMEM>>>(bq, bk, bv, nullptr, -1);

    attn2_kernel<<<BH * (NN / 32), 256, ATTN_SMEM>>>(msk, attn_ptr);

    dim3 ogrid(4, 32, 1);
    bmma_kernel<<<ogrid, 256, BMMA_SMEM>>>(bo, bo, bo, out, 3);

    dcl_kernel<<<1, 1024>>>(dcl_ptr);
}

// round 8
// speedup vs baseline: 6.9774x; 1.3316x over previous
#include <cuda_runtime.h>
#include <cuda_bf16.h>
#include <math.h>
#include <stdint.h>

#define BB 4
#define NN 1024
#define DIMD 512
#define HH 8
#define DHD 64
#define INNERD 512
#define BH (BB*HH)            // 32
#define NROWS (BH*NN)         // 32768
#define SCALE 0.125f

// ---------------- scratch (device globals; no runtime allocation) ----------
__device__ float g_qni[NROWS];              // reciprocal q norms
__device__ float g_kni[NROWS];              // reciprocal k norms
__device__ float g_clus[NROWS];
__device__ int   g_msum;                    // 8 * sum(mask)
__device__ float g_attn_fb[(size_t)BH*NN*NN];
// bf16 split operands
__device__ __nv_bfloat16 g_x_hi[(size_t)BB*NN*DIMD];
__device__ __nv_bfloat16 g_x_lo[(size_t)BB*NN*DIMD];
__device__ __nv_bfloat16 g_wt_hi[4*512*512];   // W^T [n][k], slots q,k,v,o
__device__ __nv_bfloat16 g_wt_lo[4*512*512];
__device__ __nv_bfloat16 g_ctx_hi[(size_t)BB*NN*INNERD];
__device__ __nv_bfloat16 g_ctx_lo[(size_t)BB*NN*INNERD];
__device__ __nv_bfloat16 g_q_hi[NROWS*DHD];    // [bh][n][d]
__device__ __nv_bfloat16 g_q_lo[NROWS*DHD];
__device__ __nv_bfloat16 g_k_hi[NROWS*DHD];    // [bh][n][d]
__device__ __nv_bfloat16 g_k_lo[NROWS*DHD];
__device__ __nv_bfloat16 g_vt_hi[NROWS*DHD];   // TRANSPOSED [bh][d][n]
__device__ __nv_bfloat16 g_vt_lo[NROWS*DHD];

// ---------------- helpers ----------------
__device__ __forceinline__ uint32_t smem_to_u32(const void* p) {
    uint32_t a;
    asm("{ .reg .u64 t; cvta.to.shared.u64 t, %1; cvt.u32.u64 %0, t; }"
        : "=r"(a) : "l"(p));
    return a;
}
#define SMEM_SWZ(off) ((off) ^ (((off) >> 3) & 0x70))

#define LDSM4(R0, R1, R2, R3, ADDR) \
    asm volatile("ldmatrix.sync.aligned.m8n8.x4.shared.b16 {%0,%1,%2,%3}, [%4];" \
        : "=r"(R0), "=r"(R1), "=r"(R2), "=r"(R3) : "r"(ADDR))

#define MMA16816(C, A, B0, B1) \
    asm volatile("mma.sync.aligned.m16n8k16.row.col.f32.bf16.bf16.f32 " \
        "{%0,%1,%2,%3}, {%4,%5,%6,%7}, {%8,%9}, {%0,%1,%2,%3};" \
        : "+f"((C)[0]), "+f"((C)[1]), "+f"((C)[2]), "+f"((C)[3]) \
        : "r"((A)[0]), "r"((A)[1]), "r"((A)[2]), "r"((A)[3]), "r"(B0), "r"(B1))

__device__ __forceinline__ void split_store4(__nv_bfloat16* hp, __nv_bfloat16* lp,
                                             float v0, float v1, float v2, float v3)
{
    __nv_bfloat16 h0 = __float2bfloat16(v0), h1 = __float2bfloat16(v1);
    __nv_bfloat16 h2 = __float2bfloat16(v2), h3 = __float2bfloat16(v3);
    *(__nv_bfloat162*)(hp)     = __halves2bfloat162(h0, h1);
    *(__nv_bfloat162*)(hp + 2) = __halves2bfloat162(h2, h3);
    *(__nv_bfloat162*)(lp)     = __halves2bfloat162(
        __float2bfloat16(v0 - __bfloat162float(h0)),
        __float2bfloat16(v1 - __bfloat162float(h1)));
    *(__nv_bfloat162*)(lp + 2) = __halves2bfloat162(
        __float2bfloat16(v2 - __bfloat162float(h2)),
        __float2bfloat16(v3 - __bfloat162float(h3)));
}

// ---------------- init ----------------
__global__ void init_kernel() {
    if (threadIdx.x == 0 && blockIdx.x == 0) g_msum = 0;
}

// ---------------- convert x -> hi/lo bf16 ----------------
__global__ void convx_kernel(const float* __restrict__ x) {
    int i = blockIdx.x * blockDim.x + threadIdx.x;   // 524288
    float4 v = ((const float4*)x)[i];
    split_store4(g_x_hi + (size_t)i * 4, g_x_lo + (size_t)i * 4,
                 v.x, v.y, v.z, v.w);
}

// ---------------- transpose+convert W -> W^T hi/lo bf16 ----------------
__global__ void convw_kernel(const float* __restrict__ Wq,
                             const float* __restrict__ Wk,
                             const float* __restrict__ Wv,
                             const float* __restrict__ Wo)
{
    __shared__ float tile[32][33];
    const int z = blockIdx.z;
    const float* W = (z == 0) ? Wq : (z == 1) ? Wk : (z == 2) ? Wv : Wo;
    const int tx = threadIdx.x, ty = threadIdx.y;      // (32, 8)
    const int bk = blockIdx.y * 32, bn = blockIdx.x * 32;
    #pragma unroll
    for (int r = 0; r < 4; r++)
        tile[ty + 8*r][tx] = W[(size_t)(bk + ty + 8*r) * 512 + bn + tx];
    __syncthreads();
    #pragma unroll
    for (int r = 0; r < 4; r++) {
        int n = bn + ty + 8*r, k = bk + tx;
        float v = tile[tx][ty + 8*r];
        __nv_bfloat16 h = __float2bfloat16(v);
        size_t o = (size_t)z * 262144 + (size_t)n * 512 + k;
        g_wt_hi[o] = h;
        g_wt_lo[o] = __float2bfloat16(v - __bfloat162float(h));
    }
}

// ================= HMMA projection GEMM =================
// z = 0: q bf16 hi/lo (+inv norms), 1: k bf16 hi/lo (+inv norms),
// 2: v transposed bf16 hi/lo, 3: out fp32 (A=ctx).
#define SA_HI 0
#define SA_LO 16384
#define SB_HI 32768
#define SB_LO 49152
#define BMMA_SMEM 65536

__global__ __launch_bounds__(256)
void bmma_kernel(const float* __restrict__ b0, const float* __restrict__ b1,
                 const float* __restrict__ b2, float* __restrict__ out, int mode)
{
    extern __shared__ char smc[];
    const uint32_t smb = smem_to_u32(smc);
    const int tid = threadIdx.x;
    const int wid = tid >> 5, lane = tid & 31;
    const int z = (mode < 0) ? (int)blockIdx.z : mode;
    const int bm = blockIdx.y * 128, bn = blockIdx.x * 128;
    const int wm = wid & 3, wn = wid >> 2;

    const __nv_bfloat16* Ah = (z == 3) ? g_ctx_hi : g_x_hi;
    const __nv_bfloat16* Al = (z == 3) ? g_ctx_lo : g_x_lo;
    const __nv_bfloat16* Bh = g_wt_hi + (size_t)z * 262144;
    const __nv_bfloat16* Bl = g_wt_lo + (size_t)z * 262144;
    const float* bias = (z == 0) ? b0 : (z == 1) ? b1 : (z == 2) ? b2 : b0;

    float acc[2][8][4] = {};

    const int ldr = tid >> 3, ldu = tid & 7;
    for (int kc = 0; kc < 8; kc++) {
        __syncthreads();
        #pragma unroll
        for (int it = 0; it < 4; it++) {
            int r = ldr + it * 32;
            size_t ga = (size_t)(bm + r) * 512 + kc * 64 + ldu * 8;
            size_t gb = (size_t)(bn + r) * 512 + kc * 64 + ldu * 8;
            uint32_t so = SMEM_SWZ((uint32_t)(r * 128 + ldu * 16));
            *(uint4*)(smc + SA_HI + so) = *(const uint4*)(Ah + ga);
            *(uint4*)(smc + SA_LO + so) = *(const uint4*)(Al + ga);
            *(uint4*)(smc + SB_HI + so) = *(const uint4*)(Bh + gb);
            *(uint4*)(smc + SB_LO + so) = *(const uint4*)(Bl + gb);
        }
        __syncthreads();

        #pragma unroll
        for (int ks = 0; ks < 4; ks++) {
            uint32_t ah[2][4], al[2][4], bhf[8][2], blf[8][2];
            const int arow = wm * 32 + (lane & 15);
            const int akb  = ks * 32 + (lane >> 4) * 16;
            #pragma unroll
            for (int m = 0; m < 2; m++) {
                uint32_t off = SMEM_SWZ((uint32_t)((arow + m * 16) * 128 + akb));
                LDSM4(ah[m][0], ah[m][1], ah[m][2], ah[m][3], smb + SA_HI + off);
                LDSM4(al[m][0], al[m][1], al[m][2], al[m][3], smb + SA_LO + off);
            }
            const int lr = lane & 7, sel = lane >> 3;
            const int nrow = wn * 64 + ((sel >> 1) & 1) * 8 + lr;
            const int bkb  = ks * 32 + (sel & 1) * 16;
            #pragma unroll
            for (int p = 0; p < 4; p++) {
                uint32_t off = SMEM_SWZ((uint32_t)((nrow + p * 16) * 128 + bkb));
                LDSM4(bhf[2*p][0], bhf[2*p][1], bhf[2*p+1][0], bhf[2*p+1][1],
                      smb + SB_HI + off);
                LDSM4(blf[2*p][0], blf[2*p][1], blf[2*p+1][0], blf[2*p+1][1],
                      smb + SB_LO + off);
            }
            #pragma unroll
            for (int m = 0; m < 2; m++)
                #pragma unroll
                for (int nb = 0; nb < 8; nb++) {
                    MMA16816(acc[m][nb], ah[m], bhf[nb][0], bhf[nb][1]);
                    MMA16816(acc[m][nb], ah[m], blf[nb][0], blf[nb][1]);
                    MMA16816(acc[m][nb], al[m], bhf[nb][0], bhf[nb][1]);
                }
        }
    }

    // ---------------- epilogue ----------------
    const int g = lane >> 2, t = lane & 3;
    const int cb = bn + wn * 64;
    const int h = cb >> 6;
    float2 bv[8];
    #pragma unroll
    for (int nb = 0; nb < 8; nb++)
        bv[nb] = *(const float2*)&bias[cb + nb * 8 + 2 * t];

    #pragma unroll
    for (int m = 0; m < 2; m++) {
        #pragma unroll
        for (int half = 0; half < 2; half++) {
            const int rglob = bm + wm * 32 + m * 16 + g + half * 8;
            const int bi = rglob >> 10, n = rglob & 1023;
            float ss = 0.f;
            #pragma unroll
            for (int nb = 0; nb < 8; nb++) {
                float v0 = acc[m][nb][half * 2 + 0] + bv[nb].x;
                float v1 = acc[m][nb][half * 2 + 1] + bv[nb].y;
                ss += v0 * v0 + v1 * v1;
                const int d = nb * 8 + 2 * t;
                if (z == 3) {
                    *(float2*)(out + (size_t)rglob * 512 + cb + d) =
                        make_float2(v0, v1);
                } else {
                    __nv_bfloat16 h0 = __float2bfloat16(v0);
                    __nv_bfloat16 h1 = __float2bfloat16(v1);
                    __nv_bfloat16 l0 = __float2bfloat16(v0 - __bfloat162float(h0));
                    __nv_bfloat16 l1 = __float2bfloat16(v1 - __bfloat162float(h1));
                    if (z == 2) {
                        size_t vb = ((size_t)(bi*HH + h)*DHD + d)*NN + n;
                        g_vt_hi[vb] = h0; g_vt_hi[vb + NN] = h1;
                        g_vt_lo[vb] = l0; g_vt_lo[vb + NN] = l1;
                    } else {
                        __nv_bfloat16* dh = (z == 0) ? g_q_hi : g_k_hi;
                        __nv_bfloat16* dl = (z == 0) ? g_q_lo : g_k_lo;
                        size_t qb = ((size_t)(bi*HH + h)*NN + n)*DHD + d;
                        *(__nv_bfloat162*)(dh + qb) = __halves2bfloat162(h0, h1);
                        *(__nv_bfloat162*)(dl + qb) = __halves2bfloat162(l0, l1);
                    }
                }
            }
            if (z < 2) {
                ss += __shfl_xor_sync(0xffffffffu, ss, 1);
                ss += __shfl_xor_sync(0xffffffffu, ss, 2);
                if (t == 0) {
                    float* dst = (z == 0) ? g_qni : g_kni;
                    dst[(bi * HH + h) * NN + n] = rsqrtf(ss);
                }
            }
        }
    }
}

// ============ fused attention: HMMA scores + softmax + contrastive + HMMA AV
// Block = (bh, 32 q-rows). Padded-stride smem, 3-term bf16 split GEMMs.
#define ES_B 2064
#define QT_B 144
#define KT_B 144
#define VT_B 272
#define OFF_ES_HI 0
#define OFF_ES_LO 66048
#define OFF_QT_HI 132096
#define OFF_QT_LO 136704
#define OFF_KT_HI 141312
#define OFF_KT_LO 159744
#define OFF_RED   178176
#define OFF_INVS  181248
#define OFF_WCNT  181376
#define ATTN_SMEM 181440

__global__ __launch_bounds__(256, 1)
void attn3_kernel(const int* __restrict__ mask, float* __restrict__ attn_out)
{
    extern __shared__ char smc[];
    const uint32_t smb = smem_to_u32(smc);
    float* invs = (float*)(smc + OFF_INVS);
    float* red  = (float*)(smc + OFF_RED);
    int*   wcnt = (int*)(smc + OFF_WCNT);

    const int tid  = threadIdx.x;
    const int warp = tid >> 5, lane = tid & 31;
    const int g = lane >> 2, t = lane & 3;
    const int lr = lane & 7, sel = lane >> 3;
    const int blk = blockIdx.x;             // 1024
    const int bh  = blk >> 5;
    const int i0  = (blk & 31) * 32;
    const int b   = bh >> 3;

    // ---- load q tile 32x64 hi/lo (each thread one 16B unit per buffer) ----
    {
        int r = tid >> 3, u = tid & 7;
        size_t gq = ((size_t)(bh * NN + i0 + r)) * DHD + u * 8;
        *(uint4*)(smc + OFF_QT_HI + r * QT_B + u * 16) = *(const uint4*)(g_q_hi + gq);
        *(uint4*)(smc + OFF_QT_LO + r * QT_B + u * 16) = *(const uint4*)(g_q_lo + gq);
    }
    __syncthreads();

    // ---- Q fragments (whole block's 32 rows, per warp) ----
    uint32_t qh[2][4][4], ql[2][4][4];
    #pragma unroll
    for (int m = 0; m < 2; m++)
        #pragma unroll
        for (int ks = 0; ks < 4; ks++) {
            uint32_t a = smb + OFF_QT_HI + (m * 16 + (lane & 15)) * QT_B
                       + ks * 32 + (lane >> 4) * 16;
            LDSM4(qh[m][ks][0], qh[m][ks][1], qh[m][ks][2], qh[m][ks][3], a);
            LDSM4(ql[m][ks][0], ql[m][ks][1], ql[m][ks][2], ql[m][ks][3],
                  a + (OFF_QT_LO - OFF_QT_HI));
        }

    float qn10[2][2];
    #pragma unroll
    for (int m = 0; m < 2; m++)
        #pragma unroll
        for (int hf = 0; hf < 2; hf++)
            qn10[m][hf] = g_qni[bh * NN + i0 + m * 16 + g + hf * 8] * 10.0f;

    float rall[2][2] = {}, rpos[2][2] = {}, rsum[2][2] = {};
    int cnt = 0;

    // ---- Phase A: scores, 8 k-tiles of 128 rows, register prefetch ----
    uint4 pkh[4], pkl[4];
    #pragma unroll
    for (int it = 0; it < 4; it++) {
        int idx = tid + it * 256;
        int r = idx >> 3, u = idx & 7;
        size_t gk = ((size_t)(bh * NN + r)) * DHD + u * 8;
        pkh[it] = *(const uint4*)(g_k_hi + gk);
        pkl[it] = *(const uint4*)(g_k_lo + gk);
    }

    for (int jt = 0; jt < 8; jt++) {
        __syncthreads();
        #pragma unroll
        for (int it = 0; it < 4; it++) {
            int idx = tid + it * 256;
            int r = idx >> 3, u = idx & 7;
            *(uint4*)(smc + OFF_KT_HI + r * KT_B + u * 16) = pkh[it];
            *(uint4*)(smc + OFF_KT_LO + r * KT_B + u * 16) = pkl[it];
        }
        __syncthreads();
        if (jt < 7) {
            #pragma unroll
            for (int it = 0; it < 4; it++) {
                int idx = tid + it * 256;
                int r = idx >> 3, u = idx & 7;
                size_t gk = ((size_t)(bh * NN + (jt + 1) * 128 + r)) * DHD + u * 8;
                pkh[it] = *(const uint4*)(g_k_hi + gk);
                pkl[it] = *(const uint4*)(g_k_lo + gk);
            }
        }

        float acc[2][2][4] = {};
        #pragma unroll
        for (int ks = 0; ks < 4; ks++) {
            uint32_t kh4[4], kl4[4];
            uint32_t ka = smb + OFF_KT_HI
                        + (warp * 16 + ((sel >> 1) & 1) * 8 + lr) * KT_B
                        + ks * 32 + (sel & 1) * 16;
            LDSM4(kh4[0], kh4[1], kh4[2], kh4[3], ka);
            LDSM4(kl4[0], kl4[1], kl4[2], kl4[3], ka + (OFF_KT_LO - OFF_KT_HI));
            #pragma unroll
            for (int m = 0; m < 2; m++)
                #pragma unroll
                for (int nb = 0; nb < 2; nb++) {
                    MMA16816(acc[m][nb], qh[m][ks], kh4[nb*2], kh4[nb*2+1]);
                    MMA16816(acc[m][nb], qh[m][ks], kl4[nb*2], kl4[nb*2+1]);
                    MMA16816(acc[m][nb], ql[m][ks], kh4[nb*2], kh4[nb*2+1]);
                }
        }

        // epilogue for this j-tile
        #pragma unroll
        for (int nb = 0; nb < 2; nb++) {
            const int j = jt * 128 + warp * 16 + nb * 8 + t * 2;
            float2 kn = *(const float2*)&g_kni[bh * NN + j];
            #pragma unroll
            for (int m = 0; m < 2; m++)
                #pragma unroll
                for (int hf = 0; hf < 2; hf++) {
                    const int il = m * 16 + g + hf * 8;
                    int2 mm = *(const int2*)(mask +
                              ((size_t)(b * NN + i0 + il)) * NN + j);
                    float d0 = acc[m][nb][hf * 2 + 0];
                    float d1 = acc[m][nb][hf * 2 + 1];
                    float qn = qn10[m][hf];
                    float ec0 = __expf(d0 * qn * kn.x);
                    float ec1 = __expf(d1 * qn * kn.y);
                    rall[m][hf] += ec0 + ec1;
                    rpos[m][hf] += (mm.x ? ec0 : 0.f) + (mm.y ? ec1 : 0.f);
                    cnt += (mm.x != 0) + (mm.y != 0);
                    float es0 = mm.x ? __expf(d0 * SCALE) : 0.f;
                    float es1 = mm.y ? __expf(d1 * SCALE) : 0.f;
                    rsum[m][hf] += es0 + es1;
                    __nv_bfloat16 h0 = __float2bfloat16(es0);
                    __nv_bfloat16 h1 = __float2bfloat16(es1);
                    *(__nv_bfloat162*)(smc + OFF_ES_HI + il * ES_B + j * 2) =
                        __halves2bfloat162(h0, h1);
                    *(__nv_bfloat162*)(smc + OFF_ES_LO + il * ES_B + j * 2) =
                        __halves2bfloat162(
                            __float2bfloat16(es0 - __bfloat162float(h0)),
                            __float2bfloat16(es1 - __bfloat162float(h1)));
                }
        }
    }

    // ---- row reductions ----
    #pragma unroll
    for (int m = 0; m < 2; m++)
        #pragma unroll
        for (int hf = 0; hf < 2; hf++) {
            #pragma unroll
            for (int o = 1; o <= 2; o <<= 1) {
                rall[m][hf] += __shfl_xor_sync(0xffffffffu, rall[m][hf], o);
                rpos[m][hf] += __shfl_xor_sync(0xffffffffu, rpos[m][hf], o);
                rsum[m][hf] += __shfl_xor_sync(0xffffffffu, rsum[m][hf], o);
            }
        }
    #pragma unroll
    for (int o = 16; o > 0; o >>= 1)
        cnt += __shfl_xor_sync(0xffffffffu, cnt, o);
    if (t == 0) {
        #pragma unroll
        for (int m = 0; m < 2; m++)
            #pragma unroll
            for (int hf = 0; hf < 2; hf++) {
                int il = m * 16 + g + hf * 8;
                red[(warp * 32 + il) * 3 + 0] = rall[m][hf];
                red[(warp * 32 + il) * 3 + 1] = rpos[m][hf];
                red[(warp * 32 + il) * 3 + 2] = rsum[m][hf];
            }
    }
    if (lane == 0) wcnt[warp] = cnt;
    __syncthreads();
    if (tid < 32) {
        float a = 0.f, p = 0.f, s = 0.f;
        #pragma unroll
        for (int w = 0; w < 8; w++) {
            a += red[(w * 32 + tid) * 3 + 0];
            p += red[(w * 32 + tid) * 3 + 1];
            s += red[(w * 32 + tid) * 3 + 2];
        }
        invs[tid] = __frcp_rn(s);
        g_clus[bh * NN + i0 + tid] = -__logf(__fdividef(p, a));
    }
    if (tid == 32) {
        int s = 0;
        #pragma unroll
        for (int w = 0; w < 8; w++) s += wcnt[w];
        atomicAdd(&g_msum, s);
    }
    __syncthreads();

    // ---- write normalized attn ----
    #pragma unroll 4
    for (int it = 0; it < 16; it++) {
        int idx = tid + it * 256;           // 4096 16B units
        int row = idx >> 7, u = idx & 127;
        uint4 vh = *(const uint4*)(smc + OFF_ES_HI + row * ES_B + u * 16);
        uint4 vl = *(const uint4*)(smc + OFF_ES_LO + row * ES_B + u * 16);
        float s = invs[row];
        float ov[8];
        const __nv_bfloat162* ph = (const __nv_bfloat162*)&vh;
        const __nv_bfloat162* pl = (const __nv_bfloat162*)&vl;
        #pragma unroll
        for (int p2 = 0; p2 < 4; p2++) {
            ov[2*p2+0] = (__bfloat162float(ph[p2].x) + __bfloat162float(pl[p2].x)) * s;
            ov[2*p2+1] = (__bfloat162float(ph[p2].y) + __bfloat162float(pl[p2].y)) * s;
        }
        float* dst = attn_out + ((size_t)bh * NN + i0 + row) * NN + u * 8;
        *(float4*)dst       = make_float4(ov[0], ov[1], ov[2], ov[3]);
        *(float4*)(dst + 4) = make_float4(ov[4], ov[5], ov[6], ov[7]);
    }

    // ---- Phase B: ctx = es @ V on HMMA ----
    const int wm = warp >> 2, wd = warp & 3;
    float acc2[2][4] = {};

    uint4 pvh[4], pvl[4];
    #pragma unroll
    for (int it = 0; it < 4; it++) {
        int idx = tid + it * 256;           // 1024 units: d row, u unit
        int d = idx >> 4, u = idx & 15;
        size_t gv = ((size_t)bh * DHD + d) * NN + u * 8;
        pvh[it] = *(const uint4*)(g_vt_hi + gv);
        pvl[it] = *(const uint4*)(g_vt_lo + gv);
    }

    for (int jt = 0; jt < 8; jt++) {
        __syncthreads();
        #pragma unroll
        for (int it = 0; it < 4; it++) {
            int idx = tid + it * 256;
            int d = idx >> 4, u = idx & 15;
            *(uint4*)(smc + OFF_KT_HI + d * VT_B + u * 16) = pvh[it];
            *(uint4*)(smc + OFF_KT_LO + d * VT_B + u * 16) = pvl[it];
        }
        __syncthreads();
        if (jt < 7) {
            #pragma unroll
            for (int it = 0; it < 4; it++) {
                int idx = tid + it * 256;
                int d = idx >> 4, u = idx & 15;
                size_t gv = ((size_t)bh * DHD + d) * NN + (jt + 1) * 128 + u * 8;
                pvh[it] = *(const uint4*)(g_vt_hi + gv);
                pvl[it] = *(const uint4*)(g_vt_lo + gv);
            }
        }

        #pragma unroll
        for (int ks2 = 0; ks2 < 8; ks2++) {
            uint32_t ah[4], al[4], vh4[4], vl4[4];
            uint32_t aa = smb + OFF_ES_HI + (wm * 16 + (lane & 15)) * ES_B
                        + jt * 256 + ks2 * 32 + (lane >> 4) * 16;
            LDSM4(ah[0], ah[1], ah[2], ah[3], aa);
            LDSM4(al[0], al[1], al[2], al[3], aa + (OFF_ES_LO - OFF_ES_HI));
            uint32_t va = smb + OFF_KT_HI
                        + (wd * 16 + ((sel >> 1) & 1) * 8 + lr) * VT_B
                        + ks2 * 32 + (sel & 1) * 16;
            LDSM4(vh4[0], vh4[1], vh4[2], vh4[3], va);
            LDSM4(vl4[0], vl4[1], vl4[2], vl4[3], va + (OFF_KT_LO - OFF_KT_HI));
            #pragma unroll
            for (int nb = 0; nb < 2; nb++) {
                MMA16816(acc2[nb], ah, vh4[nb*2], vh4[nb*2+1]);
                MMA16816(acc2[nb], ah, vl4[nb*2], vl4[nb*2+1]);
                MMA16816(acc2[nb], al, vh4[nb*2], vh4[nb*2+1]);
            }
        }
    }

    // ---- ctx epilogue ----
    const int h = bh & 7;
    #pragma unroll
    for (int nb = 0; nb < 2; nb++)
        #pragma unroll
        for (int hf = 0; hf < 2; hf++) {
            int i = wm * 16 + g + hf * 8;
            int d = wd * 16 + nb * 8 + t * 2;
            float s = invs[i];
            float v0 = acc2[nb][hf * 2 + 0] * s;
            float v1 = acc2[nb][hf * 2 + 1] * s;
            size_t base = ((size_t)(b * NN + i0 + i)) * INNERD + h * DHD + d;
            __nv_bfloat16 h0 = __float2bfloat16(v0);
            __nv_bfloat16 h1 = __float2bfloat16(v1);
            *(__nv_bfloat162*)(g_ctx_hi + base) = __halves2bfloat162(h0, h1);
            *(__nv_bfloat162*)(g_ctx_lo + base) = __halves2bfloat162(
                __float2bfloat16(v0 - __bfloat162float(h0)),
                __float2bfloat16(v1 - __bfloat162float(h1)));
        }
}

// ---------------- final dcl scalar ----------------
__global__ void dcl_kernel(float* out_dcl) {
    __shared__ float red[1024];
    const int tid = threadIdx.x;
    float s = 0.f;
    const int base = tid * 32;
    #pragma unroll 8
    for (int i = 0; i < 32; i++) s += g_clus[base + i];
    red[tid] = s;
    __syncthreads();
    for (int o = 512; o > 0; o >>= 1) {
        if (tid < o) red[tid] += red[tid + o];
        __syncthreads();
    }
    if (tid == 0 && out_dcl) {
        float clus_mean = red[0] / (float)NROWS;
        float regular = ((float)(g_msum >> 3) - (float)(BB * NN)) /
                        ((float)BB * (float)NN * (float)(NN - 1));
        out_dcl[0] = clus_mean + 0.3f * regular;
    }
}

// ---------------- launcher ----------------
extern "C" void kernel_launch(void* const* d_in, const int* in_sizes, int n_in,
                              void* d_out, int out_size) {
    const float* x   = (const float*)d_in[0];
    const int*   msk = (const int*)  d_in[1];
    const float* Wq  = (const float*)d_in[2];
    const float* bq  = (const float*)d_in[3];
    const float* Wk  = (const float*)d_in[4];
    const float* bk  = (const float*)d_in[5];
    const float* Wv  = (const float*)d_in[6];
    const float* bv  = (const float*)d_in[7];
    const float* Wo  = (const float*)d_in[8];
    const float* bo  = (const float*)d_in[9];
    float* out = (float*)d_out;

    const size_t OUTE  = (size_t)BB * NN * DIMD;
    const size_t ATTNE = (size_t)BH * NN * NN;

    float* attn_ptr;
    if ((size_t)out_size >= OUTE + ATTNE) {
        attn_ptr = out + OUTE;
    } else {
        void* p = nullptr;
        cudaGetSymbolAddress(&p, g_attn_fb);
        attn_ptr = (float*)p;
    }
    float* dcl_ptr = ((size_t)out_size >= OUTE + ATTNE + 1) ? (out + OUTE + ATTNE)
                                                            : nullptr;

    cudaFuncSetAttribute(attn3_kernel,
                         cudaFuncAttributeMaxDynamicSharedMemorySize, ATTN_SMEM);
    cudaFuncSetAttribute(bmma_kernel,
                         cudaFuncAttributeMaxDynamicSharedMemorySize, BMMA_SMEM);

    init_kernel<<<1, 32>>>();
    convx_kernel<<<2048, 256>>>(x);
    convw_kernel<<<dim3(16, 16, 4), dim3(32, 8)>>>(Wq, Wk, Wv, Wo);

    dim3 qkvgrid(4, 32, 3);
    bmma_kernel<<<qkvgrid, 256, BMMA_SMEM>>>(bq, bk, bv, nullptr, -1);

    attn3_kernel<<<BH * (NN / 32), 256, ATTN_SMEM>>>(msk, attn_ptr);

    dim3 ogrid(4, 32, 1);
    bmma_kernel<<<ogrid, 256, BMMA_SMEM>>>(bo, bo, bo, out, 3);

    dcl_kernel<<<1, 1024>>>(dcl_ptr);
}

// round 9
// speedup vs baseline: 7.3391x; 1.0518x over previous
#include <cuda_runtime.h>
#include <cuda_bf16.h>
#include <math.h>
#include <stdint.h>

#define BB 4
#define NN 1024
#define DIMD 512
#define HH 8
#define DHD 64
#define INNERD 512
#define BH (BB*HH)            // 32
#define NROWS (BH*NN)         // 32768
#define SCALE 0.125f

// ---------------- scratch (device globals; no runtime allocation) ----------
__device__ float g_qni[NROWS];              // reciprocal q norms
__device__ float g_kni[NROWS];              // reciprocal k norms
__device__ float g_clus[NROWS];
__device__ int   g_msum;                    // 8 * sum(mask)
__device__ float g_attn_fb[(size_t)BH*NN*NN];
// bf16 split operands
__device__ __nv_bfloat16 g_x_hi[(size_t)BB*NN*DIMD];
__device__ __nv_bfloat16 g_x_lo[(size_t)BB*NN*DIMD];
__device__ __nv_bfloat16 g_wt_hi[4*512*512];   // W^T [n][k], slots q,k,v,o
__device__ __nv_bfloat16 g_wt_lo[4*512*512];
__device__ __nv_bfloat16 g_ctx_hi[(size_t)BB*NN*INNERD];
__device__ __nv_bfloat16 g_ctx_lo[(size_t)BB*NN*INNERD];
__device__ __nv_bfloat16 g_q_hi[NROWS*DHD];    // [bh][n][d]
__device__ __nv_bfloat16 g_q_lo[NROWS*DHD];
__device__ __nv_bfloat16 g_k_hi[NROWS*DHD];    // [bh][n][d]
__device__ __nv_bfloat16 g_k_lo[NROWS*DHD];
__device__ __nv_bfloat16 g_vt_hi[NROWS*DHD];   // TRANSPOSED [bh][d][n]
__device__ __nv_bfloat16 g_vt_lo[NROWS*DHD];

// ---------------- helpers ----------------
__device__ __forceinline__ uint32_t smem_to_u32(const void* p) {
    uint32_t a;
    asm("{ .reg .u64 t; cvta.to.shared.u64 t, %1; cvt.u32.u64 %0, t; }"
        : "=r"(a) : "l"(p));
    return a;
}
#define SMEM_SWZ(off) ((off) ^ (((off) >> 3) & 0x70))

#define LDSM4(R0, R1, R2, R3, ADDR) \
    asm volatile("ldmatrix.sync.aligned.m8n8.x4.shared.b16 {%0,%1,%2,%3}, [%4];" \
        : "=r"(R0), "=r"(R1), "=r"(R2), "=r"(R3) : "r"(ADDR))

#define MMA16816(C, A, B0, B1) \
    asm volatile("mma.sync.aligned.m16n8k16.row.col.f32.bf16.bf16.f32 " \
        "{%0,%1,%2,%3}, {%4,%5,%6,%7}, {%8,%9}, {%0,%1,%2,%3};" \
        : "+f"((C)[0]), "+f"((C)[1]), "+f"((C)[2]), "+f"((C)[3]) \
        : "r"((A)[0]), "r"((A)[1]), "r"((A)[2]), "r"((A)[3]), "r"(B0), "r"(B1))

#define CP_ASYNC16(smaddr, gptr) \
    asm volatile("cp.async.cg.shared.global [%0], [%1], 16;" \
        :: "r"(smaddr), "l"(gptr) : "memory")
#define CP_COMMIT() asm volatile("cp.async.commit_group;" ::: "memory")
#define CP_WAIT1() asm volatile("cp.async.wait_group 1;" ::: "memory")
#define CP_WAIT0() asm volatile("cp.async.wait_group 0;" ::: "memory")

__device__ __forceinline__ void split_store4(__nv_bfloat16* hp, __nv_bfloat16* lp,
                                             float v0, float v1, float v2, float v3)
{
    __nv_bfloat16 h0 = __float2bfloat16(v0), h1 = __float2bfloat16(v1);
    __nv_bfloat16 h2 = __float2bfloat16(v2), h3 = __float2bfloat16(v3);
    *(__nv_bfloat162*)(hp)     = __halves2bfloat162(h0, h1);
    *(__nv_bfloat162*)(hp + 2) = __halves2bfloat162(h2, h3);
    *(__nv_bfloat162*)(lp)     = __halves2bfloat162(
        __float2bfloat16(v0 - __bfloat162float(h0)),
        __float2bfloat16(v1 - __bfloat162float(h1)));
    *(__nv_bfloat162*)(lp + 2) = __halves2bfloat162(
        __float2bfloat16(v2 - __bfloat162float(h2)),
        __float2bfloat16(v3 - __bfloat162float(h3)));
}

// ---------------- init ----------------
__global__ void init_kernel() {
    if (threadIdx.x == 0 && blockIdx.x == 0) g_msum = 0;
}

// ---------------- convert x -> hi/lo bf16 ----------------
__global__ void convx_kernel(const float* __restrict__ x) {
    int i = blockIdx.x * blockDim.x + threadIdx.x;   // 524288
    float4 v = ((const float4*)x)[i];
    split_store4(g_x_hi + (size_t)i * 4, g_x_lo + (size_t)i * 4,
                 v.x, v.y, v.z, v.w);
}

// ---------------- transpose+convert W -> W^T hi/lo bf16 ----------------
__global__ void convw_kernel(const float* __restrict__ Wq,
                             const float* __restrict__ Wk,
                             const float* __restrict__ Wv,
                             const float* __restrict__ Wo)
{
    __shared__ float tile[32][33];
    const int z = blockIdx.z;
    const float* W = (z == 0) ? Wq : (z == 1) ? Wk : (z == 2) ? Wv : Wo;
    const int tx = threadIdx.x, ty = threadIdx.y;      // (32, 8)
    const int bk = blockIdx.y * 32, bn = blockIdx.x * 32;
    #pragma unroll
    for (int r = 0; r < 4; r++)
        tile[ty + 8*r][tx] = W[(size_t)(bk + ty + 8*r) * 512 + bn + tx];
    __syncthreads();
    #pragma unroll
    for (int r = 0; r < 4; r++) {
        int n = bn + ty + 8*r, k = bk + tx;
        float v = tile[tx][ty + 8*r];
        __nv_bfloat16 h = __float2bfloat16(v);
        size_t o = (size_t)z * 262144 + (size_t)n * 512 + k;
        g_wt_hi[o] = h;
        g_wt_lo[o] = __float2bfloat16(v - __bfloat162float(h));
    }
}

// ================= HMMA projection GEMM (cp.async double-buffered) =========
// z = 0: q bf16 hi/lo (+inv norms), 1: k bf16 hi/lo (+inv norms),
// 2: v transposed bf16 hi/lo, 3: out fp32 (A=ctx).
#define SA_HI 0
#define SA_LO 16384
#define SB_HI 32768
#define SB_LO 49152
#define STAGE_B 65536
#define BMMA_SMEM (2*STAGE_B)

__global__ __launch_bounds__(256)
void bmma_kernel(const float* __restrict__ b0, const float* __restrict__ b1,
                 const float* __restrict__ b2, float* __restrict__ out, int mode)
{
    extern __shared__ char smc[];
    const uint32_t smb = smem_to_u32(smc);
    const int tid = threadIdx.x;
    const int wid = tid >> 5, lane = tid & 31;
    const int z = (mode < 0) ? (int)blockIdx.z : mode;
    const int bm = blockIdx.y * 128, bn = blockIdx.x * 128;
    const int wm = wid & 3, wn = wid >> 2;

    const __nv_bfloat16* Ah = (z == 3) ? g_ctx_hi : g_x_hi;
    const __nv_bfloat16* Al = (z == 3) ? g_ctx_lo : g_x_lo;
    const __nv_bfloat16* Bh = g_wt_hi + (size_t)z * 262144;
    const __nv_bfloat16* Bl = g_wt_lo + (size_t)z * 262144;
    const float* bias = (z == 0) ? b0 : (z == 1) ? b1 : (z == 2) ? b2 : b0;

    float acc[2][8][4] = {};
    const int ldr = tid >> 3, ldu = tid & 7;

    // cp.async issue for k-chunk kc into stage st
    auto issue = [&](int kc, int st) {
        const uint32_t sb = smb + st * STAGE_B;
        #pragma unroll
        for (int it = 0; it < 4; it++) {
            int r = ldr + it * 32;
            size_t ga = (size_t)(bm + r) * 512 + kc * 64 + ldu * 8;
            size_t gb = (size_t)(bn + r) * 512 + kc * 64 + ldu * 8;
            uint32_t so = SMEM_SWZ((uint32_t)(r * 128 + ldu * 16));
            CP_ASYNC16(sb + SA_HI + so, Ah + ga);
            CP_ASYNC16(sb + SA_LO + so, Al + ga);
            CP_ASYNC16(sb + SB_HI + so, Bh + gb);
            CP_ASYNC16(sb + SB_LO + so, Bl + gb);
        }
        CP_COMMIT();
    };

    issue(0, 0);
    for (int kc = 0; kc < 8; kc++) {
        const int st = kc & 1;
        const uint32_t sb = smb + st * STAGE_B;
        if (kc < 7) { issue(kc + 1, st ^ 1); CP_WAIT1(); }
        else        { CP_WAIT0(); }
        __syncthreads();

        #pragma unroll
        for (int ks = 0; ks < 4; ks++) {
            uint32_t ah[2][4], al[2][4], bhf[8][2], blf[8][2];
            const int arow = wm * 32 + (lane & 15);
            const int akb  = ks * 32 + (lane >> 4) * 16;
            #pragma unroll
            for (int m = 0; m < 2; m++) {
                uint32_t off = SMEM_SWZ((uint32_t)((arow + m * 16) * 128 + akb));
                LDSM4(ah[m][0], ah[m][1], ah[m][2], ah[m][3], sb + SA_HI + off);
                LDSM4(al[m][0], al[m][1], al[m][2], al[m][3], sb + SA_LO + off);
            }
            const int lr = lane & 7, sel = lane >> 3;
            const int nrow = wn * 64 + ((sel >> 1) & 1) * 8 + lr;
            const int bkb  = ks * 32 + (sel & 1) * 16;
            #pragma unroll
            for (int p = 0; p < 4; p++) {
                uint32_t off = SMEM_SWZ((uint32_t)((nrow + p * 16) * 128 + bkb));
                LDSM4(bhf[2*p][0], bhf[2*p][1], bhf[2*p+1][0], bhf[2*p+1][1],
                      sb + SB_HI + off);
                LDSM4(blf[2*p][0], blf[2*p][1], blf[2*p+1][0], blf[2*p+1][1],
                      sb + SB_LO + off);
            }
            #pragma unroll
            for (int m = 0; m < 2; m++)
                #pragma unroll
                for (int nb = 0; nb < 8; nb++) {
                    MMA16816(acc[m][nb], ah[m], bhf[nb][0], bhf[nb][1]);
                    MMA16816(acc[m][nb], ah[m], blf[nb][0], blf[nb][1]);
                    MMA16816(acc[m][nb], al[m], bhf[nb][0], bhf[nb][1]);
                }
        }
        __syncthreads();   // protect stage st before it is refilled at kc+2
    }

    // ---------------- epilogue ----------------
    const int g = lane >> 2, t = lane & 3;
    const int cb = bn + wn * 64;
    const int h = cb >> 6;
    float2 bv[8];
    #pragma unroll
    for (int nb = 0; nb < 8; nb++)
        bv[nb] = *(const float2*)&bias[cb + nb * 8 + 2 * t];

    #pragma unroll
    for (int m = 0; m < 2; m++) {
        #pragma unroll
        for (int half = 0; half < 2; half++) {
            const int rglob = bm + wm * 32 + m * 16 + g + half * 8;
            const int bi = rglob >> 10, n = rglob & 1023;
            float ss = 0.f;
            #pragma unroll
            for (int nb = 0; nb < 8; nb++) {
                float v0 = acc[m][nb][half * 2 + 0] + bv[nb].x;
                float v1 = acc[m][nb][half * 2 + 1] + bv[nb].y;
                ss += v0 * v0 + v1 * v1;
                const int d = nb * 8 + 2 * t;
                if (z == 3) {
                    *(float2*)(out + (size_t)rglob * 512 + cb + d) =
                        make_float2(v0, v1);
                } else {
                    __nv_bfloat16 h0 = __float2bfloat16(v0);
                    __nv_bfloat16 h1 = __float2bfloat16(v1);
                    __nv_bfloat16 l0 = __float2bfloat16(v0 - __bfloat162float(h0));
                    __nv_bfloat16 l1 = __float2bfloat16(v1 - __bfloat162float(h1));
                    if (z == 2) {
                        size_t vb = ((size_t)(bi*HH + h)*DHD + d)*NN + n;
                        g_vt_hi[vb] = h0; g_vt_hi[vb + NN] = h1;
                        g_vt_lo[vb] = l0; g_vt_lo[vb + NN] = l1;
                    } else {
                        __nv_bfloat16* dh = (z == 0) ? g_q_hi : g_k_hi;
                        __nv_bfloat16* dl = (z == 0) ? g_q_lo : g_k_lo;
                        size_t qb = ((size_t)(bi*HH + h)*NN + n)*DHD + d;
                        *(__nv_bfloat162*)(dh + qb) = __halves2bfloat162(h0, h1);
                        *(__nv_bfloat162*)(dl + qb) = __halves2bfloat162(l0, l1);
                    }
                }
            }
            if (z < 2) {
                ss += __shfl_xor_sync(0xffffffffu, ss, 1);
                ss += __shfl_xor_sync(0xffffffffu, ss, 2);
                if (t == 0) {
                    float* dst = (z == 0) ? g_qni : g_kni;
                    dst[(bi * HH + h) * NN + n] = rsqrtf(ss);
                }
            }
        }
    }
}

// ============ fused attention: HMMA scores + softmax + contrastive + HMMA AV
#define ES_B 2064
#define QT_B 144
#define KT_B 144
#define VT_B 272
#define OFF_ES_HI 0
#define OFF_ES_LO 66048
#define OFF_QT_HI 132096
#define OFF_QT_LO 136704
#define OFF_KT_HI 141312
#define OFF_KT_LO 159744
#define OFF_RED   178176
#define OFF_INVS  181248
#define OFF_WCNT  181376
#define ATTN_SMEM 181440

__global__ __launch_bounds__(256, 1)
void attn3_kernel(const int* __restrict__ mask, float* __restrict__ attn_out)
{
    extern __shared__ char smc[];
    const uint32_t smb = smem_to_u32(smc);
    float* invs = (float*)(smc + OFF_INVS);
    float* red  = (float*)(smc + OFF_RED);
    int*   wcnt = (int*)(smc + OFF_WCNT);

    const int tid  = threadIdx.x;
    const int warp = tid >> 5, lane = tid & 31;
    const int g = lane >> 2, t = lane & 3;
    const int lr = lane & 7, sel = lane >> 3;
    const int blk = blockIdx.x;             // 1024
    const int bh  = blk >> 5;
    const int i0  = (blk & 31) * 32;
    const int b   = bh >> 3;

    {
        int r = tid >> 3, u = tid & 7;
        size_t gq = ((size_t)(bh * NN + i0 + r)) * DHD + u * 8;
        *(uint4*)(smc + OFF_QT_HI + r * QT_B + u * 16) = *(const uint4*)(g_q_hi + gq);
        *(uint4*)(smc + OFF_QT_LO + r * QT_B + u * 16) = *(const uint4*)(g_q_lo + gq);
    }
    __syncthreads();

    uint32_t qh[2][4][4], ql[2][4][4];
    #pragma unroll
    for (int m = 0; m < 2; m++)
        #pragma unroll
        for (int ks = 0; ks < 4; ks++) {
            uint32_t a = smb + OFF_QT_HI + (m * 16 + (lane & 15)) * QT_B
                       + ks * 32 + (lane >> 4) * 16;
            LDSM4(qh[m][ks][0], qh[m][ks][1], qh[m][ks][2], qh[m][ks][3], a);
            LDSM4(ql[m][ks][0], ql[m][ks][1], ql[m][ks][2], ql[m][ks][3],
                  a + (OFF_QT_LO - OFF_QT_HI));
        }

    float qn10[2][2];
    #pragma unroll
    for (int m = 0; m < 2; m++)
        #pragma unroll
        for (int hf = 0; hf < 2; hf++)
            qn10[m][hf] = g_qni[bh * NN + i0 + m * 16 + g + hf * 8] * 10.0f;

    float rall[2][2] = {}, rpos[2][2] = {}, rsum[2][2] = {};
    int cnt = 0;

    uint4 pkh[4], pkl[4];
    #pragma unroll
    for (int it = 0; it < 4; it++) {
        int idx = tid + it * 256;
        int r = idx >> 3, u = idx & 7;
        size_t gk = ((size_t)(bh * NN + r)) * DHD + u * 8;
        pkh[it] = *(const uint4*)(g_k_hi + gk);
        pkl[it] = *(const uint4*)(g_k_lo + gk);
    }

    for (int jt = 0; jt < 8; jt++) {
        __syncthreads();
        #pragma unroll
        for (int it = 0; it < 4; it++) {
            int idx = tid + it * 256;
            int r = idx >> 3, u = idx & 7;
            *(uint4*)(smc + OFF_KT_HI + r * KT_B + u * 16) = pkh[it];
            *(uint4*)(smc + OFF_KT_LO + r * KT_B + u * 16) = pkl[it];
        }
        __syncthreads();
        if (jt < 7) {
            #pragma unroll
            for (int it = 0; it < 4; it++) {
                int idx = tid + it * 256;
                int r = idx >> 3, u = idx & 7;
                size_t gk = ((size_t)(bh * NN + (jt + 1) * 128 + r)) * DHD + u * 8;
                pkh[it] = *(const uint4*)(g_k_hi + gk);
                pkl[it] = *(const uint4*)(g_k_lo + gk);
            }
        }

        float acc[2][2][4] = {};
        #pragma unroll
        for (int ks = 0; ks < 4; ks++) {
            uint32_t kh4[4], kl4[4];
            uint32_t ka = smb + OFF_KT_HI
                        + (warp * 16 + ((sel >> 1) & 1) * 8 + lr) * KT_B
                        + ks * 32 + (sel & 1) * 16;
            LDSM4(kh4[0], kh4[1], kh4[2], kh4[3], ka);
            LDSM4(kl4[0], kl4[1], kl4[2], kl4[3], ka + (OFF_KT_LO - OFF_KT_HI));
            #pragma unroll
            for (int m = 0; m < 2; m++)
                #pragma unroll
                for (int nb = 0; nb < 2; nb++) {
                    MMA16816(acc[m][nb], qh[m][ks], kh4[nb*2], kh4[nb*2+1]);
                    MMA16816(acc[m][nb], qh[m][ks], kl4[nb*2], kl4[nb*2+1]);
                    MMA16816(acc[m][nb], ql[m][ks], kh4[nb*2], kh4[nb*2+1]);
                }
        }

        #pragma unroll
        for (int nb = 0; nb < 2; nb++) {
            const int j = jt * 128 + warp * 16 + nb * 8 + t * 2;
            float2 kn = *(const float2*)&g_kni[bh * NN + j];
            #pragma unroll
            for (int m = 0; m < 2; m++)
                #pragma unroll
                for (int hf = 0; hf < 2; hf++) {
                    const int il = m * 16 + g + hf * 8;
                    int2 mm = *(const int2*)(mask +
                              ((size_t)(b * NN + i0 + il)) * NN + j);
                    float d0 = acc[m][nb][hf * 2 + 0];
                    float d1 = acc[m][nb][hf * 2 + 1];
                    float qn = qn10[m][hf];
                    float ec0 = __expf(d0 * qn * kn.x);
                    float ec1 = __expf(d1 * qn * kn.y);
                    rall[m][hf] += ec0 + ec1;
                    rpos[m][hf] += (mm.x ? ec0 : 0.f) + (mm.y ? ec1 : 0.f);
                    cnt += (mm.x != 0) + (mm.y != 0);
                    float es0 = mm.x ? __expf(d0 * SCALE) : 0.f;
                    float es1 = mm.y ? __expf(d1 * SCALE) : 0.f;
                    rsum[m][hf] += es0 + es1;
                    __nv_bfloat16 h0 = __float2bfloat16(es0);
                    __nv_bfloat16 h1 = __float2bfloat16(es1);
                    *(__nv_bfloat162*)(smc + OFF_ES_HI + il * ES_B + j * 2) =
                        __halves2bfloat162(h0, h1);
                    *(__nv_bfloat162*)(smc + OFF_ES_LO + il * ES_B + j * 2) =
                        __halves2bfloat162(
                            __float2bfloat16(es0 - __bfloat162float(h0)),
                            __float2bfloat16(es1 - __bfloat162float(h1)));
                }
        }
    }

    #pragma unroll
    for (int m = 0; m < 2; m++)
        #pragma unroll
        for (int hf = 0; hf < 2; hf++) {
            #pragma unroll
            for (int o = 1; o <= 2; o <<= 1) {
                rall[m][hf] += __shfl_xor_sync(0xffffffffu, rall[m][hf], o);
                rpos[m][hf] += __shfl_xor_sync(0xffffffffu, rpos[m][hf], o);
                rsum[m][hf] += __shfl_xor_sync(0xffffffffu, rsum[m][hf], o);
            }
        }
    #pragma unroll
    for (int o = 16; o > 0; o >>= 1)
        cnt += __shfl_xor_sync(0xffffffffu, cnt, o);
    if (t == 0) {
        #pragma unroll
        for (int m = 0; m < 2; m++)
            #pragma unroll
            for (int hf = 0; hf < 2; hf++) {
                int il = m * 16 + g + hf * 8;
                red[(warp * 32 + il) * 3 + 0] = rall[m][hf];
                red[(warp * 32 + il) * 3 + 1] = rpos[m][hf];
                red[(warp * 32 + il) * 3 + 2] = rsum[m][hf];
            }
    }
    if (lane == 0) wcnt[warp] = cnt;
    __syncthreads();
    if (tid < 32) {
        float a = 0.f, p = 0.f, s = 0.f;
        #pragma unroll
        for (int w = 0; w < 8; w++) {
            a += red[(w * 32 + tid) * 3 + 0];
            p += red[(w * 32 + tid) * 3 + 1];
            s += red[(w * 32 + tid) * 3 + 2];
        }
        invs[tid] = __frcp_rn(s);
        g_clus[bh * NN + i0 + tid] = -__logf(__fdividef(p, a));
    }
    if (tid == 32) {
        int s = 0;
        #pragma unroll
        for (int w = 0; w < 8; w++) s += wcnt[w];
        atomicAdd(&g_msum, s);
    }
    __syncthreads();

    #pragma unroll 4
    for (int it = 0; it < 16; it++) {
        int idx = tid + it * 256;
        int row = idx >> 7, u = idx & 127;
        uint4 vh = *(const uint4*)(smc + OFF_ES_HI + row * ES_B + u * 16);
        uint4 vl = *(const uint4*)(smc + OFF_ES_LO + row * ES_B + u * 16);
        float s = invs[row];
        float ov[8];
        const __nv_bfloat162* ph = (const __nv_bfloat162*)&vh;
        const __nv_bfloat162* pl = (const __nv_bfloat162*)&vl;
        #pragma unroll
        for (int p2 = 0; p2 < 4; p2++) {
            ov[2*p2+0] = (__bfloat162float(ph[p2].x) + __bfloat162float(pl[p2].x)) * s;
            ov[2*p2+1] = (__bfloat162float(ph[p2].y) + __bfloat162float(pl[p2].y)) * s;
        }
        float* dst = attn_out + ((size_t)bh * NN + i0 + row) * NN + u * 8;
        *(float4*)dst       = make_float4(ov[0], ov[1], ov[2], ov[3]);
        *(float4*)(dst + 4) = make_float4(ov[4], ov[5], ov[6], ov[7]);
    }

    // ---- Phase B: ctx = es @ V on HMMA ----
    const int wm = warp >> 2, wd = warp & 3;
    float acc2[2][4] = {};

    uint4 pvh[4], pvl[4];
    #pragma unroll
    for (int it = 0; it < 4; it++) {
        int idx = tid + it * 256;
        int d = idx >> 4, u = idx & 15;
        size_t gv = ((size_t)bh * DHD + d) * NN + u * 8;
        pvh[it] = *(const uint4*)(g_vt_hi + gv);
        pvl[it] = *(const uint4*)(g_vt_lo + gv);
    }

    for (int jt = 0; jt < 8; jt++) {
        __syncthreads();
        #pragma unroll
        for (int it = 0; it < 4; it++) {
            int idx = tid + it * 256;
            int d = idx >> 4, u = idx & 15;
            *(uint4*)(smc + OFF_KT_HI + d * VT_B + u * 16) = pvh[it];
            *(uint4*)(smc + OFF_KT_LO + d * VT_B + u * 16) = pvl[it];
        }
        __syncthreads();
        if (jt < 7) {
            #pragma unroll
            for (int it = 0; it < 4; it++) {
                int idx = tid + it * 256;
                int d = idx >> 4, u = idx & 15;
                size_t gv = ((size_t)bh * DHD + d) * NN + (jt + 1) * 128 + u * 8;
                pvh[it] = *(const uint4*)(g_vt_hi + gv);
                pvl[it] = *(const uint4*)(g_vt_lo + gv);
            }
        }

        #pragma unroll
        for (int ks2 = 0; ks2 < 8; ks2++) {
            uint32_t ah[4], al[4], vh4[4], vl4[4];
            uint32_t aa = smb + OFF_ES_HI + (wm * 16 + (lane & 15)) * ES_B
                        + jt * 256 + ks2 * 32 + (lane >> 4) * 16;
            LDSM4(ah[0], ah[1], ah[2], ah[3], aa);
            LDSM4(al[0], al[1], al[2], al[3], aa + (OFF_ES_LO - OFF_ES_HI));
            uint32_t va = smb + OFF_KT_HI
                        + (wd * 16 + ((sel >> 1) & 1) * 8 + lr) * VT_B
                        + ks2 * 32 + (sel & 1) * 16;
            LDSM4(vh4[0], vh4[1], vh4[2], vh4[3], va);
            LDSM4(vl4[0], vl4[1], vl4[2], vl4[3], va + (OFF_KT_LO - OFF_KT_HI));
            #pragma unroll
            for (int nb = 0; nb < 2; nb++) {
                MMA16816(acc2[nb], ah, vh4[nb*2], vh4[nb*2+1]);
                MMA16816(acc2[nb], ah, vl4[nb*2], vl4[nb*2+1]);
                MMA16816(acc2[nb], al, vh4[nb*2], vh4[nb*2+1]);
            }
        }
    }

    const int h = bh & 7;
    #pragma unroll
    for (int nb = 0; nb < 2; nb++)
        #pragma unroll
        for (int hf = 0; hf < 2; hf++) {
            int i = wm * 16 + g + hf * 8;
            int d = wd * 16 + nb * 8 + t * 2;
            float s = invs[i];
            float v0 = acc2[nb][hf * 2 + 0] * s;
            float v1 = acc2[nb][hf * 2 + 1] * s;
            size_t base = ((size_t)(b * NN + i0 + i)) * INNERD + h * DHD + d;
            __nv_bfloat16 h0 = __float2bfloat16(v0);
            __nv_bfloat16 h1 = __float2bfloat16(v1);
            *(__nv_bfloat162*)(g_ctx_hi + base) = __halves2bfloat162(h0, h1);
            *(__nv_bfloat162*)(g_ctx_lo + base) = __halves2bfloat162(
                __float2bfloat16(v0 - __bfloat162float(h0)),
                __float2bfloat16(v1 - __bfloat162float(h1)));
        }
}

// ---------------- final dcl scalar ----------------
__global__ void dcl_kernel(float* out_dcl) {
    __shared__ float red[1024];
    const int tid = threadIdx.x;
    float s = 0.f;
    const int base = tid * 32;
    #pragma unroll 8
    for (int i = 0; i < 32; i++) s += g_clus[base + i];
    red[tid] = s;
    __syncthreads();
    for (int o = 512; o > 0; o >>= 1) {
        if (tid < o) red[tid] += red[tid + o];
        __syncthreads();
    }
    if (tid == 0 && out_dcl) {
        float clus_mean = red[0] / (float)NROWS;
        float regular = ((float)(g_msum >> 3) - (float)(BB * NN)) /
                        ((float)BB * (float)NN * (float)(NN - 1));
        out_dcl[0] = clus_mean + 0.3f * regular;
    }
}

// ---------------- launcher ----------------
extern "C" void kernel_launch(void* const* d_in, const int* in_sizes, int n_in,
                              void* d_out, int out_size) {
    const float* x   = (const float*)d_in[0];
    const int*   msk = (const int*)  d_in[1];
    const float* Wq  = (const float*)d_in[2];
    const float* bq  = (const float*)d_in[3];
    const float* Wk  = (const float*)d_in[4];
    const float* bk  = (const float*)d_in[5];
    const float* Wv  = (const float*)d_in[6];
    const float* bv  = (const float*)d_in[7];
    const float* Wo  = (const float*)d_in[8];
    const float* bo  = (const float*)d_in[9];
    float* out = (float*)d_out;

    const size_t OUTE  = (size_t)BB * NN * DIMD;
    const size_t ATTNE = (size_t)BH * NN * NN;

    float* attn_ptr;
    if ((size_t)out_size >= OUTE + ATTNE) {
        attn_ptr = out + OUTE;
    } else {
        void* p = nullptr;
        cudaGetSymbolAddress(&p, g_attn_fb);
        attn_ptr = (float*)p;
    }
    float* dcl_ptr = ((size_t)out_size >= OUTE + ATTNE + 1) ? (out + OUTE + ATTNE)
                                                            : nullptr;

    cudaFuncSetAttribute(attn3_kernel,
                         cudaFuncAttributeMaxDynamicSharedMemorySize, ATTN_SMEM);
    cudaFuncSetAttribute(bmma_kernel,
                         cudaFuncAttributeMaxDynamicSharedMemorySize, BMMA_SMEM);

    init_kernel<<<1, 32>>>();
    convx_kernel<<<2048, 256>>>(x);
    convw_kernel<<<dim3(16, 16, 4), dim3(32, 8)>>>(Wq, Wk, Wv, Wo);

    dim3 qkvgrid(4, 32, 3);
    bmma_kernel<<<qkvgrid, 256, BMMA_SMEM>>>(bq, bk, bv, nullptr, -1);

    attn3_kernel<<<BH * (NN / 32), 256, ATTN_SMEM>>>(msk, attn_ptr);

    dim3 ogrid(4, 32, 1);
    bmma_kernel<<<ogrid, 256, BMMA_SMEM>>>(bo, bo, bo, out, 3);

    dcl_kernel<<<1, 1024>>>(dcl_ptr);
}

// round 10
// speedup vs baseline: 7.5257x; 1.0254x over previous
#include <cuda_runtime.h>
#include <cuda_bf16.h>
#include <math.h>
#include <stdint.h>

#define BB 4
#define NN 1024
#define DIMD 512
#define HH 8
#define DHD 64
#define INNERD 512
#define BH (BB*HH)            // 32
#define NROWS (BH*NN)         // 32768
#define SCALE 0.125f

// ---------------- scratch (device globals; no runtime allocation) ----------
__device__ float g_qni[NROWS];              // reciprocal q norms
__device__ float g_kni[NROWS];              // reciprocal k norms
__device__ float g_clus[NROWS];
__device__ int   g_msum;                    // 8 * sum(mask)
__device__ float g_attn_fb[(size_t)BH*NN*NN];
// bf16 split operands
__device__ __nv_bfloat16 g_x_hi[(size_t)BB*NN*DIMD];
__device__ __nv_bfloat16 g_x_lo[(size_t)BB*NN*DIMD];
__device__ __nv_bfloat16 g_wt_hi[4*512*512];   // W^T [n][k], slots q,k,v,o
__device__ __nv_bfloat16 g_wt_lo[4*512*512];
__device__ __nv_bfloat16 g_ctx_hi[(size_t)BB*NN*INNERD];
__device__ __nv_bfloat16 g_ctx_lo[(size_t)BB*NN*INNERD];
__device__ __nv_bfloat16 g_q_hi[NROWS*DHD];    // [bh][n][d]
__device__ __nv_bfloat16 g_q_lo[NROWS*DHD];
__device__ __nv_bfloat16 g_k_hi[NROWS*DHD];    // [bh][n][d]
__device__ __nv_bfloat16 g_k_lo[NROWS*DHD];
__device__ __nv_bfloat16 g_vt_hi[NROWS*DHD];   // TRANSPOSED [bh][d][n]
__device__ __nv_bfloat16 g_vt_lo[NROWS*DHD];

// ---------------- helpers ----------------
__device__ __forceinline__ uint32_t smem_to_u32(const void* p) {
    uint32_t a;
    asm("{ .reg .u64 t; cvta.to.shared.u64 t, %1; cvt.u32.u64 %0, t; }"
        : "=r"(a) : "l"(p));
    return a;
}
#define SMEM_SWZ(off) ((off) ^ (((off) >> 3) & 0x70))

#define LDSM4(R0, R1, R2, R3, ADDR) \
    asm volatile("ldmatrix.sync.aligned.m8n8.x4.shared.b16 {%0,%1,%2,%3}, [%4];" \
        : "=r"(R0), "=r"(R1), "=r"(R2), "=r"(R3) : "r"(ADDR))

#define MMA16816(C, A, B0, B1) \
    asm volatile("mma.sync.aligned.m16n8k16.row.col.f32.bf16.bf16.f32 " \
        "{%0,%1,%2,%3}, {%4,%5,%6,%7}, {%8,%9}, {%0,%1,%2,%3};" \
        : "+f"((C)[0]), "+f"((C)[1]), "+f"((C)[2]), "+f"((C)[3]) \
        : "r"((A)[0]), "r"((A)[1]), "r"((A)[2]), "r"((A)[3]), "r"(B0), "r"(B1))

#define CP_ASYNC16(smaddr, gptr) \
    asm volatile("cp.async.cg.shared.global [%0], [%1], 16;" \
        :: "r"(smaddr), "l"(gptr) : "memory")
#define CP_COMMIT() asm volatile("cp.async.commit_group;" ::: "memory")
#define CP_WAIT1() asm volatile("cp.async.wait_group 1;" ::: "memory")
#define CP_WAIT0() asm volatile("cp.async.wait_group 0;" ::: "memory")

// FMA-pipe exp (no MUFU): exp(x) = 2^(x*log2e), magic-number range reduction,
// degree-5 poly on [-0.5,0.5], exponent insert via int add. rel err ~1e-7.
__device__ __forceinline__ float fexp(float x) {
    float t = x * 1.4426950408889634f;
    float z = t + 12582912.0f;               // 2^23 + 2^22
    int ni = __float_as_int(z) << 23;        // == n << 23 (mod 2^32)
    float f = t - (z - 12582912.0f);
    float p =            1.3333558e-3f;
    p = fmaf(p, f, 9.6181291e-3f);
    p = fmaf(p, f, 5.5504110e-2f);
    p = fmaf(p, f, 2.4022651e-1f);
    p = fmaf(p, f, 6.9314718e-1f);
    p = fmaf(p, f, 1.0f);
    return __int_as_float(__float_as_int(p) + ni);
}

__device__ __forceinline__ void split_store4(__nv_bfloat16* hp, __nv_bfloat16* lp,
                                             float v0, float v1, float v2, float v3)
{
    __nv_bfloat16 h0 = __float2bfloat16(v0), h1 = __float2bfloat16(v1);
    __nv_bfloat16 h2 = __float2bfloat16(v2), h3 = __float2bfloat16(v3);
    *(__nv_bfloat162*)(hp)     = __halves2bfloat162(h0, h1);
    *(__nv_bfloat162*)(hp + 2) = __halves2bfloat162(h2, h3);
    *(__nv_bfloat162*)(lp)     = __halves2bfloat162(
        __float2bfloat16(v0 - __bfloat162float(h0)),
        __float2bfloat16(v1 - __bfloat162float(h1)));
    *(__nv_bfloat162*)(lp + 2) = __halves2bfloat162(
        __float2bfloat16(v2 - __bfloat162float(h2)),
        __float2bfloat16(v3 - __bfloat162float(h3)));
}

// ---------------- init ----------------
__global__ void init_kernel() {
    if (threadIdx.x == 0 && blockIdx.x == 0) g_msum = 0;
}

// ---------------- convert x -> hi/lo bf16 ----------------
__global__ void convx_kernel(const float* __restrict__ x) {
    int i = blockIdx.x * blockDim.x + threadIdx.x;   // 524288
    float4 v = ((const float4*)x)[i];
    split_store4(g_x_hi + (size_t)i * 4, g_x_lo + (size_t)i * 4,
                 v.x, v.y, v.z, v.w);
}

// ---------------- transpose+convert W -> W^T hi/lo bf16 ----------------
__global__ void convw_kernel(const float* __restrict__ Wq,
                             const float* __restrict__ Wk,
                             const float* __restrict__ Wv,
                             const float* __restrict__ Wo)
{
    __shared__ float tile[32][33];
    const int z = blockIdx.z;
    const float* W = (z == 0) ? Wq : (z == 1) ? Wk : (z == 2) ? Wv : Wo;
    const int tx = threadIdx.x, ty = threadIdx.y;      // (32, 8)
    const int bk = blockIdx.y * 32, bn = blockIdx.x * 32;
    #pragma unroll
    for (int r = 0; r < 4; r++)
        tile[ty + 8*r][tx] = W[(size_t)(bk + ty + 8*r) * 512 + bn + tx];
    __syncthreads();
    #pragma unroll
    for (int r = 0; r < 4; r++) {
        int n = bn + ty + 8*r, k = bk + tx;
        float v = tile[tx][ty + 8*r];
        __nv_bfloat16 h = __float2bfloat16(v);
        size_t o = (size_t)z * 262144 + (size_t)n * 512 + k;
        g_wt_hi[o] = h;
        g_wt_lo[o] = __float2bfloat16(v - __bfloat162float(h));
    }
}

// ================= HMMA projection GEMM (cp.async double-buffered) =========
#define SA_HI 0
#define SA_LO 16384
#define SB_HI 32768
#define SB_LO 49152
#define STAGE_B 65536
#define BMMA_SMEM (2*STAGE_B)

__global__ __launch_bounds__(256)
void bmma_kernel(const float* __restrict__ b0, const float* __restrict__ b1,
                 const float* __restrict__ b2, float* __restrict__ out, int mode)
{
    extern __shared__ char smc[];
    const uint32_t smb = smem_to_u32(smc);
    const int tid = threadIdx.x;
    const int wid = tid >> 5, lane = tid & 31;
    const int z = (mode < 0) ? (int)blockIdx.z : mode;
    const int bm = blockIdx.y * 128, bn = blockIdx.x * 128;
    const int wm = wid & 3, wn = wid >> 2;

    const __nv_bfloat16* Ah = (z == 3) ? g_ctx_hi : g_x_hi;
    const __nv_bfloat16* Al = (z == 3) ? g_ctx_lo : g_x_lo;
    const __nv_bfloat16* Bh = g_wt_hi + (size_t)z * 262144;
    const __nv_bfloat16* Bl = g_wt_lo + (size_t)z * 262144;
    const float* bias = (z == 0) ? b0 : (z == 1) ? b1 : (z == 2) ? b2 : b0;

    float acc[2][8][4] = {};
    const int ldr = tid >> 3, ldu = tid & 7;

    auto issue = [&](int kc, int st) {
        const uint32_t sb = smb + st * STAGE_B;
        #pragma unroll
        for (int it = 0; it < 4; it++) {
            int r = ldr + it * 32;
            size_t ga = (size_t)(bm + r) * 512 + kc * 64 + ldu * 8;
            size_t gb = (size_t)(bn + r) * 512 + kc * 64 + ldu * 8;
            uint32_t so = SMEM_SWZ((uint32_t)(r * 128 + ldu * 16));
            CP_ASYNC16(sb + SA_HI + so, Ah + ga);
            CP_ASYNC16(sb + SA_LO + so, Al + ga);
            CP_ASYNC16(sb + SB_HI + so, Bh + gb);
            CP_ASYNC16(sb + SB_LO + so, Bl + gb);
        }
        CP_COMMIT();
    };

    issue(0, 0);
    for (int kc = 0; kc < 8; kc++) {
        const int st = kc & 1;
        const uint32_t sb = smb + st * STAGE_B;
        if (kc < 7) { issue(kc + 1, st ^ 1); CP_WAIT1(); }
        else        { CP_WAIT0(); }
        __syncthreads();

        #pragma unroll
        for (int ks = 0; ks < 4; ks++) {
            uint32_t ah[2][4], al[2][4], bhf[8][2], blf[8][2];
            const int arow = wm * 32 + (lane & 15);
            const int akb  = ks * 32 + (lane >> 4) * 16;
            #pragma unroll
            for (int m = 0; m < 2; m++) {
                uint32_t off = SMEM_SWZ((uint32_t)((arow + m * 16) * 128 + akb));
                LDSM4(ah[m][0], ah[m][1], ah[m][2], ah[m][3], sb + SA_HI + off);
                LDSM4(al[m][0], al[m][1], al[m][2], al[m][3], sb + SA_LO + off);
            }
            const int lr = lane & 7, sel = lane >> 3;
            const int nrow = wn * 64 + ((sel >> 1) & 1) * 8 + lr;
            const int bkb  = ks * 32 + (sel & 1) * 16;
            #pragma unroll
            for (int p = 0; p < 4; p++) {
                uint32_t off = SMEM_SWZ((uint32_t)((nrow + p * 16) * 128 + bkb));
                LDSM4(bhf[2*p][0], bhf[2*p][1], bhf[2*p+1][0], bhf[2*p+1][1],
                      sb + SB_HI + off);
                LDSM4(blf[2*p][0], blf[2*p][1], blf[2*p+1][0], blf[2*p+1][1],
                      sb + SB_LO + off);
            }
            #pragma unroll
            for (int m = 0; m < 2; m++)
                #pragma unroll
                for (int nb = 0; nb < 8; nb++) {
                    MMA16816(acc[m][nb], ah[m], bhf[nb][0], bhf[nb][1]);
                    MMA16816(acc[m][nb], ah[m], blf[nb][0], blf[nb][1]);
                    MMA16816(acc[m][nb], al[m], bhf[nb][0], bhf[nb][1]);
                }
        }
        __syncthreads();
    }

    // ---------------- epilogue ----------------
    const int g = lane >> 2, t = lane & 3;
    const int cb = bn + wn * 64;
    const int h = cb >> 6;
    float2 bv[8];
    #pragma unroll
    for (int nb = 0; nb < 8; nb++)
        bv[nb] = *(const float2*)&bias[cb + nb * 8 + 2 * t];

    #pragma unroll
    for (int m = 0; m < 2; m++) {
        #pragma unroll
        for (int half = 0; half < 2; half++) {
            const int rglob = bm + wm * 32 + m * 16 + g + half * 8;
            const int bi = rglob >> 10, n = rglob & 1023;
            float ss = 0.f;
            #pragma unroll
            for (int nb = 0; nb < 8; nb++) {
                float v0 = acc[m][nb][half * 2 + 0] + bv[nb].x;
                float v1 = acc[m][nb][half * 2 + 1] + bv[nb].y;
                ss += v0 * v0 + v1 * v1;
                const int d = nb * 8 + 2 * t;
                if (z == 3) {
                    *(float2*)(out + (size_t)rglob * 512 + cb + d) =
                        make_float2(v0, v1);
                } else {
                    __nv_bfloat16 h0 = __float2bfloat16(v0);
                    __nv_bfloat16 h1 = __float2bfloat16(v1);
                    __nv_bfloat16 l0 = __float2bfloat16(v0 - __bfloat162float(h0));
                    __nv_bfloat16 l1 = __float2bfloat16(v1 - __bfloat162float(h1));
                    if (z == 2) {
                        size_t vb = ((size_t)(bi*HH + h)*DHD + d)*NN + n;
                        g_vt_hi[vb] = h0; g_vt_hi[vb + NN] = h1;
                        g_vt_lo[vb] = l0; g_vt_lo[vb + NN] = l1;
                    } else {
                        __nv_bfloat16* dh = (z == 0) ? g_q_hi : g_k_hi;
                        __nv_bfloat16* dl = (z == 0) ? g_q_lo : g_k_lo;
                        size_t qb = ((size_t)(bi*HH + h)*NN + n)*DHD + d;
                        *(__nv_bfloat162*)(dh + qb) = __halves2bfloat162(h0, h1);
                        *(__nv_bfloat162*)(dl + qb) = __halves2bfloat162(l0, l1);
                    }
                }
            }
            if (z < 2) {
                ss += __shfl_xor_sync(0xffffffffu, ss, 1);
                ss += __shfl_xor_sync(0xffffffffu, ss, 2);
                if (t == 0) {
                    float* dst = (z == 0) ? g_qni : g_kni;
                    dst[(bi * HH + h) * NN + n] = rsqrtf(ss);
                }
            }
        }
    }
}

// ============ fused attention: HMMA + FMA-pipe exp + cp.async stages ========
#define ES_B 2064
#define QT_B 144
#define KT_B 144
#define VT_B 272
#define STG_LO 18432
#define OFF_ES_HI 0
#define OFF_ES_LO 66048
#define OFF_QT_HI 132096
#define OFF_QT_LO 136704
#define OFF_ST0   141312
#define OFF_ST1   178176
#define OFF_RED   215040
#define OFF_INVS  218112
#define OFF_WCNT  218240
#define ATTN_SMEM 218304

__global__ __launch_bounds__(256, 1)
void attn3_kernel(const int* __restrict__ mask, float* __restrict__ attn_out)
{
    extern __shared__ char smc[];
    const uint32_t smb = smem_to_u32(smc);
    float* invs = (float*)(smc + OFF_INVS);
    float* red  = (float*)(smc + OFF_RED);
    int*   wcnt = (int*)(smc + OFF_WCNT);

    const int tid  = threadIdx.x;
    const int warp = tid >> 5, lane = tid & 31;
    const int g = lane >> 2, t = lane & 3;
    const int lr = lane & 7, sel = lane >> 3;
    const int blk = blockIdx.x;             // 1024
    const int bh  = blk >> 5;
    const int i0  = (blk & 31) * 32;
    const int b   = bh >> 3;

    const uint32_t stg[2] = {smb + OFF_ST0, smb + OFF_ST1};

    auto issueK = [&](int jt, uint32_t sb) {
        #pragma unroll
        for (int it = 0; it < 4; it++) {
            int idx = tid + it * 256;
            int r = idx >> 3, u = idx & 7;
            size_t gk = ((size_t)(bh * NN + jt * 128 + r)) * DHD + u * 8;
            CP_ASYNC16(sb + r * KT_B + u * 16, g_k_hi + gk);
            CP_ASYNC16(sb + STG_LO + r * KT_B + u * 16, g_k_lo + gk);
        }
        CP_COMMIT();
    };
    auto issueV = [&](int jt, uint32_t sb) {
        #pragma unroll
        for (int it = 0; it < 4; it++) {
            int idx = tid + it * 256;
            int d = idx >> 4, u = idx & 15;
            size_t gv = ((size_t)bh * DHD + d) * NN + jt * 128 + u * 8;
            CP_ASYNC16(sb + d * VT_B + u * 16, g_vt_hi + gv);
            CP_ASYNC16(sb + STG_LO + d * VT_B + u * 16, g_vt_lo + gv);
        }
        CP_COMMIT();
    };

    issueK(0, stg[0]);

    // ---- q tile 32x64 hi/lo ----
    {
        int r = tid >> 3, u = tid & 7;
        size_t gq = ((size_t)(bh * NN + i0 + r)) * DHD + u * 8;
        *(uint4*)(smc + OFF_QT_HI + r * QT_B + u * 16) = *(const uint4*)(g_q_hi + gq);
        *(uint4*)(smc + OFF_QT_LO + r * QT_B + u * 16) = *(const uint4*)(g_q_lo + gq);
    }
    __syncthreads();

    uint32_t qh[2][4][4], ql[2][4][4];
    #pragma unroll
    for (int m = 0; m < 2; m++)
        #pragma unroll
        for (int ks = 0; ks < 4; ks++) {
            uint32_t a = smb + OFF_QT_HI + (m * 16 + (lane & 15)) * QT_B
                       + ks * 32 + (lane >> 4) * 16;
            LDSM4(qh[m][ks][0], qh[m][ks][1], qh[m][ks][2], qh[m][ks][3], a);
            LDSM4(ql[m][ks][0], ql[m][ks][1], ql[m][ks][2], ql[m][ks][3],
                  a + (OFF_QT_LO - OFF_QT_HI));
        }

    float qn10[2][2];
    #pragma unroll
    for (int m = 0; m < 2; m++)
        #pragma unroll
        for (int hf = 0; hf < 2; hf++)
            qn10[m][hf] = g_qni[bh * NN + i0 + m * 16 + g + hf * 8] * 10.0f;

    float rall[2][2] = {}, rpos[2][2] = {}, rsum[2][2] = {};
    int cnt = 0;

    // ---- Phase A: scores ----
    for (int jt = 0; jt < 8; jt++) {
        const uint32_t sb = stg[jt & 1];
        CP_WAIT0();
        __syncthreads();
        if (jt < 7) issueK(jt + 1, stg[(jt + 1) & 1]);

        float acc[2][2][4] = {};
        #pragma unroll
        for (int ks = 0; ks < 4; ks++) {
            uint32_t kh4[4], kl4[4];
            uint32_t ka = sb + (warp * 16 + ((sel >> 1) & 1) * 8 + lr) * KT_B
                        + ks * 32 + (sel & 1) * 16;
            LDSM4(kh4[0], kh4[1], kh4[2], kh4[3], ka);
            LDSM4(kl4[0], kl4[1], kl4[2], kl4[3], ka + STG_LO);
            #pragma unroll
            for (int m = 0; m < 2; m++)
                #pragma unroll
                for (int nb = 0; nb < 2; nb++) {
                    MMA16816(acc[m][nb], qh[m][ks], kh4[nb*2], kh4[nb*2+1]);
                    MMA16816(acc[m][nb], qh[m][ks], kl4[nb*2], kl4[nb*2+1]);
                    MMA16816(acc[m][nb], ql[m][ks], kh4[nb*2], kh4[nb*2+1]);
                }
        }

        #pragma unroll
        for (int nb = 0; nb < 2; nb++) {
            const int j = jt * 128 + warp * 16 + nb * 8 + t * 2;
            float2 kn = *(const float2*)&g_kni[bh * NN + j];
            #pragma unroll
            for (int m = 0; m < 2; m++)
                #pragma unroll
                for (int hf = 0; hf < 2; hf++) {
                    const int il = m * 16 + g + hf * 8;
                    int2 mm = *(const int2*)(mask +
                              ((size_t)(b * NN + i0 + il)) * NN + j);
                    float d0 = acc[m][nb][hf * 2 + 0];
                    float d1 = acc[m][nb][hf * 2 + 1];
                    float qn = qn10[m][hf];
                    float ec0 = fexp(d0 * qn * kn.x);
                    float ec1 = fexp(d1 * qn * kn.y);
                    rall[m][hf] += ec0 + ec1;
                    rpos[m][hf] += (mm.x ? ec0 : 0.f) + (mm.y ? ec1 : 0.f);
                    cnt += (mm.x != 0) + (mm.y != 0);
                    float es0 = mm.x ? fexp(d0 * SCALE) : 0.f;
                    float es1 = mm.y ? fexp(d1 * SCALE) : 0.f;
                    rsum[m][hf] += es0 + es1;
                    __nv_bfloat16 h0 = __float2bfloat16(es0);
                    __nv_bfloat16 h1 = __float2bfloat16(es1);
                    *(__nv_bfloat162*)(smc + OFF_ES_HI + il * ES_B + j * 2) =
                        __halves2bfloat162(h0, h1);
                    *(__nv_bfloat162*)(smc + OFF_ES_LO + il * ES_B + j * 2) =
                        __halves2bfloat162(
                            __float2bfloat16(es0 - __bfloat162float(h0)),
                            __float2bfloat16(es1 - __bfloat162float(h1)));
                }
        }
    }

    #pragma unroll
    for (int m = 0; m < 2; m++)
        #pragma unroll
        for (int hf = 0; hf < 2; hf++) {
            #pragma unroll
            for (int o = 1; o <= 2; o <<= 1) {
                rall[m][hf] += __shfl_xor_sync(0xffffffffu, rall[m][hf], o);
                rpos[m][hf] += __shfl_xor_sync(0xffffffffu, rpos[m][hf], o);
                rsum[m][hf] += __shfl_xor_sync(0xffffffffu, rsum[m][hf], o);
            }
        }
    #pragma unroll
    for (int o = 16; o > 0; o >>= 1)
        cnt += __shfl_xor_sync(0xffffffffu, cnt, o);
    if (t == 0) {
        #pragma unroll
        for (int m = 0; m < 2; m++)
            #pragma unroll
            for (int hf = 0; hf < 2; hf++) {
                int il = m * 16 + g + hf * 8;
                red[(warp * 32 + il) * 3 + 0] = rall[m][hf];
                red[(warp * 32 + il) * 3 + 1] = rpos[m][hf];
                red[(warp * 32 + il) * 3 + 2] = rsum[m][hf];
            }
    }
    if (lane == 0) wcnt[warp] = cnt;
    __syncthreads();
    if (tid < 32) {
        float a = 0.f, p = 0.f, s = 0.f;
        #pragma unroll
        for (int w = 0; w < 8; w++) {
            a += red[(w * 32 + tid) * 3 + 0];
            p += red[(w * 32 + tid) * 3 + 1];
            s += red[(w * 32 + tid) * 3 + 2];
        }
        invs[tid] = __frcp_rn(s);
        g_clus[bh * NN + i0 + tid] = -__logf(__fdividef(p, a));
    }
    if (tid == 32) {
        int s = 0;
        #pragma unroll
        for (int w = 0; w < 8; w++) s += wcnt[w];
        atomicAdd(&g_msum, s);
    }
    __syncthreads();

    // ---- write normalized attn ----
    #pragma unroll 4
    for (int it = 0; it < 16; it++) {
        int idx = tid + it * 256;
        int row = idx >> 7, u = idx & 127;
        uint4 vh = *(const uint4*)(smc + OFF_ES_HI + row * ES_B + u * 16);
        uint4 vl = *(const uint4*)(smc + OFF_ES_LO + row * ES_B + u * 16);
        float s = invs[row];
        float ov[8];
        const __nv_bfloat162* ph = (const __nv_bfloat162*)&vh;
        const __nv_bfloat162* pl = (const __nv_bfloat162*)&vl;
        #pragma unroll
        for (int p2 = 0; p2 < 4; p2++) {
            ov[2*p2+0] = (__bfloat162float(ph[p2].x) + __bfloat162float(pl[p2].x)) * s;
            ov[2*p2+1] = (__bfloat162float(ph[p2].y) + __bfloat162float(pl[p2].y)) * s;
        }
        float* dst = attn_out + ((size_t)bh * NN + i0 + row) * NN + u * 8;
        *(float4*)dst       = make_float4(ov[0], ov[1], ov[2], ov[3]);
        *(float4*)(dst + 4) = make_float4(ov[4], ov[5], ov[6], ov[7]);
    }

    // ---- Phase B: ctx = es @ V on HMMA (cp.async staged) ----
    issueV(0, stg[0]);
    const int wm = warp >> 2, wd = warp & 3;
    float acc2[2][4] = {};

    for (int jt = 0; jt < 8; jt++) {
        const uint32_t sb = stg[jt & 1];
        CP_WAIT0();
        __syncthreads();
        if (jt < 7) issueV(jt + 1, stg[(jt + 1) & 1]);

        #pragma unroll
        for (int ks2 = 0; ks2 < 8; ks2++) {
            uint32_t ah[4], al[4], vh4[4], vl4[4];
            uint32_t aa = smb + OFF_ES_HI + (wm * 16 + (lane & 15)) * ES_B
                        + jt * 256 + ks2 * 32 + (lane >> 4) * 16;
            LDSM4(ah[0], ah[1], ah[2], ah[3], aa);
            LDSM4(al[0], al[1], al[2], al[3], aa + (OFF_ES_LO - OFF_ES_HI));
            uint32_t va = sb + (wd * 16 + ((sel >> 1) & 1) * 8 + lr) * VT_B
                        + ks2 * 32 + (sel & 1) * 16;
            LDSM4(vh4[0], vh4[1], vh4[2], vh4[3], va);
            LDSM4(vl4[0], vl4[1], vl4[2], vl4[3], va + STG_LO);
            #pragma unroll
            for (int nb = 0; nb < 2; nb++) {
                MMA16816(acc2[nb], ah, vh4[nb*2], vh4[nb*2+1]);
                MMA16816(acc2[nb], ah, vl4[nb*2], vl4[nb*2+1]);
                MMA16816(acc2[nb], al, vh4[nb*2], vh4[nb*2+1]);
            }
        }
    }

    const int h = bh & 7;
    #pragma unroll
    for (int nb = 0; nb < 2; nb++)
        #pragma unroll
        for (int hf = 0; hf < 2; hf++) {
            int i = wm * 16 + g + hf * 8;
            int d = wd * 16 + nb * 8 + t * 2;
            float s = invs[i];
            float v0 = acc2[nb][hf * 2 + 0] * s;
            float v1 = acc2[nb][hf * 2 + 1] * s;
            size_t base = ((size_t)(b * NN + i0 + i)) * INNERD + h * DHD + d;
            __nv_bfloat16 h0 = __float2bfloat16(v0);
            __nv_bfloat16 h1 = __float2bfloat16(v1);
            *(__nv_bfloat162*)(g_ctx_hi + base) = __halves2bfloat162(h0, h1);
            *(__nv_bfloat162*)(g_ctx_lo + base) = __halves2bfloat162(
                __float2bfloat16(v0 - __bfloat162float(h0)),
                __float2bfloat16(v1 - __bfloat162float(h1)));
        }
}

// ---------------- final dcl scalar ----------------
__global__ void dcl_kernel(float* out_dcl) {
    __shared__ float red[1024];
    const int tid = threadIdx.x;
    float s = 0.f;
    const int base = tid * 32;
    #pragma unroll 8
    for (int i = 0; i < 32; i++) s += g_clus[base + i];
    red[tid] = s;
    __syncthreads();
    for (int o = 512; o > 0; o >>= 1) {
        if (tid < o) red[tid] += red[tid + o];
        __syncthreads();
    }
    if (tid == 0 && out_dcl) {
        float clus_mean = red[0] / (float)NROWS;
        float regular = ((float)(g_msum >> 3) - (float)(BB * NN)) /
                        ((float)BB * (float)NN * (float)(NN - 1));
        out_dcl[0] = clus_mean + 0.3f * regular;
    }
}

// ---------------- launcher ----------------
extern "C" void kernel_launch(void* const* d_in, const int* in_sizes, int n_in,
                              void* d_out, int out_size) {
    const float* x   = (const float*)d_in[0];
    const int*   msk = (const int*)  d_in[1];
    const float* Wq  = (const float*)d_in[2];
    const float* bq  = (const float*)d_in[3];
    const float* Wk  = (const float*)d_in[4];
    const float* bk  = (const float*)d_in[5];
    const float* Wv  = (const float*)d_in[6];
    const float* bv  = (const float*)d_in[7];
    const float* Wo  = (const float*)d_in[8];
    const float* bo  = (const float*)d_in[9];
    float* out = (float*)d_out;

    const size_t OUTE  = (size_t)BB * NN * DIMD;
    const size_t ATTNE = (size_t)BH * NN * NN;

    float* attn_ptr;
    if ((size_t)out_size >= OUTE + ATTNE) {
        attn_ptr = out + OUTE;
    } else {
        void* p = nullptr;
        cudaGetSymbolAddress(&p, g_attn_fb);
        attn_ptr = (float*)p;
    }
    float* dcl_ptr = ((size_t)out_size >= OUTE + ATTNE + 1) ? (out + OUTE + ATTNE)
                                                            : nullptr;

    cudaFuncSetAttribute(attn3_kernel,
                         cudaFuncAttributeMaxDynamicSharedMemorySize, ATTN_SMEM);
    cudaFuncSetAttribute(bmma_kernel,
                         cudaFuncAttributeMaxDynamicSharedMemorySize, BMMA_SMEM);

    init_kernel<<<1, 32>>>();
    convx_kernel<<<2048, 256>>>(x);
    convw_kernel<<<dim3(16, 16, 4), dim3(32, 8)>>>(Wq, Wk, Wv, Wo);

    dim3 qkvgrid(4, 32, 3);
    bmma_kernel<<<qkvgrid, 256, BMMA_SMEM>>>(bq, bk, bv, nullptr, -1);

    attn3_kernel<<<BH * (NN / 32), 256, ATTN_SMEM>>>(msk, attn_ptr);

    dim3 ogrid(4, 32, 1);
    bmma_kernel<<<ogrid, 256, BMMA_SMEM>>>(bo, bo, bo, out, 3);

    dcl_kernel<<<1, 1024>>>(dcl_ptr);
}

// round 11
// speedup vs baseline: 9.0427x; 1.2016x over previous
#include <cuda_runtime.h>
#include <cuda_bf16.h>
#include <cuda_fp16.h>
#include <math.h>
#include <stdint.h>

#define BB 4
#define NN 1024
#define DIMD 512
#define HH 8
#define DHD 64
#define INNERD 512
#define BH (BB*HH)            // 32
#define NROWS (BH*NN)         // 32768
#define SCALE 0.125f

// ---------------- scratch (device globals; no runtime allocation) ----------
__device__ float g_qni[NROWS];              // reciprocal q norms
__device__ float g_kni[NROWS];              // reciprocal k norms
__device__ float g_clus[NROWS];
__device__ int   g_msum;                    // 8 * sum(mask)
__device__ float g_attn_fb[(size_t)BH*NN*NN];
// bf16 split operands
__device__ __nv_bfloat16 g_x_hi[(size_t)BB*NN*DIMD];
__device__ __nv_bfloat16 g_x_lo[(size_t)BB*NN*DIMD];
__device__ __nv_bfloat16 g_wt_hi[4*512*512];   // W^T [n][k], slots q,k,v,o
__device__ __nv_bfloat16 g_wt_lo[4*512*512];
__device__ __nv_bfloat16 g_ctx_hi[(size_t)BB*NN*INNERD];
__device__ __nv_bfloat16 g_ctx_lo[(size_t)BB*NN*INNERD];
__device__ __nv_bfloat16 g_q_hi[NROWS*DHD];    // [bh][n][d]
__device__ __nv_bfloat16 g_q_lo[NROWS*DHD];
__device__ __nv_bfloat16 g_k_hi[NROWS*DHD];    // [bh][n][d]
__device__ __nv_bfloat16 g_k_lo[NROWS*DHD];
__device__ __half        g_vt_h[NROWS*DHD];    // fp16 TRANSPOSED [bh][d][n]

// ---------------- helpers ----------------
__device__ __forceinline__ uint32_t smem_to_u32(const void* p) {
    uint32_t a;
    asm("{ .reg .u64 t; cvta.to.shared.u64 t, %1; cvt.u32.u64 %0, t; }"
        : "=r"(a) : "l"(p));
    return a;
}
#define SMEM_SWZ(off) ((off) ^ (((off) >> 3) & 0x70))

#define LDSM4(R0, R1, R2, R3, ADDR) \
    asm volatile("ldmatrix.sync.aligned.m8n8.x4.shared.b16 {%0,%1,%2,%3}, [%4];" \
        : "=r"(R0), "=r"(R1), "=r"(R2), "=r"(R3) : "r"(ADDR))

#define MMA16816(C, A, B0, B1) \
    asm volatile("mma.sync.aligned.m16n8k16.row.col.f32.bf16.bf16.f32 " \
        "{%0,%1,%2,%3}, {%4,%5,%6,%7}, {%8,%9}, {%0,%1,%2,%3};" \
        : "+f"((C)[0]), "+f"((C)[1]), "+f"((C)[2]), "+f"((C)[3]) \
        : "r"((A)[0]), "r"((A)[1]), "r"((A)[2]), "r"((A)[3]), "r"(B0), "r"(B1))

#define MMA16816H(C, A, B0, B1) \
    asm volatile("mma.sync.aligned.m16n8k16.row.col.f32.f16.f16.f32 " \
        "{%0,%1,%2,%3}, {%4,%5,%6,%7}, {%8,%9}, {%0,%1,%2,%3};" \
        : "+f"((C)[0]), "+f"((C)[1]), "+f"((C)[2]), "+f"((C)[3]) \
        : "r"((A)[0]), "r"((A)[1]), "r"((A)[2]), "r"((A)[3]), "r"(B0), "r"(B1))

#define CP_ASYNC16(smaddr, gptr) \
    asm volatile("cp.async.cg.shared.global [%0], [%1], 16;" \
        :: "r"(smaddr), "l"(gptr) : "memory")
#define CP_COMMIT() asm volatile("cp.async.commit_group;" ::: "memory")
#define CP_WAIT1() asm volatile("cp.async.wait_group 1;" ::: "memory")
#define CP_WAIT0() asm volatile("cp.async.wait_group 0;" ::: "memory")

// FMA-pipe exp (no MUFU)
__device__ __forceinline__ float fexp(float x) {
    float t = x * 1.4426950408889634f;
    float z = t + 12582912.0f;
    int ni = __float_as_int(z) << 23;
    float f = t - (z - 12582912.0f);
    float p =            1.3333558e-3f;
    p = fmaf(p, f, 9.6181291e-3f);
    p = fmaf(p, f, 5.5504110e-2f);
    p = fmaf(p, f, 2.4022651e-1f);
    p = fmaf(p, f, 6.9314718e-1f);
    p = fmaf(p, f, 1.0f);
    return __int_as_float(__float_as_int(p) + ni);
}

__device__ __forceinline__ void split_store4(__nv_bfloat16* hp, __nv_bfloat16* lp,
                                             float v0, float v1, float v2, float v3)
{
    __nv_bfloat16 h0 = __float2bfloat16(v0), h1 = __float2bfloat16(v1);
    __nv_bfloat16 h2 = __float2bfloat16(v2), h3 = __float2bfloat16(v3);
    *(__nv_bfloat162*)(hp)     = __halves2bfloat162(h0, h1);
    *(__nv_bfloat162*)(hp + 2) = __halves2bfloat162(h2, h3);
    *(__nv_bfloat162*)(lp)     = __halves2bfloat162(
        __float2bfloat16(v0 - __bfloat162float(h0)),
        __float2bfloat16(v1 - __bfloat162float(h1)));
    *(__nv_bfloat162*)(lp + 2) = __halves2bfloat162(
        __float2bfloat16(v2 - __bfloat162float(h2)),
        __float2bfloat16(v3 - __bfloat162float(h3)));
}

// ---------------- init ----------------
__global__ void init_kernel() {
    if (threadIdx.x == 0 && blockIdx.x == 0) g_msum = 0;
}

// ---------------- convert x -> hi/lo bf16 ----------------
__global__ void convx_kernel(const float* __restrict__ x) {
    int i = blockIdx.x * blockDim.x + threadIdx.x;
    float4 v = ((const float4*)x)[i];
    split_store4(g_x_hi + (size_t)i * 4, g_x_lo + (size_t)i * 4,
                 v.x, v.y, v.z, v.w);
}

// ---------------- transpose+convert W -> W^T hi/lo bf16 ----------------
__global__ void convw_kernel(const float* __restrict__ Wq,
                             const float* __restrict__ Wk,
                             const float* __restrict__ Wv,
                             const float* __restrict__ Wo)
{
    __shared__ float tile[32][33];
    const int z = blockIdx.z;
    const float* W = (z == 0) ? Wq : (z == 1) ? Wk : (z == 2) ? Wv : Wo;
    const int tx = threadIdx.x, ty = threadIdx.y;
    const int bk = blockIdx.y * 32, bn = blockIdx.x * 32;
    #pragma unroll
    for (int r = 0; r < 4; r++)
        tile[ty + 8*r][tx] = W[(size_t)(bk + ty + 8*r) * 512 + bn + tx];
    __syncthreads();
    #pragma unroll
    for (int r = 0; r < 4; r++) {
        int n = bn + ty + 8*r, k = bk + tx;
        float v = tile[tx][ty + 8*r];
        __nv_bfloat16 h = __float2bfloat16(v);
        size_t o = (size_t)z * 262144 + (size_t)n * 512 + k;
        g_wt_hi[o] = h;
        g_wt_lo[o] = __float2bfloat16(v - __bfloat162float(h));
    }
}

// ================= HMMA projection GEMM (cp.async double-buffered) =========
#define SA_HI 0
#define SA_LO 16384
#define SB_HI 32768
#define SB_LO 49152
#define STAGE_B 65536
#define BMMA_SMEM (2*STAGE_B)

__global__ __launch_bounds__(256)
void bmma_kernel(const float* __restrict__ b0, const float* __restrict__ b1,
                 const float* __restrict__ b2, float* __restrict__ out, int mode)
{
    extern __shared__ char smc[];
    const uint32_t smb = smem_to_u32(smc);
    const int tid = threadIdx.x;
    const int wid = tid >> 5, lane = tid & 31;
    const int z = (mode < 0) ? (int)blockIdx.z : mode;
    const int bm = blockIdx.y * 128, bn = blockIdx.x * 128;
    const int wm = wid & 3, wn = wid >> 2;

    const __nv_bfloat16* Ah = (z == 3) ? g_ctx_hi : g_x_hi;
    const __nv_bfloat16* Al = (z == 3) ? g_ctx_lo : g_x_lo;
    const __nv_bfloat16* Bh = g_wt_hi + (size_t)z * 262144;
    const __nv_bfloat16* Bl = g_wt_lo + (size_t)z * 262144;
    const float* bias = (z == 0) ? b0 : (z == 1) ? b1 : (z == 2) ? b2 : b0;

    float acc[2][8][4] = {};
    const int ldr = tid >> 3, ldu = tid & 7;

    auto issue = [&](int kc, int st) {
        const uint32_t sb = smb + st * STAGE_B;
        #pragma unroll
        for (int it = 0; it < 4; it++) {
            int r = ldr + it * 32;
            size_t ga = (size_t)(bm + r) * 512 + kc * 64 + ldu * 8;
            size_t gb = (size_t)(bn + r) * 512 + kc * 64 + ldu * 8;
            uint32_t so = SMEM_SWZ((uint32_t)(r * 128 + ldu * 16));
            CP_ASYNC16(sb + SA_HI + so, Ah + ga);
            CP_ASYNC16(sb + SA_LO + so, Al + ga);
            CP_ASYNC16(sb + SB_HI + so, Bh + gb);
            CP_ASYNC16(sb + SB_LO + so, Bl + gb);
        }
        CP_COMMIT();
    };

    issue(0, 0);
    for (int kc = 0; kc < 8; kc++) {
        const int st = kc & 1;
        const uint32_t sb = smb + st * STAGE_B;
        if (kc < 7) { issue(kc + 1, st ^ 1); CP_WAIT1(); }
        else        { CP_WAIT0(); }
        __syncthreads();

        #pragma unroll
        for (int ks = 0; ks < 4; ks++) {
            uint32_t ah[2][4], al[2][4], bhf[8][2], blf[8][2];
            const int arow = wm * 32 + (lane & 15);
            const int akb  = ks * 32 + (lane >> 4) * 16;
            #pragma unroll
            for (int m = 0; m < 2; m++) {
                uint32_t off = SMEM_SWZ((uint32_t)((arow + m * 16) * 128 + akb));
                LDSM4(ah[m][0], ah[m][1], ah[m][2], ah[m][3], sb + SA_HI + off);
                LDSM4(al[m][0], al[m][1], al[m][2], al[m][3], sb + SA_LO + off);
            }
            const int lr = lane & 7, sel = lane >> 3;
            const int nrow = wn * 64 + ((sel >> 1) & 1) * 8 + lr;
            const int bkb  = ks * 32 + (sel & 1) * 16;
            #pragma unroll
            for (int p = 0; p < 4; p++) {
                uint32_t off = SMEM_SWZ((uint32_t)((nrow + p * 16) * 128 + bkb));
                LDSM4(bhf[2*p][0], bhf[2*p][1], bhf[2*p+1][0], bhf[2*p+1][1],
                      sb + SB_HI + off);
                LDSM4(blf[2*p][0], blf[2*p][1], blf[2*p+1][0], blf[2*p+1][1],
                      sb + SB_LO + off);
            }
            #pragma unroll
            for (int m = 0; m < 2; m++)
                #pragma unroll
                for (int nb = 0; nb < 8; nb++) {
                    MMA16816(acc[m][nb], ah[m], bhf[nb][0], bhf[nb][1]);
                    MMA16816(acc[m][nb], ah[m], blf[nb][0], blf[nb][1]);
                    MMA16816(acc[m][nb], al[m], bhf[nb][0], bhf[nb][1]);
                }
        }
        __syncthreads();
    }

    // ---------------- epilogue ----------------
    const int g = lane >> 2, t = lane & 3;
    const int cb = bn + wn * 64;
    const int h = cb >> 6;
    float2 bv[8];
    #pragma unroll
    for (int nb = 0; nb < 8; nb++)
        bv[nb] = *(const float2*)&bias[cb + nb * 8 + 2 * t];

    #pragma unroll
    for (int m = 0; m < 2; m++) {
        #pragma unroll
        for (int half = 0; half < 2; half++) {
            const int rglob = bm + wm * 32 + m * 16 + g + half * 8;
            const int bi = rglob >> 10, n = rglob & 1023;
            float ss = 0.f;
            #pragma unroll
            for (int nb = 0; nb < 8; nb++) {
                float v0 = acc[m][nb][half * 2 + 0] + bv[nb].x;
                float v1 = acc[m][nb][half * 2 + 1] + bv[nb].y;
                ss += v0 * v0 + v1 * v1;
                const int d = nb * 8 + 2 * t;
                if (z == 3) {
                    *(float2*)(out + (size_t)rglob * 512 + cb + d) =
                        make_float2(v0, v1);
                } else if (z == 2) {
                    size_t vb = ((size_t)(bi*HH + h)*DHD + d)*NN + n;
                    g_vt_h[vb]      = __float2half_rn(v0);
                    g_vt_h[vb + NN] = __float2half_rn(v1);
                } else {
                    __nv_bfloat16 h0 = __float2bfloat16(v0);
                    __nv_bfloat16 h1 = __float2bfloat16(v1);
                    __nv_bfloat16 l0 = __float2bfloat16(v0 - __bfloat162float(h0));
                    __nv_bfloat16 l1 = __float2bfloat16(v1 - __bfloat162float(h1));
                    __nv_bfloat16* dh = (z == 0) ? g_q_hi : g_k_hi;
                    __nv_bfloat16* dl = (z == 0) ? g_q_lo : g_k_lo;
                    size_t qb = ((size_t)(bi*HH + h)*NN + n)*DHD + d;
                    *(__nv_bfloat162*)(dh + qb) = __halves2bfloat162(h0, h1);
                    *(__nv_bfloat162*)(dl + qb) = __halves2bfloat162(l0, l1);
                }
            }
            if (z < 2) {
                ss += __shfl_xor_sync(0xffffffffu, ss, 1);
                ss += __shfl_xor_sync(0xffffffffu, ss, 2);
                if (t == 0) {
                    float* dst = (z == 0) ? g_qni : g_kni;
                    dst[(bi * HH + h) * NN + n] = rsqrtf(ss);
                }
            }
        }
    }
}

// ============ fused attention, occ=2: fp16 es, 64-wide K tiles ============
#define ES_B 2064
#define KT_B 144
#define VT_B 272
#define STG_LO2 9216
#define OFF_ES  0
#define OFF_ST0 66048
#define OFF_ST1 84480
#define OFF_RED 102912
#define OFF_INVS 105984
#define OFF_WCNT 106112
#define ATTN_SMEM 106496

__global__ __launch_bounds__(256, 2)
void attn4_kernel(const int* __restrict__ mask, float* __restrict__ attn_out)
{
    extern __shared__ char smc[];
    const uint32_t smb = smem_to_u32(smc);
    float* invs = (float*)(smc + OFF_INVS);
    float* red  = (float*)(smc + OFF_RED);
    int*   wcnt = (int*)(smc + OFF_WCNT);

    const int tid  = threadIdx.x;
    const int warp = tid >> 5, lane = tid & 31;
    const int g = lane >> 2, t = lane & 3;
    const int lr = lane & 7, sel = lane >> 3;
    const int blk = blockIdx.x;             // 1024
    const int bh  = blk >> 5;
    const int i0  = (blk & 31) * 32;
    const int b   = bh >> 3;

    const uint32_t stg[2] = {smb + OFF_ST0, smb + OFF_ST1};

    auto issueK = [&](int jt, uint32_t sb) {  // 64 j-rows, hi+lo
        #pragma unroll
        for (int it = 0; it < 2; it++) {
            int idx = tid + it * 256;
            int r = idx >> 3, u = idx & 7;
            size_t gk = ((size_t)(bh * NN + jt * 64 + r)) * DHD + u * 8;
            CP_ASYNC16(sb + r * KT_B + u * 16, g_k_hi + gk);
            CP_ASYNC16(sb + STG_LO2 + r * KT_B + u * 16, g_k_lo + gk);
        }
        CP_COMMIT();
    };
    auto issueV = [&](int jt, uint32_t sb) {  // 64 d-rows x 128 j, fp16
        #pragma unroll
        for (int it = 0; it < 4; it++) {
            int idx = tid + it * 256;
            int d = idx >> 4, u = idx & 15;
            size_t gv = ((size_t)bh * DHD + d) * NN + jt * 128 + u * 8;
            CP_ASYNC16(sb + d * VT_B + u * 16, g_vt_h + gv);
        }
        CP_COMMIT();
    };

    // prologue: K tile 0 in flight; stage q in ST1
    issueK(0, stg[0]);
    {
        int r = tid >> 3, u = tid & 7;
        size_t gq = ((size_t)(bh * NN + i0 + r)) * DHD + u * 8;
        *(uint4*)(smc + OFF_ST1 + r * KT_B + u * 16) = *(const uint4*)(g_q_hi + gq);
        *(uint4*)(smc + OFF_ST1 + 4608 + r * KT_B + u * 16) = *(const uint4*)(g_q_lo + gq);
    }
    __syncthreads();
    uint32_t qh[2][4][4], ql[2][4][4];
    #pragma unroll
    for (int m = 0; m < 2; m++)
        #pragma unroll
        for (int ks = 0; ks < 4; ks++) {
            uint32_t a = smb + OFF_ST1 + (m * 16 + (lane & 15)) * KT_B
                       + ks * 32 + (lane >> 4) * 16;
            LDSM4(qh[m][ks][0], qh[m][ks][1], qh[m][ks][2], qh[m][ks][3], a);
            LDSM4(ql[m][ks][0], ql[m][ks][1], ql[m][ks][2], ql[m][ks][3], a + 4608);
        }
    __syncthreads();
    issueK(1, stg[1]);

    float qn10[2][2];
    #pragma unroll
    for (int m = 0; m < 2; m++)
        #pragma unroll
        for (int hf = 0; hf < 2; hf++)
            qn10[m][hf] = g_qni[bh * NN + i0 + m * 16 + g + hf * 8] * 10.0f;

    float rall[2][2] = {}, rpos[2][2] = {}, rsum[2][2] = {};
    int cnt = 0;

    // ---- Phase A: 16 tiles of 64 j ----
    for (int jt = 0; jt < 16; jt++) {
        if (jt < 15) CP_WAIT1(); else CP_WAIT0();
        __syncthreads();
        const uint32_t sb = stg[jt & 1];

        float acc[2][4] = {};
        #pragma unroll
        for (int kp = 0; kp < 2; kp++) {
            uint32_t kh4[4], kl4[4];
            uint32_t ka = sb + (warp * 8 + lr) * KT_B + kp * 64 + sel * 16;
            LDSM4(kh4[0], kh4[1], kh4[2], kh4[3], ka);
            LDSM4(kl4[0], kl4[1], kl4[2], kl4[3], ka + STG_LO2);
            #pragma unroll
            for (int h2 = 0; h2 < 2; h2++) {
                const int ks = kp * 2 + h2;
                #pragma unroll
                for (int m = 0; m < 2; m++) {
                    MMA16816(acc[m], qh[m][ks], kh4[h2*2], kh4[h2*2+1]);
                    MMA16816(acc[m], qh[m][ks], kl4[h2*2], kl4[h2*2+1]);
                    MMA16816(acc[m], ql[m][ks], kh4[h2*2], kh4[h2*2+1]);
                }
            }
        }

        const int j0 = jt * 64 + warp * 8 + t * 2;
        float2 kn = *(const float2*)&g_kni[bh * NN + j0];
        #pragma unroll
        for (int m = 0; m < 2; m++)
            #pragma unroll
            for (int hf = 0; hf < 2; hf++) {
                const int il = m * 16 + g + hf * 8;
                int2 mm = *(const int2*)(mask +
                          ((size_t)(b * NN + i0 + il)) * NN + j0);
                float d0 = acc[m][hf * 2 + 0];
                float d1 = acc[m][hf * 2 + 1];
                float qn = qn10[m][hf];
                float ec0 = fexp(d0 * qn * kn.x);
                float ec1 = fexp(d1 * qn * kn.y);
                rall[m][hf] += ec0 + ec1;
                rpos[m][hf] += (mm.x ? ec0 : 0.f) + (mm.y ? ec1 : 0.f);
                cnt += (mm.x != 0) + (mm.y != 0);
                float es0 = mm.x ? fexp(d0 * SCALE) : 0.f;
                float es1 = mm.y ? fexp(d1 * SCALE) : 0.f;
                rsum[m][hf] += es0 + es1;
                *(__half2*)(smc + OFF_ES + il * ES_B + j0 * 2) =
                    __floats2half2_rn(es0, es1);
            }
        __syncthreads();
        if (jt + 2 <= 15) issueK(jt + 2, stg[jt & 1]);
    }

    // ---- row reductions (lanes with same g across t and warps) ----
    #pragma unroll
    for (int m = 0; m < 2; m++)
        #pragma unroll
        for (int hf = 0; hf < 2; hf++) {
            #pragma unroll
            for (int o = 1; o <= 2; o <<= 1) {
                rall[m][hf] += __shfl_xor_sync(0xffffffffu, rall[m][hf], o);
                rpos[m][hf] += __shfl_xor_sync(0xffffffffu, rpos[m][hf], o);
                rsum[m][hf] += __shfl_xor_sync(0xffffffffu, rsum[m][hf], o);
            }
        }
    #pragma unroll
    for (int o = 16; o > 0; o >>= 1)
        cnt += __shfl_xor_sync(0xffffffffu, cnt, o);
    if (t == 0) {
        #pragma unroll
        for (int m = 0; m < 2; m++)
            #pragma unroll
            for (int hf = 0; hf < 2; hf++) {
                int il = m * 16 + g + hf * 8;
                red[(warp * 32 + il) * 3 + 0] = rall[m][hf];
                red[(warp * 32 + il) * 3 + 1] = rpos[m][hf];
                red[(warp * 32 + il) * 3 + 2] = rsum[m][hf];
            }
    }
    if (lane == 0) wcnt[warp] = cnt;
    __syncthreads();
    if (tid < 32) {
        float a = 0.f, p = 0.f, s = 0.f;
        #pragma unroll
        for (int w = 0; w < 8; w++) {
            a += red[(w * 32 + tid) * 3 + 0];
            p += red[(w * 32 + tid) * 3 + 1];
            s += red[(w * 32 + tid) * 3 + 2];
        }
        invs[tid] = __frcp_rn(s);
        g_clus[bh * NN + i0 + tid] = -__logf(__fdividef(p, a));
    }
    if (tid == 32) {
        int s = 0;
        #pragma unroll
        for (int w = 0; w < 8; w++) s += wcnt[w];
        atomicAdd(&g_msum, s);
    }
    __syncthreads();

    // ---- start V pipeline, then write normalized attn ----
    issueV(0, stg[0]);
    issueV(1, stg[1]);

    #pragma unroll 4
    for (int it = 0; it < 16; it++) {
        int idx = tid + it * 256;           // 4096 16B units (8 halfs)
        int row = idx >> 7, u = idx & 127;
        uint4 vh = *(const uint4*)(smc + OFF_ES + row * ES_B + u * 16);
        float s = invs[row];
        const __half2* ph = (const __half2*)&vh;
        float ov[8];
        #pragma unroll
        for (int p2 = 0; p2 < 4; p2++) {
            float2 f = __half22float2(ph[p2]);
            ov[2*p2+0] = f.x * s;
            ov[2*p2+1] = f.y * s;
        }
        float* dst = attn_out + ((size_t)bh * NN + i0 + row) * NN + u * 8;
        *(float4*)dst       = make_float4(ov[0], ov[1], ov[2], ov[3]);
        *(float4*)(dst + 4) = make_float4(ov[4], ov[5], ov[6], ov[7]);
    }

    // ---- Phase B: ctx = es @ V, fp16 single-term HMMA ----
    const int wm = warp >> 2, wd = warp & 3;
    float acc2[2][4] = {};

    for (int jt = 0; jt < 8; jt++) {
        if (jt < 7) CP_WAIT1(); else CP_WAIT0();
        __syncthreads();
        const uint32_t sb = stg[jt & 1];

        #pragma unroll
        for (int ks2 = 0; ks2 < 8; ks2++) {
            uint32_t ah[4], vh4[4];
            uint32_t aa = smb + OFF_ES + (wm * 16 + (lane & 15)) * ES_B
                        + jt * 256 + ks2 * 32 + (lane >> 4) * 16;
            LDSM4(ah[0], ah[1], ah[2], ah[3], aa);
            uint32_t va = sb + (wd * 16 + ((sel >> 1) & 1) * 8 + lr) * VT_B
                        + ks2 * 32 + (sel & 1) * 16;
            LDSM4(vh4[0], vh4[1], vh4[2], vh4[3], va);
            #pragma unroll
            for (int nb = 0; nb < 2; nb++)
                MMA16816H(acc2[nb], ah, vh4[nb*2], vh4[nb*2+1]);
        }
        __syncthreads();
        if (jt + 2 <= 7) issueV(jt + 2, stg[jt & 1]);
    }

    const int h = bh & 7;
    #pragma unroll
    for (int nb = 0; nb < 2; nb++)
        #pragma unroll
        for (int hf = 0; hf < 2; hf++) {
            int i = wm * 16 + g + hf * 8;
            int d = wd * 16 + nb * 8 + t * 2;
            float s = invs[i];
            float v0 = acc2[nb][hf * 2 + 0] * s;
            float v1 = acc2[nb][hf * 2 + 1] * s;
            size_t base = ((size_t)(b * NN + i0 + i)) * INNERD + h * DHD + d;
            __nv_bfloat16 h0 = __float2bfloat16(v0);
            __nv_bfloat16 h1 = __float2bfloat16(v1);
            *(__nv_bfloat162*)(g_ctx_hi + base) = __halves2bfloat162(h0, h1);
            *(__nv_bfloat162*)(g_ctx_lo + base) = __halves2bfloat162(
                __float2bfloat16(v0 - __bfloat162float(h0)),
                __float2bfloat16(v1 - __bfloat162float(h1)));
        }
}

// ---------------- final dcl scalar ----------------
__global__ void dcl_kernel(float* out_dcl) {
    __shared__ float red[1024];
    const int tid = threadIdx.x;
    float s = 0.f;
    const int base = tid * 32;
    #pragma unroll 8
    for (int i = 0; i < 32; i++) s += g_clus[base + i];
    red[tid] = s;
    __syncthreads();
    for (int o = 512; o > 0; o >>= 1) {
        if (tid < o) red[tid] += red[tid + o];
        __syncthreads();
    }
    if (tid == 0 && out_dcl) {
        float clus_mean = red[0] / (float)NROWS;
        float regular = ((float)(g_msum >> 3) - (float)(BB * NN)) /
                        ((float)BB * (float)NN * (float)(NN - 1));
        out_dcl[0] = clus_mean + 0.3f * regular;
    }
}

// ---------------- launcher ----------------
extern "C" void kernel_launch(void* const* d_in, const int* in_sizes, int n_in,
                              void* d_out, int out_size) {
    const float* x   = (const float*)d_in[0];
    const int*   msk = (const int*)  d_in[1];
    const float* Wq  = (const float*)d_in[2];
    const float* bq  = (const float*)d_in[3];
    const float* Wk  = (const float*)d_in[4];
    const float* bk  = (const float*)d_in[5];
    const float* Wv  = (const float*)d_in[6];
    const float* bv  = (const float*)d_in[7];
    const float* Wo  = (const float*)d_in[8];
    const float* bo  = (const float*)d_in[9];
    float* out = (float*)d_out;

    const size_t OUTE  = (size_t)BB * NN * DIMD;
    const size_t ATTNE = (size_t)BH * NN * NN;

    float* attn_ptr;
    if ((size_t)out_size >= OUTE + ATTNE) {
        attn_ptr = out + OUTE;
    } else {
        void* p = nullptr;
        cudaGetSymbolAddress(&p, g_attn_fb);
        attn_ptr = (float*)p;
    }
    float* dcl_ptr = ((size_t)out_size >= OUTE + ATTNE + 1) ? (out + OUTE + ATTNE)
                                                            : nullptr;

    cudaFuncSetAttribute(attn4_kernel,
                         cudaFuncAttributeMaxDynamicSharedMemorySize, ATTN_SMEM);
    cudaFuncSetAttribute(bmma_kernel,
                         cudaFuncAttributeMaxDynamicSharedMemorySize, BMMA_SMEM);

    init_kernel<<<1, 32>>>();
    convx_kernel<<<2048, 256>>>(x);
    convw_kernel<<<dim3(16, 16, 4), dim3(32, 8)>>>(Wq, Wk, Wv, Wo);

    dim3 qkvgrid(4, 32, 3);
    bmma_kernel<<<qkvgrid, 256, BMMA_SMEM>>>(bq, bk, bv, nullptr, -1);

    attn4_kernel<<<BH * (NN / 32), 256, ATTN_SMEM>>>(msk, attn_ptr);

    dim3 ogrid(4, 32, 1);
    bmma_kernel<<<ogrid, 256, BMMA_SMEM>>>(bo, bo, bo, out, 3);

    dcl_kernel<<<1, 1024>>>(dcl_ptr);
}

// round 12
// speedup vs baseline: 9.1647x; 1.0135x over previous
#include <cuda_runtime.h>
#include <cuda_bf16.h>
#include <cuda_fp16.h>
#include <math.h>
#include <stdint.h>

#define BB 4
#define NN 1024
#define DIMD 512
#define HH 8
#define DHD 64
#define INNERD 512
#define BH (BB*HH)            // 32
#define NROWS (BH*NN)         // 32768
#define SCALE 0.125f

// ---------------- scratch (device globals; no runtime allocation) ----------
__device__ float g_qni[NROWS];              // reciprocal q norms
__device__ float g_kni[NROWS];              // reciprocal k norms
__device__ float g_clus[NROWS];
__device__ int   g_msum;                    // 8 * sum(mask)
__device__ float g_attn_fb[(size_t)BH*NN*NN];
// bf16 split operands
__device__ __nv_bfloat16 g_x_hi[(size_t)BB*NN*DIMD];
__device__ __nv_bfloat16 g_x_lo[(size_t)BB*NN*DIMD];
__device__ __nv_bfloat16 g_wt_hi[4*512*512];   // W^T [n][k], slots q,k,v,o
__device__ __nv_bfloat16 g_wt_lo[4*512*512];
__device__ __nv_bfloat16 g_ctx_hi[(size_t)BB*NN*INNERD];
__device__ __nv_bfloat16 g_ctx_lo[(size_t)BB*NN*INNERD];
__device__ __nv_bfloat16 g_q_hi[NROWS*DHD];    // [bh][n][d]
__device__ __nv_bfloat16 g_q_lo[NROWS*DHD];
__device__ __nv_bfloat16 g_k_hi[NROWS*DHD];    // [bh][n][d]
__device__ __nv_bfloat16 g_k_lo[NROWS*DHD];
__device__ __half        g_vt_h[NROWS*DHD];    // fp16 TRANSPOSED [bh][d][n]

// ---------------- helpers ----------------
__device__ __forceinline__ uint32_t smem_to_u32(const void* p) {
    uint32_t a;
    asm("{ .reg .u64 t; cvta.to.shared.u64 t, %1; cvt.u32.u64 %0, t; }"
        : "=r"(a) : "l"(p));
    return a;
}
#define SMEM_SWZ(off) ((off) ^ (((off) >> 3) & 0x70))

#define LDSM4(R0, R1, R2, R3, ADDR) \
    asm volatile("ldmatrix.sync.aligned.m8n8.x4.shared.b16 {%0,%1,%2,%3}, [%4];" \
        : "=r"(R0), "=r"(R1), "=r"(R2), "=r"(R3) : "r"(ADDR))

#define MMA16816(C, A, B0, B1) \
    asm volatile("mma.sync.aligned.m16n8k16.row.col.f32.bf16.bf16.f32 " \
        "{%0,%1,%2,%3}, {%4,%5,%6,%7}, {%8,%9}, {%0,%1,%2,%3};" \
        : "+f"((C)[0]), "+f"((C)[1]), "+f"((C)[2]), "+f"((C)[3]) \
        : "r"((A)[0]), "r"((A)[1]), "r"((A)[2]), "r"((A)[3]), "r"(B0), "r"(B1))

#define MMA16816H(C, A, B0, B1) \
    asm volatile("mma.sync.aligned.m16n8k16.row.col.f32.f16.f16.f32 " \
        "{%0,%1,%2,%3}, {%4,%5,%6,%7}, {%8,%9}, {%0,%1,%2,%3};" \
        : "+f"((C)[0]), "+f"((C)[1]), "+f"((C)[2]), "+f"((C)[3]) \
        : "r"((A)[0]), "r"((A)[1]), "r"((A)[2]), "r"((A)[3]), "r"(B0), "r"(B1))

#define CP_ASYNC16(smaddr, gptr) \
    asm volatile("cp.async.cg.shared.global [%0], [%1], 16;" \
        :: "r"(smaddr), "l"(gptr) : "memory")
#define CP_COMMIT() asm volatile("cp.async.commit_group;" ::: "memory")
#define CP_WAIT1() asm volatile("cp.async.wait_group 1;" ::: "memory")
#define CP_WAIT0() asm volatile("cp.async.wait_group 0;" ::: "memory")

// FMA-pipe exp (no MUFU)
__device__ __forceinline__ float fexp(float x) {
    float t = x * 1.4426950408889634f;
    float z = t + 12582912.0f;
    int ni = __float_as_int(z) << 23;
    float f = t - (z - 12582912.0f);
    float p =            1.3333558e-3f;
    p = fmaf(p, f, 9.6181291e-3f);
    p = fmaf(p, f, 5.5504110e-2f);
    p = fmaf(p, f, 2.4022651e-1f);
    p = fmaf(p, f, 6.9314718e-1f);
    p = fmaf(p, f, 1.0f);
    return __int_as_float(__float_as_int(p) + ni);
}

__device__ __forceinline__ void split_store4(__nv_bfloat16* hp, __nv_bfloat16* lp,
                                             float v0, float v1, float v2, float v3)
{
    __nv_bfloat16 h0 = __float2bfloat16(v0), h1 = __float2bfloat16(v1);
    __nv_bfloat16 h2 = __float2bfloat16(v2), h3 = __float2bfloat16(v3);
    *(__nv_bfloat162*)(hp)     = __halves2bfloat162(h0, h1);
    *(__nv_bfloat162*)(hp + 2) = __halves2bfloat162(h2, h3);
    *(__nv_bfloat162*)(lp)     = __halves2bfloat162(
        __float2bfloat16(v0 - __bfloat162float(h0)),
        __float2bfloat16(v1 - __bfloat162float(h1)));
    *(__nv_bfloat162*)(lp + 2) = __halves2bfloat162(
        __float2bfloat16(v2 - __bfloat162float(h2)),
        __float2bfloat16(v3 - __bfloat162float(h3)));
}

// ---------------- init ----------------
__global__ void init_kernel() {
    if (threadIdx.x == 0 && blockIdx.x == 0) g_msum = 0;
}

// ---------------- convert x -> hi/lo bf16 ----------------
__global__ void convx_kernel(const float* __restrict__ x) {
    int i = blockIdx.x * blockDim.x + threadIdx.x;
    float4 v = ((const float4*)x)[i];
    split_store4(g_x_hi + (size_t)i * 4, g_x_lo + (size_t)i * 4,
                 v.x, v.y, v.z, v.w);
}

// ---------------- transpose+convert W -> W^T hi/lo bf16 ----------------
__global__ void convw_kernel(const float* __restrict__ Wq,
                             const float* __restrict__ Wk,
                             const float* __restrict__ Wv,
                             const float* __restrict__ Wo)
{
    __shared__ float tile[32][33];
    const int z = blockIdx.z;
    const float* W = (z == 0) ? Wq : (z == 1) ? Wk : (z == 2) ? Wv : Wo;
    const int tx = threadIdx.x, ty = threadIdx.y;
    const int bk = blockIdx.y * 32, bn = blockIdx.x * 32;
    #pragma unroll
    for (int r = 0; r < 4; r++)
        tile[ty + 8*r][tx] = W[(size_t)(bk + ty + 8*r) * 512 + bn + tx];
    __syncthreads();
    #pragma unroll
    for (int r = 0; r < 4; r++) {
        int n = bn + ty + 8*r, k = bk + tx;
        float v = tile[tx][ty + 8*r];
        __nv_bfloat16 h = __float2bfloat16(v);
        size_t o = (size_t)z * 262144 + (size_t)n * 512 + k;
        g_wt_hi[o] = h;
        g_wt_lo[o] = __float2bfloat16(v - __bfloat162float(h));
    }
}

// ================= HMMA projection GEMM, 128x64 tile, occ 2 =================
// warp w = m-tile (16 rows); each warp spans the full 64-col head.
#define SA_HI 0
#define SA_LO 16384
#define SB_HI 32768
#define SB_LO 40960
#define STAGE_B 49152
#define BMMA_SMEM (2*STAGE_B)

__global__ __launch_bounds__(256, 2)
void bmma_kernel(const float* __restrict__ b0, const float* __restrict__ b1,
                 const float* __restrict__ b2, float* __restrict__ out, int mode)
{
    extern __shared__ char smc[];
    const uint32_t smb = smem_to_u32(smc);
    const int tid = threadIdx.x;
    const int wid = tid >> 5, lane = tid & 31;
    const int z = (mode < 0) ? (int)blockIdx.z : mode;
    const int bm = blockIdx.y * 128, bn = blockIdx.x * 64;

    const __nv_bfloat16* Ah = (z == 3) ? g_ctx_hi : g_x_hi;
    const __nv_bfloat16* Al = (z == 3) ? g_ctx_lo : g_x_lo;
    const __nv_bfloat16* Bh = g_wt_hi + (size_t)z * 262144;
    const __nv_bfloat16* Bl = g_wt_lo + (size_t)z * 262144;
    const float* bias = (z == 0) ? b0 : (z == 1) ? b1 : (z == 2) ? b2 : b0;

    float acc[8][4] = {};
    const int ldr = tid >> 3, ldu = tid & 7;

    auto issue = [&](int kc, int st) {
        const uint32_t sb = smb + st * STAGE_B;
        #pragma unroll
        for (int it = 0; it < 4; it++) {           // A: 128 rows
            int r = ldr + it * 32;
            size_t ga = (size_t)(bm + r) * 512 + kc * 64 + ldu * 8;
            uint32_t so = SMEM_SWZ((uint32_t)(r * 128 + ldu * 16));
            CP_ASYNC16(sb + SA_HI + so, Ah + ga);
            CP_ASYNC16(sb + SA_LO + so, Al + ga);
        }
        #pragma unroll
        for (int it = 0; it < 2; it++) {           // B: 64 rows
            int r = ldr + it * 32;
            size_t gb = (size_t)(bn + r) * 512 + kc * 64 + ldu * 8;
            uint32_t so = SMEM_SWZ((uint32_t)(r * 128 + ldu * 16));
            CP_ASYNC16(sb + SB_HI + so, Bh + gb);
            CP_ASYNC16(sb + SB_LO + so, Bl + gb);
        }
        CP_COMMIT();
    };

    issue(0, 0);
    for (int kc = 0; kc < 8; kc++) {
        const int st = kc & 1;
        const uint32_t sb = smb + st * STAGE_B;
        if (kc < 7) { issue(kc + 1, st ^ 1); CP_WAIT1(); }
        else        { CP_WAIT0(); }
        __syncthreads();

        #pragma unroll
        for (int ks = 0; ks < 4; ks++) {
            uint32_t ah[4], al[4], bhf[8][2], blf[8][2];
            const int arow = wid * 16 + (lane & 15);
            const int akb  = ks * 32 + (lane >> 4) * 16;
            {
                uint32_t off = SMEM_SWZ((uint32_t)(arow * 128 + akb));
                LDSM4(ah[0], ah[1], ah[2], ah[3], sb + SA_HI + off);
                LDSM4(al[0], al[1], al[2], al[3], sb + SA_LO + off);
            }
            const int lr = lane & 7, sel = lane >> 3;
            const int nrow = ((sel >> 1) & 1) * 8 + lr;
            const int bkb  = ks * 32 + (sel & 1) * 16;
            #pragma unroll
            for (int p = 0; p < 4; p++) {
                uint32_t off = SMEM_SWZ((uint32_t)((nrow + p * 16) * 128 + bkb));
                LDSM4(bhf[2*p][0], bhf[2*p][1], bhf[2*p+1][0], bhf[2*p+1][1],
                      sb + SB_HI + off);
                LDSM4(blf[2*p][0], blf[2*p][1], blf[2*p+1][0], blf[2*p+1][1],
                      sb + SB_LO + off);
            }
            #pragma unroll
            for (int nb = 0; nb < 8; nb++) {
                MMA16816(acc[nb], ah, bhf[nb][0], bhf[nb][1]);
                MMA16816(acc[nb], ah, blf[nb][0], blf[nb][1]);
                MMA16816(acc[nb], al, bhf[nb][0], bhf[nb][1]);
            }
        }
        __syncthreads();
    }

    // ---------------- epilogue ----------------
    const int g = lane >> 2, t = lane & 3;
    const int h = bn >> 6;
    float2 bv[8];
    #pragma unroll
    for (int nb = 0; nb < 8; nb++)
        bv[nb] = *(const float2*)&bias[bn + nb * 8 + 2 * t];

    #pragma unroll
    for (int half = 0; half < 2; half++) {
        const int rglob = bm + wid * 16 + g + half * 8;
        const int bi = rglob >> 10, n = rglob & 1023;
        float ss = 0.f;
        #pragma unroll
        for (int nb = 0; nb < 8; nb++) {
            float v0 = acc[nb][half * 2 + 0] + bv[nb].x;
            float v1 = acc[nb][half * 2 + 1] + bv[nb].y;
            ss += v0 * v0 + v1 * v1;
            const int d = nb * 8 + 2 * t;
            if (z == 3) {
                *(float2*)(out + (size_t)rglob * 512 + bn + d) =
                    make_float2(v0, v1);
            } else if (z == 2) {
                size_t vb = ((size_t)(bi*HH + h)*DHD + d)*NN + n;
                g_vt_h[vb]      = __float2half_rn(v0);
                g_vt_h[vb + NN] = __float2half_rn(v1);
            } else {
                __nv_bfloat16 h0 = __float2bfloat16(v0);
                __nv_bfloat16 h1 = __float2bfloat16(v1);
                __nv_bfloat16 l0 = __float2bfloat16(v0 - __bfloat162float(h0));
                __nv_bfloat16 l1 = __float2bfloat16(v1 - __bfloat162float(h1));
                __nv_bfloat16* dh = (z == 0) ? g_q_hi : g_k_hi;
                __nv_bfloat16* dl = (z == 0) ? g_q_lo : g_k_lo;
                size_t qb = ((size_t)(bi*HH + h)*NN + n)*DHD + d;
                *(__nv_bfloat162*)(dh + qb) = __halves2bfloat162(h0, h1);
                *(__nv_bfloat162*)(dl + qb) = __halves2bfloat162(l0, l1);
            }
        }
        if (z < 2) {
            ss += __shfl_xor_sync(0xffffffffu, ss, 1);
            ss += __shfl_xor_sync(0xffffffffu, ss, 2);
            if (t == 0) {
                float* dst = (z == 0) ? g_qni : g_kni;
                dst[(bi * HH + h) * NN + n] = rsqrtf(ss);
            }
        }
    }
}

// ============ fused attention, occ=2: fp16 es, 64-wide K tiles ============
#define ES_B 2064
#define KT_B 144
#define VT_B 272
#define STG_LO2 9216
#define OFF_ES  0
#define OFF_ST0 66048
#define OFF_ST1 84480
#define OFF_RED 102912
#define OFF_INVS 105984
#define OFF_WCNT 106112
#define ATTN_SMEM 106496

__global__ __launch_bounds__(256, 2)
void attn4_kernel(const int* __restrict__ mask, float* __restrict__ attn_out)
{
    extern __shared__ char smc[];
    const uint32_t smb = smem_to_u32(smc);
    float* invs = (float*)(smc + OFF_INVS);
    float* red  = (float*)(smc + OFF_RED);
    int*   wcnt = (int*)(smc + OFF_WCNT);

    const int tid  = threadIdx.x;
    const int warp = tid >> 5, lane = tid & 31;
    const int g = lane >> 2, t = lane & 3;
    const int lr = lane & 7, sel = lane >> 3;
    const int blk = blockIdx.x;             // 1024
    const int bh  = blk >> 5;
    const int i0  = (blk & 31) * 32;
    const int b   = bh >> 3;

    const uint32_t stg[2] = {smb + OFF_ST0, smb + OFF_ST1};

    auto issueK = [&](int jt, uint32_t sb) {
        #pragma unroll
        for (int it = 0; it < 2; it++) {
            int idx = tid + it * 256;
            int r = idx >> 3, u = idx & 7;
            size_t gk = ((size_t)(bh * NN + jt * 64 + r)) * DHD + u * 8;
            CP_ASYNC16(sb + r * KT_B + u * 16, g_k_hi + gk);
            CP_ASYNC16(sb + STG_LO2 + r * KT_B + u * 16, g_k_lo + gk);
        }
        CP_COMMIT();
    };
    auto issueV = [&](int jt, uint32_t sb) {
        #pragma unroll
        for (int it = 0; it < 4; it++) {
            int idx = tid + it * 256;
            int d = idx >> 4, u = idx & 15;
            size_t gv = ((size_t)bh * DHD + d) * NN + jt * 128 + u * 8;
            CP_ASYNC16(sb + d * VT_B + u * 16, g_vt_h + gv);
        }
        CP_COMMIT();
    };

    issueK(0, stg[0]);
    {
        int r = tid >> 3, u = tid & 7;
        size_t gq = ((size_t)(bh * NN + i0 + r)) * DHD + u * 8;
        *(uint4*)(smc + OFF_ST1 + r * KT_B + u * 16) = *(const uint4*)(g_q_hi + gq);
        *(uint4*)(smc + OFF_ST1 + 4608 + r * KT_B + u * 16) = *(const uint4*)(g_q_lo + gq);
    }
    __syncthreads();
    uint32_t qh[2][4][4], ql[2][4][4];
    #pragma unroll
    for (int m = 0; m < 2; m++)
        #pragma unroll
        for (int ks = 0; ks < 4; ks++) {
            uint32_t a = smb + OFF_ST1 + (m * 16 + (lane & 15)) * KT_B
                       + ks * 32 + (lane >> 4) * 16;
            LDSM4(qh[m][ks][0], qh[m][ks][1], qh[m][ks][2], qh[m][ks][3], a);
            LDSM4(ql[m][ks][0], ql[m][ks][1], ql[m][ks][2], ql[m][ks][3], a + 4608);
        }
    __syncthreads();
    issueK(1, stg[1]);

    float qn10[2][2];
    #pragma unroll
    for (int m = 0; m < 2; m++)
        #pragma unroll
        for (int hf = 0; hf < 2; hf++)
            qn10[m][hf] = g_qni[bh * NN + i0 + m * 16 + g + hf * 8] * 10.0f;

    float rall[2][2] = {}, rpos[2][2] = {}, rsum[2][2] = {};
    int cnt = 0;

    for (int jt = 0; jt < 16; jt++) {
        if (jt < 15) CP_WAIT1(); else CP_WAIT0();
        __syncthreads();
        const uint32_t sb = stg[jt & 1];

        float acc[2][4] = {};
        #pragma unroll
        for (int kp = 0; kp < 2; kp++) {
            uint32_t kh4[4], kl4[4];
            uint32_t ka = sb + (warp * 8 + lr) * KT_B + kp * 64 + sel * 16;
            LDSM4(kh4[0], kh4[1], kh4[2], kh4[3], ka);
            LDSM4(kl4[0], kl4[1], kl4[2], kl4[3], ka + STG_LO2);
            #pragma unroll
            for (int h2 = 0; h2 < 2; h2++) {
                const int ks = kp * 2 + h2;
                #pragma unroll
                for (int m = 0; m < 2; m++) {
                    MMA16816(acc[m], qh[m][ks], kh4[h2*2], kh4[h2*2+1]);
                    MMA16816(acc[m], qh[m][ks], kl4[h2*2], kl4[h2*2+1]);
                    MMA16816(acc[m], ql[m][ks], kh4[h2*2], kh4[h2*2+1]);
                }
            }
        }

        const int j0 = jt * 64 + warp * 8 + t * 2;
        float2 kn = *(const float2*)&g_kni[bh * NN + j0];
        #pragma unroll
        for (int m = 0; m < 2; m++)
            #pragma unroll
            for (int hf = 0; hf < 2; hf++) {
                const int il = m * 16 + g + hf * 8;
                int2 mm = *(const int2*)(mask +
                          ((size_t)(b * NN + i0 + il)) * NN + j0);
                float d0 = acc[m][hf * 2 + 0];
                float d1 = acc[m][hf * 2 + 1];
                float qn = qn10[m][hf];
                float ec0 = fexp(d0 * qn * kn.x);
                float ec1 = fexp(d1 * qn * kn.y);
                rall[m][hf] += ec0 + ec1;
                rpos[m][hf] += (mm.x ? ec0 : 0.f) + (mm.y ? ec1 : 0.f);
                cnt += (mm.x != 0) + (mm.y != 0);
                float es0 = mm.x ? fexp(d0 * SCALE) : 0.f;
                float es1 = mm.y ? fexp(d1 * SCALE) : 0.f;
                rsum[m][hf] += es0 + es1;
                *(__half2*)(smc + OFF_ES + il * ES_B + j0 * 2) =
                    __floats2half2_rn(es0, es1);
            }
        __syncthreads();
        if (jt + 2 <= 15) issueK(jt + 2, stg[jt & 1]);
    }

    #pragma unroll
    for (int m = 0; m < 2; m++)
        #pragma unroll
        for (int hf = 0; hf < 2; hf++) {
            #pragma unroll
            for (int o = 1; o <= 2; o <<= 1) {
                rall[m][hf] += __shfl_xor_sync(0xffffffffu, rall[m][hf], o);
                rpos[m][hf] += __shfl_xor_sync(0xffffffffu, rpos[m][hf], o);
                rsum[m][hf] += __shfl_xor_sync(0xffffffffu, rsum[m][hf], o);
            }
        }
    #pragma unroll
    for (int o = 16; o > 0; o >>= 1)
        cnt += __shfl_xor_sync(0xffffffffu, cnt, o);
    if (t == 0) {
        #pragma unroll
        for (int m = 0; m < 2; m++)
            #pragma unroll
            for (int hf = 0; hf < 2; hf++) {
                int il = m * 16 + g + hf * 8;
                red[(warp * 32 + il) * 3 + 0] = rall[m][hf];
                red[(warp * 32 + il) * 3 + 1] = rpos[m][hf];
                red[(warp * 32 + il) * 3 + 2] = rsum[m][hf];
            }
    }
    if (lane == 0) wcnt[warp] = cnt;
    __syncthreads();
    if (tid < 32) {
        float a = 0.f, p = 0.f, s = 0.f;
        #pragma unroll
        for (int w = 0; w < 8; w++) {
            a += red[(w * 32 + tid) * 3 + 0];
            p += red[(w * 32 + tid) * 3 + 1];
            s += red[(w * 32 + tid) * 3 + 2];
        }
        invs[tid] = __frcp_rn(s);
        g_clus[bh * NN + i0 + tid] = -__logf(__fdividef(p, a));
    }
    if (tid == 32) {
        int s = 0;
        #pragma unroll
        for (int w = 0; w < 8; w++) s += wcnt[w];
        atomicAdd(&g_msum, s);
    }
    __syncthreads();

    issueV(0, stg[0]);
    issueV(1, stg[1]);

    #pragma unroll 4
    for (int it = 0; it < 16; it++) {
        int idx = tid + it * 256;
        int row = idx >> 7, u = idx & 127;
        uint4 vh = *(const uint4*)(smc + OFF_ES + row * ES_B + u * 16);
        float s = invs[row];
        const __half2* ph = (const __half2*)&vh;
        float ov[8];
        #pragma unroll
        for (int p2 = 0; p2 < 4; p2++) {
            float2 f = __half22float2(ph[p2]);
            ov[2*p2+0] = f.x * s;
            ov[2*p2+1] = f.y * s;
        }
        float* dst = attn_out + ((size_t)bh * NN + i0 + row) * NN + u * 8;
        *(float4*)dst       = make_float4(ov[0], ov[1], ov[2], ov[3]);
        *(float4*)(dst + 4) = make_float4(ov[4], ov[5], ov[6], ov[7]);
    }

    const int wm = warp >> 2, wd = warp & 3;
    float acc2[2][4] = {};

    for (int jt = 0; jt < 8; jt++) {
        if (jt < 7) CP_WAIT1(); else CP_WAIT0();
        __syncthreads();
        const uint32_t sb = stg[jt & 1];

        #pragma unroll
        for (int ks2 = 0; ks2 < 8; ks2++) {
            uint32_t ah[4], vh4[4];
            uint32_t aa = smb + OFF_ES + (wm * 16 + (lane & 15)) * ES_B
                        + jt * 256 + ks2 * 32 + (lane >> 4) * 16;
            LDSM4(ah[0], ah[1], ah[2], ah[3], aa);
            uint32_t va = sb + (wd * 16 + ((sel >> 1) & 1) * 8 + lr) * VT_B
                        + ks2 * 32 + (sel & 1) * 16;
            LDSM4(vh4[0], vh4[1], vh4[2], vh4[3], va);
            #pragma unroll
            for (int nb = 0; nb < 2; nb++)
                MMA16816H(acc2[nb], ah, vh4[nb*2], vh4[nb*2+1]);
        }
        __syncthreads();
        if (jt + 2 <= 7) issueV(jt + 2, stg[jt & 1]);
    }

    const int h = bh & 7;
    #pragma unroll
    for (int nb = 0; nb < 2; nb++)
        #pragma unroll
        for (int hf = 0; hf < 2; hf++) {
            int i = wm * 16 + g + hf * 8;
            int d = wd * 16 + nb * 8 + t * 2;
            float s = invs[i];
            float v0 = acc2[nb][hf * 2 + 0] * s;
            float v1 = acc2[nb][hf * 2 + 1] * s;
            size_t base = ((size_t)(b * NN + i0 + i)) * INNERD + h * DHD + d;
            __nv_bfloat16 h0 = __float2bfloat16(v0);
            __nv_bfloat16 h1 = __float2bfloat16(v1);
            *(__nv_bfloat162*)(g_ctx_hi + base) = __halves2bfloat162(h0, h1);
            *(__nv_bfloat162*)(g_ctx_lo + base) = __halves2bfloat162(
                __float2bfloat16(v0 - __bfloat162float(h0)),
                __float2bfloat16(v1 - __bfloat162float(h1)));
        }
}

// ---------------- final dcl scalar ----------------
__global__ void dcl_kernel(float* out_dcl) {
    __shared__ float red[1024];
    const int tid = threadIdx.x;
    float s = 0.f;
    const int base = tid * 32;
    #pragma unroll 8
    for (int i = 0; i < 32; i++) s += g_clus[base + i];
    red[tid] = s;
    __syncthreads();
    for (int o = 512; o > 0; o >>= 1) {
        if (tid < o) red[tid] += red[tid + o];
        __syncthreads();
    }
    if (tid == 0 && out_dcl) {
        float clus_mean = red[0] / (float)NROWS;
        float regular = ((float)(g_msum >> 3) - (float)(BB * NN)) /
                        ((float)BB * (float)NN * (float)(NN - 1));
        out_dcl[0] = clus_mean + 0.3f * regular;
    }
}

// ---------------- launcher ----------------
extern "C" void kernel_launch(void* const* d_in, const int* in_sizes, int n_in,
                              void* d_out, int out_size) {
    const float* x   = (const float*)d_in[0];
    const int*   msk = (const int*)  d_in[1];
    const float* Wq  = (const float*)d_in[2];
    const float* bq  = (const float*)d_in[3];
    const float* Wk  = (const float*)d_in[4];
    const float* bk  = (const float*)d_in[5];
    const float* Wv  = (const float*)d_in[6];
    const float* bv  = (const float*)d_in[7];
    const float* Wo  = (const float*)d_in[8];
    const float* bo  = (const float*)d_in[9];
    float* out = (float*)d_out;

    const size_t OUTE  = (size_t)BB * NN * DIMD;
    const size_t ATTNE = (size_t)BH * NN * NN;

    float* attn_ptr;
    if ((size_t)out_size >= OUTE + ATTNE) {
        attn_ptr = out + OUTE;
    } else {
        void* p = nullptr;
        cudaGetSymbolAddress(&p, g_attn_fb);
        attn_ptr = (float*)p;
    }
    float* dcl_ptr = ((size_t)out_size >= OUTE + ATTNE + 1) ? (out + OUTE + ATTNE)
                                                            : nullptr;

    cudaFuncSetAttribute(attn4_kernel,
                         cudaFuncAttributeMaxDynamicSharedMemorySize, ATTN_SMEM);
    cudaFuncSetAttribute(bmma_kernel,
                         cudaFuncAttributeMaxDynamicSharedMemorySize, BMMA_SMEM);

    init_kernel<<<1, 32>>>();
    convx_kernel<<<2048, 256>>>(x);
    convw_kernel<<<dim3(16, 16, 4), dim3(32, 8)>>>(Wq, Wk, Wv, Wo);

    dim3 qkvgrid(DIMD / 64, (BB * NN) / 128, 3);   // (8, 32, 3)
    bmma_kernel<<<qkvgrid, 256, BMMA_SMEM>>>(bq, bk, bv, nullptr, -1);

    attn4_kernel<<<BH * (NN / 32), 256, ATTN_SMEM>>>(msk, attn_ptr);

    dim3 ogrid(DIMD / 64, (BB * NN) / 128, 1);     // (8, 32)
    bmma_kernel<<<ogrid, 256, BMMA_SMEM>>>(bo, bo, bo, out, 3);

    dcl_kernel<<<1, 1024>>>(dcl_ptr);
}